// round 8
// baseline (speedup 1.0000x reference)
#include <cuda_runtime.h>
#include <cuda_fp16.h>
#include <cstdint>
#include <math.h>

#define S_LEN 2048
#define B_SZ  2
#define DM    1024
#define NH    16
#define DK    64
#define MROWS (B_SZ * S_LEN)
#define INV_SC 0.000244140625f   // 2^-12

// ---- scratch -----------------------------------------------------------
__device__ __half  g_qh[MROWS*DM];  __device__ uint8_t g_ql8[MROWS*DM], g_qh8[MROWS*DM];
__device__ __half  g_kh[MROWS*DM];  __device__ uint8_t g_kl8[MROWS*DM], g_kh8[MROWS*DM];
__device__ __half  g_vh[MROWS*DM];  __device__ uint8_t g_vl8[MROWS*DM], g_vh8[MROWS*DM];
__device__ __half  g_wqh[DM*DM];    __device__ uint8_t g_wql8[DM*DM], g_wqh8[DM*DM];
__device__ __half  g_wkh[DM*DM];    __device__ uint8_t g_wkl8[DM*DM], g_wkh8[DM*DM];
__device__ __half  g_wvh[DM*DM];    __device__ uint8_t g_wvl8[DM*DM], g_wvh8[DM*DM];
__device__ __half  g_woh[DM*DM];    __device__ uint8_t g_wol8[DM*DM], g_woh8[DM*DM];
__device__ __half  g_Qh[MROWS*DM];  __device__ uint8_t g_Ql8[MROWS*DM], g_Qh8[MROWS*DM];
__device__ __half  g_Kh[MROWS*DM];  __device__ uint8_t g_Kl8[MROWS*DM], g_Kh8[MROWS*DM];
__device__ __half  g_Vh[MROWS*DM];  __device__ uint8_t g_Vl8[MROWS*DM], g_Vh8[MROWS*DM];
__device__ __half  g_Ah[MROWS*DM];  __device__ uint8_t g_Al8[MROWS*DM], g_Ah8[MROWS*DM];
__device__ int g_mask_ones;

// ---- helpers -----------------------------------------------------------
__device__ __forceinline__ uint32_t smem_u32(const void* p) {
    uint32_t a;
    asm("{ .reg .u64 t; cvta.to.shared.u64 t, %1; cvt.u32.u64 %0, t; }" : "=r"(a) : "l"(p));
    return a;
}
__device__ __forceinline__ void ldmx4(uint32_t* r, uint32_t addr) {
    asm volatile("ldmatrix.sync.aligned.m8n8.x4.shared.b16 {%0,%1,%2,%3}, [%4];"
                 : "=r"(r[0]), "=r"(r[1]), "=r"(r[2]), "=r"(r[3]) : "r"(addr));
}
__device__ __forceinline__ void ldmx4t(uint32_t* r, uint32_t addr) {
    asm volatile("ldmatrix.sync.aligned.m8n8.x4.trans.shared.b16 {%0,%1,%2,%3}, [%4];"
                 : "=r"(r[0]), "=r"(r[1]), "=r"(r[2]), "=r"(r[3]) : "r"(addr));
}
__device__ __forceinline__ void mma_f16(float* c, const uint32_t* a, const uint32_t* b) {
    asm volatile("mma.sync.aligned.m16n8k16.row.col.f32.f16.f16.f32 "
                 "{%0,%1,%2,%3}, {%4,%5,%6,%7}, {%8,%9}, {%0,%1,%2,%3};"
                 : "+f"(c[0]), "+f"(c[1]), "+f"(c[2]), "+f"(c[3])
                 : "r"(a[0]), "r"(a[1]), "r"(a[2]), "r"(a[3]), "r"(b[0]), "r"(b[1]));
}
__device__ __forceinline__ void mma_e4m3(float* c, const uint32_t* a, uint32_t b0, uint32_t b1) {
    asm volatile("mma.sync.aligned.m16n8k32.row.col.f32.e4m3.e4m3.f32 "
                 "{%0,%1,%2,%3}, {%4,%5,%6,%7}, {%8,%9}, {%0,%1,%2,%3};"
                 : "+f"(c[0]), "+f"(c[1]), "+f"(c[2]), "+f"(c[3])
                 : "r"(a[0]), "r"(a[1]), "r"(a[2]), "r"(a[3]), "r"(b0), "r"(b1));
}
// byte0 = cvt(b), byte1 = cvt(a)
__device__ __forceinline__ uint16_t f2_e4m3x2(float a, float b) {
    uint16_t u;
    asm("cvt.rn.satfinite.e4m3x2.f32 %0, %1, %2;" : "=h"(u) : "f"(a), "f"(b));
    return u;
}
__device__ __forceinline__ uint32_t split2h(float x, float y, uint32_t& lo) {
    __half hx = __float2half_rn(x), hy = __float2half_rn(y);
    __half2 h(hx, hy), l(__float2half_rn(x - __half2float(hx)),
                         __float2half_rn(y - __half2float(hy)));
    lo = *reinterpret_cast<uint32_t*>(&l);
    return *reinterpret_cast<uint32_t*>(&h);
}
// fp32 pair -> fp16 pair + e4m3 residual*4096 pair + e4m3(hi) pair
__device__ __forceinline__ void trip(float x0, float x1, uint32_t& h,
                                     uint16_t& l8, uint16_t& h8) {
    __half h0 = __float2half_rn(x0), h1 = __float2half_rn(x1);
    float f0 = __half2float(h0), f1 = __half2float(h1);
    __half2 hh(h0, h1);
    h  = *reinterpret_cast<uint32_t*>(&hh);
    l8 = f2_e4m3x2((x1 - f1) * 4096.f, (x0 - f0) * 4096.f);
    h8 = f2_e4m3x2(f1, f0);
}

__global__ void reset_flag() { g_mask_ones = 1; }
__global__ __launch_bounds__(256) void check_mask(const int* __restrict__ m, int n) {
    int i = blockIdx.x * blockDim.x + threadIdx.x;
    int ok = 1;
    for (; i < n; i += gridDim.x * blockDim.x) ok &= (m[i] != 0);
    ok = __all_sync(0xffffffffu, ok);
    if ((threadIdx.x & 31) == 0 && !ok) atomicExch(&g_mask_ones, 0);
}

// ---- split fp32 -> triple; 8 elements / thread -------------------------
__global__ __launch_bounds__(256) void split3(
    const float* __restrict__ x, __half* __restrict__ h,
    uint8_t* __restrict__ l8, uint8_t* __restrict__ h8, int n8)
{
    int i = blockIdx.x * blockDim.x + threadIdx.x;
    if (i >= n8) return;
    const float4* xp = (const float4*)x;
    float4 a = xp[2*i], b = xp[2*i+1];
    float xs[8] = { a.x, a.y, a.z, a.w, b.x, b.y, b.z, b.w };
    uint32_t hw[4]; uint16_t lw[4], gw[4];
    #pragma unroll
    for (int j = 0; j < 4; j++) trip(xs[2*j], xs[2*j+1], hw[j], lw[j], gw[j]);
    *(uint4*)(h + 8*(size_t)i) = make_uint4(hw[0], hw[1], hw[2], hw[3]);
    *(uint2*)(l8 + 8*(size_t)i) = make_uint2((uint32_t)lw[0] | ((uint32_t)lw[1] << 16),
                                             (uint32_t)lw[2] | ((uint32_t)lw[3] << 16));
    *(uint2*)(h8 + 8*(size_t)i) = make_uint2((uint32_t)gw[0] | ((uint32_t)gw[1] << 16),
                                             (uint32_t)gw[2] | ((uint32_t)gw[3] << 16));
}

// ---- GEMM: C = A@W^T + bias; fp16 hh + fp8 cross -----------------------
struct GemmP {
    const __half* ah; const uint8_t *al8, *ah8;
    const __half* wh; const uint8_t *wh8, *wl8;
    const float* bias;
    float* outf;
    __half* outh; uint8_t *outl8, *outh8;
};

__global__ __launch_bounds__(256, 1) void gemm_hmma(GemmP p0, GemmP p1, GemmP p2)
{
    __shared__ char smem[2*8192 + 4*4096];   // Ah|Wh|Al8|Ah8|Wh8|Wl8
    GemmP p = (blockIdx.z == 0) ? p0 : (blockIdx.z == 1 ? p1 : p2);

    const int tid = threadIdx.x, lane = tid & 31, wid = tid >> 5;
    const int wm = wid & 1, wn = wid >> 1;
    const int bm = blockIdx.y * 128, bn = blockIdx.x * 128;

    const uint32_t sb = smem_u32(smem);
    const uint32_t sAh = sb, sWh = sb + 8192;
    const uint32_t sAl8 = sb + 16384, sAh8 = sb + 20480;
    const uint32_t sWh8 = sb + 24576, sWl8 = sb + 28672;

    // fp16 staging (64B rows)
    const int u = tid & 3, r0 = tid >> 2, r1 = r0 + 64;
    const uint32_t d0 = (uint32_t)(r0*64 + ((u ^ ((r0 >> 1) & 3)) << 4));
    const uint32_t d1 = (uint32_t)(r1*64 + ((u ^ ((r1 >> 1) & 3)) << 4));
    const size_t offA0 = (size_t)(bm + r0)*DM + u*8, offA1 = (size_t)(bm + r1)*DM + u*8;
    const size_t offW0 = (size_t)(bn + r0)*DM + u*8, offW1 = (size_t)(bn + r1)*DM + u*8;
    // fp8 staging (32B rows)
    const int r8s = tid >> 1, u8s = tid & 1;
    const uint32_t d8 = (uint32_t)(r8s*32 + ((u8s ^ ((r8s >> 2) & 1)) << 4));
    const size_t offA8 = (size_t)(bm + r8s)*DM + u8s*16;
    const size_t offW8 = (size_t)(bn + r8s)*DM + u8s*16;

    // fp16 ldmatrix geometry (validated R4)
    const int sub = lane >> 3;
    const int a_r16 = ((sub & 1) << 3) + (lane & 7), a_usel = sub >> 1;
    const int b_nt = sub >> 1, b_usel = sub & 1, b_r8 = lane & 7;
    // fp8 ldmatrix geometry
    const int r8f = ((lane >> 3) & 1)*8 + (lane & 7), u8f = (lane >> 4) & 1;

    int arow[4], asw[4];
    #pragma unroll
    for (int mt = 0; mt < 4; mt++) {
        const int gr = wm*64 + mt*16 + a_r16;
        arow[mt] = gr*64; asw[mt] = (gr >> 1) & 3;
    }
    int brow[2], bsw[2];
    #pragma unroll
    for (int j = 0; j < 2; j++) {
        const int nr = wn*32 + (2*j + b_nt)*8 + b_r8;
        brow[j] = nr*64; bsw[j] = (nr >> 1) & 3;
    }
    uint32_t a8addr[4], w8addr[2];
    #pragma unroll
    for (int mt = 0; mt < 4; mt++) {
        const int rr = wm*64 + mt*16 + r8f;
        a8addr[mt] = (uint32_t)(rr*32 + ((u8f ^ ((rr >> 2) & 1)) << 4));
    }
    #pragma unroll
    for (int g = 0; g < 2; g++) {
        const int rr = wn*32 + g*16 + r8f;
        w8addr[g] = (uint32_t)(rr*32 + ((u8f ^ ((rr >> 2) & 1)) << 4));
    }

    float acc[4][4][4], acc2[4][4][4];
    #pragma unroll
    for (int mt = 0; mt < 4; mt++)
        #pragma unroll
        for (int nt = 0; nt < 4; nt++)
            #pragma unroll
            for (int r = 0; r < 4; r++) { acc[mt][nt][r] = 0.f; acc2[mt][nt][r] = 0.f; }

    uint4 fA0 = *(const uint4*)(p.ah + offA0), fA1 = *(const uint4*)(p.ah + offA1);
    uint4 fW0 = *(const uint4*)(p.wh + offW0), fW1 = *(const uint4*)(p.wh + offW1);
    uint4 fAl = *(const uint4*)(p.al8 + offA8), fAg = *(const uint4*)(p.ah8 + offA8);
    uint4 fWg = *(const uint4*)(p.wh8 + offW8), fWl = *(const uint4*)(p.wl8 + offW8);

    for (int ch = 0; ch < DM/32; ch++) {
        __syncthreads();
        *(uint4*)(smem + (sAh  - sb) + d0) = fA0;
        *(uint4*)(smem + (sAh  - sb) + d1) = fA1;
        *(uint4*)(smem + (sWh  - sb) + d0) = fW0;
        *(uint4*)(smem + (sWh  - sb) + d1) = fW1;
        *(uint4*)(smem + (sAl8 - sb) + d8) = fAl;
        *(uint4*)(smem + (sAh8 - sb) + d8) = fAg;
        *(uint4*)(smem + (sWh8 - sb) + d8) = fWg;
        *(uint4*)(smem + (sWl8 - sb) + d8) = fWl;
        __syncthreads();

        if (ch + 1 < DM/32) {
            const int kb = (ch + 1)*32;
            fA0 = *(const uint4*)(p.ah + offA0 + kb);
            fA1 = *(const uint4*)(p.ah + offA1 + kb);
            fW0 = *(const uint4*)(p.wh + offW0 + kb);
            fW1 = *(const uint4*)(p.wh + offW1 + kb);
            fAl = *(const uint4*)(p.al8 + offA8 + kb);
            fAg = *(const uint4*)(p.ah8 + offA8 + kb);
            fWg = *(const uint4*)(p.wh8 + offW8 + kb);
            fWl = *(const uint4*)(p.wl8 + offW8 + kb);
        }

        // fp16 hi*hi
        #pragma unroll
        for (int ks = 0; ks < 2; ks++) {
            uint32_t bh[4][2];
            #pragma unroll
            for (int j = 0; j < 2; j++)
                ldmx4(&bh[2*j][0], sWh + (uint32_t)(((2*ks + b_usel) ^ bsw[j]) << 4) + brow[j]);
            #pragma unroll
            for (int mt = 0; mt < 4; mt++) {
                uint32_t ah[4];
                ldmx4(ah, sAh + (uint32_t)(((2*ks + a_usel) ^ asw[mt]) << 4) + arow[mt]);
                #pragma unroll
                for (int nt = 0; nt < 4; nt++) mma_f16(acc[mt][nt], ah, bh[nt]);
            }
        }
        // fp8 cross (k32)
        {
            uint32_t w8h[2][4], w8l[2][4];
            #pragma unroll
            for (int g = 0; g < 2; g++) {
                ldmx4(w8h[g], sWh8 + w8addr[g]);
                ldmx4(w8l[g], sWl8 + w8addr[g]);
            }
            #pragma unroll
            for (int mt = 0; mt < 4; mt++) {
                uint32_t a8l[4], a8h[4];
                ldmx4(a8l, sAl8 + a8addr[mt]);
                ldmx4(a8h, sAh8 + a8addr[mt]);
                #pragma unroll
                for (int g = 0; g < 2; g++) {
                    mma_e4m3(acc2[mt][2*g],   a8l, w8h[g][0], w8h[g][2]);
                    mma_e4m3(acc2[mt][2*g+1], a8l, w8h[g][1], w8h[g][3]);
                    mma_e4m3(acc2[mt][2*g],   a8h, w8l[g][0], w8l[g][2]);
                    mma_e4m3(acc2[mt][2*g+1], a8h, w8l[g][1], w8l[g][3]);
                }
            }
        }
    }

    #pragma unroll
    for (int mt = 0; mt < 4; mt++) {
        const int row0 = bm + wm*64 + mt*16 + (lane >> 2);
        #pragma unroll
        for (int nt = 0; nt < 4; nt++) {
            const int col = bn + wn*32 + nt*8 + (lane & 3)*2;
            const float2 bv = *(const float2*)(p.bias + col);
            float x0 = acc[mt][nt][0] + acc2[mt][nt][0]*INV_SC + bv.x;
            float y0 = acc[mt][nt][1] + acc2[mt][nt][1]*INV_SC + bv.y;
            float x1 = acc[mt][nt][2] + acc2[mt][nt][2]*INV_SC + bv.x;
            float y1 = acc[mt][nt][3] + acc2[mt][nt][3]*INV_SC + bv.y;
            if (p.outf) {
                *(float2*)(p.outf + (size_t)row0*DM + col)     = make_float2(x0, y0);
                *(float2*)(p.outf + (size_t)(row0+8)*DM + col) = make_float2(x1, y1);
            } else {
                uint32_t h0, h1; uint16_t la, ga, lb, gb;
                trip(x0, y0, h0, la, ga);
                trip(x1, y1, h1, lb, gb);
                *(uint32_t*)(p.outh  + (size_t)row0*DM + col)     = h0;
                *(uint16_t*)(p.outl8 + (size_t)row0*DM + col)     = la;
                *(uint16_t*)(p.outh8 + (size_t)row0*DM + col)     = ga;
                *(uint32_t*)(p.outh  + (size_t)(row0+8)*DM + col) = h1;
                *(uint16_t*)(p.outl8 + (size_t)(row0+8)*DM + col) = lb;
                *(uint16_t*)(p.outh8 + (size_t)(row0+8)*DM + col) = gb;
            }
        }
    }
}

// ---- flash attention: QK fp16+fp8 cross, PV fp16 2-term ----------------
#define ATT_SMEM 57344

__global__ __launch_bounds__(256, 2) void flash_attn_mma(
    const __half* __restrict__ Qh, const uint8_t* __restrict__ Ql8,
    const uint8_t* __restrict__ Qh8,
    const __half* __restrict__ Kh, const uint8_t* __restrict__ Kh8,
    const uint8_t* __restrict__ Kl8,
    const __half* __restrict__ Vh,
    const int* __restrict__ mask,
    __half* __restrict__ AOh, uint8_t* __restrict__ AOl8,
    uint8_t* __restrict__ AOh8)
{
    extern __shared__ char sm[];
    const uint32_t sb = smem_u32(sm);
    const uint32_t sQh = sb, sQl8 = sb + 16384, sQh8 = sb + 24576;
    const uint32_t sKh = sb + 32768, sKh8 = sb + 40960, sKl8 = sb + 45056;
    const uint32_t sVh = sb + 49152;

    const int tid = threadIdx.x, lane = tid & 31, wid = tid >> 5;
    const int qb = blockIdx.x, bh = blockIdx.y;
    const int b = bh >> 4, h = bh & 15;
    const int q0 = qb*128;
    const size_t rowbase = (size_t)b*S_LEN;
    const int hoff = h*DK;
    const int allones = g_mask_ones;

    // Q fp16 (128x128B) + fp8 (128x64B)
    #pragma unroll
    for (int t = 0; t < 4; t++) {
        const int idx = tid + t*256;
        const int r = idx >> 3, uu = idx & 7;
        const uint32_t d = (uint32_t)(r*128 + ((uu ^ (r & 7)) << 4));
        *(uint4*)(sm + (sQh - sb) + d) = *(const uint4*)(Qh + (rowbase + q0 + r)*DM + hoff + uu*8);
    }
    #pragma unroll
    for (int t = 0; t < 2; t++) {
        const int idx = tid + t*256;
        const int r = idx >> 2, uu = idx & 3;
        const uint32_t d = (uint32_t)(r*64 + ((uu ^ ((r >> 1) & 3)) << 4));
        const size_t g = (rowbase + q0 + r)*DM + hoff + uu*16;
        *(uint4*)(sm + (sQl8 - sb) + d) = *(const uint4*)(Ql8 + g);
        *(uint4*)(sm + (sQh8 - sb) + d) = *(const uint4*)(Qh8 + g);
    }

    const int sub = lane >> 3, l7 = lane & 7;
    const int a_r = ((sub & 1) << 3) + l7, a_us = sub >> 1;
    const int b_nt = sub >> 1, b_us = sub & 1;
    const int qrow = wid*16 + a_r;
    const int vro = ((sub & 1) << 3) + l7, vus = sub >> 1;
    const int r8f = ((lane >> 3) & 1)*8 + (lane & 7), u8f = (lane >> 4) & 1;
    const int qr8 = wid*16 + r8f;

    float o[8][4];
    #pragma unroll
    for (int nt = 0; nt < 8; nt++)
        #pragma unroll
        for (int e = 0; e < 4; e++) o[nt][e] = 0.f;
    float m0 = -3.0e38f, m1 = -3.0e38f, l0 = 0.f, l1 = 0.f;

    for (int kb = 0; kb < S_LEN/64; kb++) {
        const int k0g = kb*64;

        // K fp16 + Vh (64x128B each); K fp8 (64x64B each)
        #pragma unroll
        for (int t = 0; t < 2; t++) {
            const int idx = tid + t*256;
            const int r = idx >> 3, uu = idx & 7;
            const size_t g = (rowbase + k0g + r)*DM + hoff + uu*8;
            const uint32_t d = (uint32_t)(r*128 + ((uu ^ (r & 7)) << 4));
            *(uint4*)(sm + (sKh - sb) + d) = *(const uint4*)(Kh + g);
            *(uint4*)(sm + (sVh - sb) + d) = *(const uint4*)(Vh + g);
        }
        {
            const int r = tid >> 2, uu = tid & 3;
            const uint32_t d = (uint32_t)(r*64 + ((uu ^ ((r >> 1) & 3)) << 4));
            const size_t g = (rowbase + k0g + r)*DM + hoff + uu*16;
            *(uint4*)(sm + (sKh8 - sb) + d) = *(const uint4*)(Kh8 + g);
            *(uint4*)(sm + (sKl8 - sb) + d) = *(const uint4*)(Kl8 + g);
        }
        __syncthreads();

        float c[8][4];
        #pragma unroll
        for (int j = 0; j < 8; j++)
            #pragma unroll
            for (int e = 0; e < 4; e++) c[j][e] = 0.f;

        // fp8 cross first (into c), then scale, then fp16 on top
        #pragma unroll
        for (int cc = 0; cc < 2; cc++) {
            const int uq = 2*cc + u8f;
            uint32_t a8l[4], a8h[4];
            const uint32_t uaq = (uint32_t)(qr8*64 + ((uq ^ ((qr8 >> 1) & 3)) << 4));
            ldmx4(a8l, sQl8 + uaq);
            ldmx4(a8h, sQh8 + uaq);
            #pragma unroll
            for (int g = 0; g < 4; g++) {
                const int kr = g*16 + r8f;
                const uint32_t ukr = (uint32_t)(kr*64 + ((uq ^ ((kr >> 1) & 3)) << 4));
                uint32_t k8h[4], k8l[4];
                ldmx4(k8h, sKh8 + ukr);
                ldmx4(k8l, sKl8 + ukr);
                mma_e4m3(c[2*g],   a8l, k8h[0], k8h[2]);
                mma_e4m3(c[2*g+1], a8l, k8h[1], k8h[3]);
                mma_e4m3(c[2*g],   a8h, k8l[0], k8l[2]);
                mma_e4m3(c[2*g+1], a8h, k8l[1], k8l[3]);
            }
        }
        #pragma unroll
        for (int j = 0; j < 8; j++)
            #pragma unroll
            for (int e = 0; e < 4; e++) c[j][e] *= INV_SC;

        #pragma unroll
        for (int ks = 0; ks < 4; ks++) {
            uint32_t ah[4];
            ldmx4(ah, sQh + (uint32_t)((((2*ks + a_us) ^ (qrow & 7)) << 4) + qrow*128));
            #pragma unroll
            for (int jp = 0; jp < 4; jp++) {
                uint32_t kh4[4];
                const int nr = jp*16 + b_nt*8 + l7;
                ldmx4(kh4, sKh + (uint32_t)((((2*ks + b_us) ^ (nr & 7)) << 4) + nr*128));
                mma_f16(c[2*jp],   ah, kh4);
                mma_f16(c[2*jp+1], ah, kh4 + 2);
            }
        }

        // scale + mask
        if (allones) {
            #pragma unroll
            for (int j = 0; j < 8; j++)
                #pragma unroll
                for (int e = 0; e < 4; e++) c[j][e] *= 0.125f;
        } else {
            const int qg0 = q0 + wid*16 + (lane >> 2);
            #pragma unroll
            for (int j = 0; j < 8; j++) {
                const int colb = k0g + j*8 + 2*(lane & 3);
                #pragma unroll
                for (int e = 0; e < 4; e++) {
                    const int qq = (e < 2) ? qg0 : qg0 + 8;
                    const int mv = mask[(size_t)qq*S_LEN + colb + (e & 1)];
                    c[j][e] = mv ? c[j][e]*0.125f : -1e9f;
                }
            }
        }

        // online softmax
        float rm0 = -3.0e38f, rm1 = -3.0e38f;
        #pragma unroll
        for (int j = 0; j < 8; j++) {
            rm0 = fmaxf(rm0, fmaxf(c[j][0], c[j][1]));
            rm1 = fmaxf(rm1, fmaxf(c[j][2], c[j][3]));
        }
        rm0 = fmaxf(rm0, __shfl_xor_sync(0xffffffffu, rm0, 1));
        rm0 = fmaxf(rm0, __shfl_xor_sync(0xffffffffu, rm0, 2));
        rm1 = fmaxf(rm1, __shfl_xor_sync(0xffffffffu, rm1, 1));
        rm1 = fmaxf(rm1, __shfl_xor_sync(0xffffffffu, rm1, 2));
        const float mn0 = fmaxf(m0, rm0), mn1 = fmaxf(m1, rm1);
        const float al0 = __expf(m0 - mn0), al1 = __expf(m1 - mn1);
        float rs0 = 0.f, rs1 = 0.f;
        #pragma unroll
        for (int j = 0; j < 8; j++) {
            c[j][0] = __expf(c[j][0] - mn0);
            c[j][1] = __expf(c[j][1] - mn0);
            c[j][2] = __expf(c[j][2] - mn1);
            c[j][3] = __expf(c[j][3] - mn1);
            rs0 += c[j][0] + c[j][1];
            rs1 += c[j][2] + c[j][3];
        }
        rs0 += __shfl_xor_sync(0xffffffffu, rs0, 1);
        rs0 += __shfl_xor_sync(0xffffffffu, rs0, 2);
        rs1 += __shfl_xor_sync(0xffffffffu, rs1, 1);
        rs1 += __shfl_xor_sync(0xffffffffu, rs1, 2);
        l0 = l0*al0 + rs0;
        l1 = l1*al1 + rs1;
        m0 = mn0; m1 = mn1;
        #pragma unroll
        for (int nt = 0; nt < 8; nt++) {
            o[nt][0] *= al0; o[nt][1] *= al0;
            o[nt][2] *= al1; o[nt][3] *= al1;
        }

        // O += P V : fp16, P split register-local (hi+lo), V hi only
        #pragma unroll
        for (int kt = 0; kt < 4; kt++) {
            uint32_t ph[4], pl[4];
            ph[0] = split2h(c[2*kt][0],   c[2*kt][1],   pl[0]);
            ph[1] = split2h(c[2*kt][2],   c[2*kt][3],   pl[1]);
            ph[2] = split2h(c[2*kt+1][0], c[2*kt+1][1], pl[2]);
            ph[3] = split2h(c[2*kt+1][2], c[2*kt+1][3], pl[3]);
            const int tv = kt*16 + vro;
            #pragma unroll
            for (int dp = 0; dp < 4; dp++) {
                uint32_t vh4[4];
                ldmx4t(vh4, sVh + (uint32_t)((((2*dp + vus) ^ (tv & 7)) << 4) + tv*128));
                mma_f16(o[2*dp],   ph, vh4);
                mma_f16(o[2*dp],   pl, vh4);
                mma_f16(o[2*dp+1], ph, vh4 + 2);
                mma_f16(o[2*dp+1], pl, vh4 + 2);
            }
        }
        __syncthreads();
    }

    // epilogue -> AO triple
    const float inv0 = 1.f/l0, inv1 = 1.f/l1;
    const size_t gr0 = rowbase + q0 + wid*16 + (lane >> 2);
    #pragma unroll
    for (int nt = 0; nt < 8; nt++) {
        const int col = hoff + nt*8 + 2*(lane & 3);
        uint32_t h0, h1; uint16_t la, ga, lb, gb;
        trip(o[nt][0]*inv0, o[nt][1]*inv0, h0, la, ga);
        trip(o[nt][2]*inv1, o[nt][3]*inv1, h1, lb, gb);
        *(uint32_t*)(AOh  + gr0*DM + col)     = h0;
        *(uint16_t*)(AOl8 + gr0*DM + col)     = la;
        *(uint16_t*)(AOh8 + gr0*DM + col)     = ga;
        *(uint32_t*)(AOh  + (gr0+8)*DM + col) = h1;
        *(uint16_t*)(AOl8 + (gr0+8)*DM + col) = lb;
        *(uint16_t*)(AOh8 + (gr0+8)*DM + col) = gb;
    }
}

// ---- host --------------------------------------------------------------
extern "C" void kernel_launch(void* const* d_in, const int* in_sizes, int n_in,
                              void* d_out, int out_size)
{
    const float* q    = (const float*)d_in[0];
    const float* k    = (const float*)d_in[1];
    const float* v    = (const float*)d_in[2];
    const int*   mask = (const int*)  d_in[3];
    const float* Wq   = (const float*)d_in[4];
    const float* bq   = (const float*)d_in[5];
    const float* Wk   = (const float*)d_in[6];
    const float* bk   = (const float*)d_in[7];
    const float* Wv   = (const float*)d_in[8];
    const float* bv   = (const float*)d_in[9];
    const float* Wo   = (const float*)d_in[10];
    const float* bo   = (const float*)d_in[11];
    float* out = (float*)d_out;

    __half *qh, *kh, *vh, *wqh, *wkh, *wvh, *woh, *Qh, *Kh, *Vh, *Ah;
    uint8_t *ql8,*qh8,*kl8,*kh8,*vl8,*vh8,*wql8,*wqh8,*wkl8,*wkh8,*wvl8,*wvh8,*wol8,*woh8;
    uint8_t *Ql8,*Qh8,*Kl8,*Kh8,*Vl8,*Vh8,*Al8,*Ah8;
    cudaGetSymbolAddress((void**)&qh, g_qh);   cudaGetSymbolAddress((void**)&ql8, g_ql8);  cudaGetSymbolAddress((void**)&qh8, g_qh8);
    cudaGetSymbolAddress((void**)&kh, g_kh);   cudaGetSymbolAddress((void**)&kl8, g_kl8);  cudaGetSymbolAddress((void**)&kh8, g_kh8);
    cudaGetSymbolAddress((void**)&vh, g_vh);   cudaGetSymbolAddress((void**)&vl8, g_vl8);  cudaGetSymbolAddress((void**)&vh8, g_vh8);
    cudaGetSymbolAddress((void**)&wqh, g_wqh); cudaGetSymbolAddress((void**)&wql8, g_wql8);cudaGetSymbolAddress((void**)&wqh8, g_wqh8);
    cudaGetSymbolAddress((void**)&wkh, g_wkh); cudaGetSymbolAddress((void**)&wkl8, g_wkl8);cudaGetSymbolAddress((void**)&wkh8, g_wkh8);
    cudaGetSymbolAddress((void**)&wvh, g_wvh); cudaGetSymbolAddress((void**)&wvl8, g_wvl8);cudaGetSymbolAddress((void**)&wvh8, g_wvh8);
    cudaGetSymbolAddress((void**)&woh, g_woh); cudaGetSymbolAddress((void**)&wol8, g_wol8);cudaGetSymbolAddress((void**)&woh8, g_woh8);
    cudaGetSymbolAddress((void**)&Qh, g_Qh);   cudaGetSymbolAddress((void**)&Ql8, g_Ql8);  cudaGetSymbolAddress((void**)&Qh8, g_Qh8);
    cudaGetSymbolAddress((void**)&Kh, g_Kh);   cudaGetSymbolAddress((void**)&Kl8, g_Kl8);  cudaGetSymbolAddress((void**)&Kh8, g_Kh8);
    cudaGetSymbolAddress((void**)&Vh, g_Vh);   cudaGetSymbolAddress((void**)&Vl8, g_Vl8);  cudaGetSymbolAddress((void**)&Vh8, g_Vh8);
    cudaGetSymbolAddress((void**)&Ah, g_Ah);   cudaGetSymbolAddress((void**)&Al8, g_Al8);  cudaGetSymbolAddress((void**)&Ah8, g_Ah8);

    cudaFuncSetAttribute(flash_attn_mma, cudaFuncAttributeMaxDynamicSharedMemorySize, ATT_SMEM);

    const int n8_in = MROWS*DM/8, n8_w = DM*DM/8;

    reset_flag<<<1, 1>>>();
    check_mask<<<1024, 256>>>(mask, S_LEN*S_LEN);

    split3<<<n8_in/256, 256>>>(q,  qh,  ql8,  qh8,  n8_in);
    split3<<<n8_in/256, 256>>>(k,  kh,  kl8,  kh8,  n8_in);
    split3<<<n8_in/256, 256>>>(v,  vh,  vl8,  vh8,  n8_in);
    split3<<<n8_w/256,  256>>>(Wq, wqh, wql8, wqh8, n8_w);
    split3<<<n8_w/256,  256>>>(Wk, wkh, wkl8, wkh8, n8_w);
    split3<<<n8_w/256,  256>>>(Wv, wvh, wvl8, wvh8, n8_w);
    split3<<<n8_w/256,  256>>>(Wo, woh, wol8, woh8, n8_w);

    GemmP pq = { qh, ql8, qh8, wqh, wqh8, wql8, bq, nullptr, Qh, Ql8, Qh8 };
    GemmP pk = { kh, kl8, kh8, wkh, wkh8, wkl8, bk, nullptr, Kh, Kl8, Kh8 };
    GemmP pv = { vh, vl8, vh8, wvh, wvh8, wvl8, bv, nullptr, Vh, Vl8, Vh8 };
    dim3 gg3(DM/128, MROWS/128, 3);
    gemm_hmma<<<gg3, 256>>>(pq, pk, pv);

    dim3 ga(S_LEN/128, B_SZ*NH);
    flash_attn_mma<<<ga, 256, ATT_SMEM>>>(Qh, Ql8, Qh8, Kh, Kh8, Kl8, Vh, mask,
                                          Ah, Al8, Ah8);

    GemmP po = { Ah, Al8, Ah8, woh, woh8, wol8, bo, out, nullptr, nullptr, nullptr };
    dim3 gg1(DM/128, MROWS/128, 1);
    gemm_hmma<<<gg1, 256>>>(po, po, po);
}

// round 9
// speedup vs baseline: 1.3991x; 1.3991x over previous
#include <cuda_runtime.h>
#include <cuda_fp16.h>
#include <cstdint>
#include <math.h>

#define S_LEN 2048
#define B_SZ  2
#define DM    1024
#define NH    16
#define DK    64
#define MROWS (B_SZ * S_LEN)

// ---- scratch -----------------------------------------------------------
__device__ __half g_qh[MROWS*DM], g_ql[MROWS*DM];
__device__ __half g_kh[MROWS*DM], g_kl[MROWS*DM];
__device__ __half g_vh[MROWS*DM], g_vl[MROWS*DM];
__device__ __half g_wqh[DM*DM], g_wql[DM*DM];
__device__ __half g_wkh[DM*DM], g_wkl[DM*DM];
__device__ __half g_wvh[DM*DM], g_wvl[DM*DM];
__device__ __half g_woh[DM*DM], g_wol[DM*DM];
__device__ __half g_Qh[MROWS*DM], g_Ql[MROWS*DM];
__device__ __half g_Kh[MROWS*DM], g_Kl[MROWS*DM];
__device__ __half g_Vh[MROWS*DM], g_Vl[MROWS*DM];
__device__ __half g_Ah[MROWS*DM], g_Al[MROWS*DM];
__device__ int g_mask_ones;

// ---- helpers -----------------------------------------------------------
__device__ __forceinline__ uint32_t smem_u32(const void* p) {
    uint32_t a;
    asm("{ .reg .u64 t; cvta.to.shared.u64 t, %1; cvt.u32.u64 %0, t; }" : "=r"(a) : "l"(p));
    return a;
}
__device__ __forceinline__ void ldmx4(uint32_t* r, uint32_t addr) {
    asm volatile("ldmatrix.sync.aligned.m8n8.x4.shared.b16 {%0,%1,%2,%3}, [%4];"
                 : "=r"(r[0]), "=r"(r[1]), "=r"(r[2]), "=r"(r[3]) : "r"(addr));
}
__device__ __forceinline__ void ldmx4t(uint32_t* r, uint32_t addr) {
    asm volatile("ldmatrix.sync.aligned.m8n8.x4.trans.shared.b16 {%0,%1,%2,%3}, [%4];"
                 : "=r"(r[0]), "=r"(r[1]), "=r"(r[2]), "=r"(r[3]) : "r"(addr));
}
__device__ __forceinline__ void mma_f16(float* c, const uint32_t* a, const uint32_t* b) {
    asm volatile("mma.sync.aligned.m16n8k16.row.col.f32.f16.f16.f32 "
                 "{%0,%1,%2,%3}, {%4,%5,%6,%7}, {%8,%9}, {%0,%1,%2,%3};"
                 : "+f"(c[0]), "+f"(c[1]), "+f"(c[2]), "+f"(c[3])
                 : "r"(a[0]), "r"(a[1]), "r"(a[2]), "r"(a[3]), "r"(b[0]), "r"(b[1]));
}
// (x,y) -> fp16x2 hi word; residual -> fp16x2 lo word
__device__ __forceinline__ uint32_t split2h(float x, float y, uint32_t& lo) {
    __half hx = __float2half_rn(x), hy = __float2half_rn(y);
    __half2 h(hx, hy), l(__float2half_rn(x - __half2float(hx)),
                         __float2half_rn(y - __half2float(hy)));
    lo = *reinterpret_cast<uint32_t*>(&l);
    return *reinterpret_cast<uint32_t*>(&h);
}

__global__ void reset_flag() { g_mask_ones = 1; }
__global__ __launch_bounds__(256) void check_mask(const int* __restrict__ m, int n) {
    int i = blockIdx.x * blockDim.x + threadIdx.x;
    int ok = 1;
    for (; i < n; i += gridDim.x * blockDim.x) ok &= (m[i] != 0);
    ok = __all_sync(0xffffffffu, ok);
    if ((threadIdx.x & 31) == 0 && !ok) atomicExch(&g_mask_ones, 0);
}

// ---- split fp32 -> (fp16 hi, fp16 lo) ----------------------------------
__global__ __launch_bounds__(256) void split_h(
    const float* __restrict__ x, __half* __restrict__ hi,
    __half* __restrict__ lo, int n4)
{
    int i = blockIdx.x * blockDim.x + threadIdx.x;
    if (i >= n4) return;
    float4 v = ((const float4*)x)[i];
    uint32_t l0, l1;
    uint32_t h0 = split2h(v.x, v.y, l0);
    uint32_t h1 = split2h(v.z, v.w, l1);
    ((uint32_t*)hi)[2*i] = h0; ((uint32_t*)hi)[2*i+1] = h1;
    ((uint32_t*)lo)[2*i] = l0; ((uint32_t*)lo)[2*i+1] = l1;
}

// ---- GEMM: C = (Ah+Al)@(Wh+Wl)^T + bias ; fp16 3-term ------------------
struct GemmP {
    const __half *ahi, *alo, *whi, *wlo;
    const float* bias;
    float* outf;
    __half *outh, *outl;
};

#define GT_BYTES 8192   // 128 x 32 fp16

__global__ __launch_bounds__(256, 1) void gemm_hmma(GemmP p0, GemmP p1, GemmP p2)
{
    __shared__ char smem[4 * GT_BYTES];   // Ah | Al | Wh | Wl
    GemmP p = (blockIdx.z == 0) ? p0 : (blockIdx.z == 1 ? p1 : p2);

    const int tid = threadIdx.x, lane = tid & 31, wid = tid >> 5;
    const int wm = wid & 1, wn = wid >> 1;
    const int bm = blockIdx.y * 128, bn = blockIdx.x * 128;

    const uint32_t sb = smem_u32(smem);
    const uint32_t sAh = sb, sAl = sb + GT_BYTES;
    const uint32_t sWh = sb + 2*GT_BYTES, sWl = sb + 3*GT_BYTES;

    const int u = tid & 3, r0 = tid >> 2, r1 = r0 + 64;
    const uint32_t d0 = (uint32_t)(r0*64 + ((u ^ ((r0 >> 1) & 3)) << 4));
    const uint32_t d1 = (uint32_t)(r1*64 + ((u ^ ((r1 >> 1) & 3)) << 4));
    const size_t offA0 = (size_t)(bm + r0)*DM + u*8, offA1 = (size_t)(bm + r1)*DM + u*8;
    const size_t offW0 = (size_t)(bn + r0)*DM + u*8, offW1 = (size_t)(bn + r1)*DM + u*8;

    const int sub = lane >> 3;
    const int a_r16 = ((sub & 1) << 3) + (lane & 7), a_usel = sub >> 1;
    const int b_nt = sub >> 1, b_usel = sub & 1, b_r8 = lane & 7;

    int arow[4], asw[4];
    #pragma unroll
    for (int mt = 0; mt < 4; mt++) {
        const int gr = wm*64 + mt*16 + a_r16;
        arow[mt] = gr*64; asw[mt] = (gr >> 1) & 3;
    }
    int brow[2], bsw[2];
    #pragma unroll
    for (int j = 0; j < 2; j++) {
        const int nr = wn*32 + (2*j + b_nt)*8 + b_r8;
        brow[j] = nr*64; bsw[j] = (nr >> 1) & 3;
    }

    float acc[4][4][4];
    #pragma unroll
    for (int mt = 0; mt < 4; mt++)
        #pragma unroll
        for (int nt = 0; nt < 4; nt++)
            #pragma unroll
            for (int r = 0; r < 4; r++) acc[mt][nt][r] = 0.f;

    uint4 fAh0 = *(const uint4*)(p.ahi + offA0), fAh1 = *(const uint4*)(p.ahi + offA1);
    uint4 fAl0 = *(const uint4*)(p.alo + offA0), fAl1 = *(const uint4*)(p.alo + offA1);
    uint4 fWh0 = *(const uint4*)(p.whi + offW0), fWh1 = *(const uint4*)(p.whi + offW1);
    uint4 fWl0 = *(const uint4*)(p.wlo + offW0), fWl1 = *(const uint4*)(p.wlo + offW1);

    for (int ch = 0; ch < DM/32; ch++) {
        __syncthreads();
        *(uint4*)(smem + (sAh - sb) + d0) = fAh0;
        *(uint4*)(smem + (sAh - sb) + d1) = fAh1;
        *(uint4*)(smem + (sAl - sb) + d0) = fAl0;
        *(uint4*)(smem + (sAl - sb) + d1) = fAl1;
        *(uint4*)(smem + (sWh - sb) + d0) = fWh0;
        *(uint4*)(smem + (sWh - sb) + d1) = fWh1;
        *(uint4*)(smem + (sWl - sb) + d0) = fWl0;
        *(uint4*)(smem + (sWl - sb) + d1) = fWl1;
        __syncthreads();

        if (ch + 1 < DM/32) {
            const int kb = (ch + 1)*32;
            fAh0 = *(const uint4*)(p.ahi + offA0 + kb);
            fAh1 = *(const uint4*)(p.ahi + offA1 + kb);
            fAl0 = *(const uint4*)(p.alo + offA0 + kb);
            fAl1 = *(const uint4*)(p.alo + offA1 + kb);
            fWh0 = *(const uint4*)(p.whi + offW0 + kb);
            fWh1 = *(const uint4*)(p.whi + offW1 + kb);
            fWl0 = *(const uint4*)(p.wlo + offW0 + kb);
            fWl1 = *(const uint4*)(p.wlo + offW1 + kb);
        }

        #pragma unroll
        for (int ks = 0; ks < 2; ks++) {
            uint32_t bh[4][2], bl[4][2];
            #pragma unroll
            for (int j = 0; j < 2; j++) {
                const uint32_t uoff = (uint32_t)(((2*ks + b_usel) ^ bsw[j]) << 4) + brow[j];
                ldmx4(&bh[2*j][0], sWh + uoff);
                ldmx4(&bl[2*j][0], sWl + uoff);
            }
            #pragma unroll
            for (int mt = 0; mt < 4; mt++) {
                uint32_t ah[4], al[4];
                const uint32_t uoff = (uint32_t)(((2*ks + a_usel) ^ asw[mt]) << 4) + arow[mt];
                ldmx4(ah, sAh + uoff);
                ldmx4(al, sAl + uoff);
                #pragma unroll
                for (int nt = 0; nt < 4; nt++) {
                    mma_f16(acc[mt][nt], ah, bh[nt]);
                    mma_f16(acc[mt][nt], ah, bl[nt]);
                    mma_f16(acc[mt][nt], al, bh[nt]);
                }
            }
        }
    }

    #pragma unroll
    for (int mt = 0; mt < 4; mt++) {
        const int row0 = bm + wm*64 + mt*16 + (lane >> 2);
        #pragma unroll
        for (int nt = 0; nt < 4; nt++) {
            const int col = bn + wn*32 + nt*8 + (lane & 3)*2;
            const float2 bv = *(const float2*)(p.bias + col);
            float x0 = acc[mt][nt][0] + bv.x, y0 = acc[mt][nt][1] + bv.y;
            float x1 = acc[mt][nt][2] + bv.x, y1 = acc[mt][nt][3] + bv.y;
            if (p.outf) {
                *(float2*)(p.outf + (size_t)row0*DM + col)     = make_float2(x0, y0);
                *(float2*)(p.outf + (size_t)(row0+8)*DM + col) = make_float2(x1, y1);
            } else {
                uint32_t l0, l1;
                uint32_t h0 = split2h(x0, y0, l0);
                uint32_t h1 = split2h(x1, y1, l1);
                *(uint32_t*)(p.outh + (size_t)row0*DM + col)     = h0;
                *(uint32_t*)(p.outl + (size_t)row0*DM + col)     = l0;
                *(uint32_t*)(p.outh + (size_t)(row0+8)*DM + col) = h1;
                *(uint32_t*)(p.outl + (size_t)(row0+8)*DM + col) = l1;
            }
        }
    }
}

// ---- flash attention: QK 2-term (Q corrected), PV 2-term (P corrected) -
// CTA = 128 queries x (b,h); 8 warps m16; KV block 64.
// smem: Qh 16K | Ql 16K | Kh 8K | Vh 8K = 48K
#define ATT_SMEM 49152

__global__ __launch_bounds__(256, 2) void flash_attn_mma(
    const __half* __restrict__ Qh, const __half* __restrict__ Ql,
    const __half* __restrict__ Kh, const __half* __restrict__ Vh,
    const int* __restrict__ mask,
    __half* __restrict__ Oh, __half* __restrict__ Ol)
{
    extern __shared__ char sm[];
    const uint32_t sb = smem_u32(sm);
    const uint32_t sQh = sb, sQl = sb + 16384;
    const uint32_t sKh = sb + 32768, sVh = sb + 40960;

    const int tid = threadIdx.x, lane = tid & 31, wid = tid >> 5;
    const int qb = blockIdx.x, bh = blockIdx.y;
    const int b = bh >> 4, h = bh & 15;
    const int q0 = qb*128;
    const size_t rowbase = (size_t)b*S_LEN;
    const int hoff = h*DK;
    const int allones = g_mask_ones;

    #pragma unroll
    for (int t = 0; t < 4; t++) {
        const int idx = tid + t*256;
        const int r = idx >> 3, uu = idx & 7;
        const size_t g = (rowbase + q0 + r)*DM + hoff + uu*8;
        const uint32_t d = (uint32_t)(r*128 + ((uu ^ (r & 7)) << 4));
        *(uint4*)(sm + (sQh - sb) + d) = *(const uint4*)(Qh + g);
        *(uint4*)(sm + (sQl - sb) + d) = *(const uint4*)(Ql + g);
    }

    const int sub = lane >> 3, l7 = lane & 7;
    const int a_r = ((sub & 1) << 3) + l7, a_us = sub >> 1;
    const int b_nt = sub >> 1, b_us = sub & 1;
    const int qrow = wid*16 + a_r;
    const int vro = ((sub & 1) << 3) + l7, vus = sub >> 1;

    float o[8][4];
    #pragma unroll
    for (int nt = 0; nt < 8; nt++)
        #pragma unroll
        for (int e = 0; e < 4; e++) o[nt][e] = 0.f;
    float m0 = -3.0e38f, m1 = -3.0e38f, l0 = 0.f, l1 = 0.f;

    for (int kb = 0; kb < S_LEN/64; kb++) {
        const int k0g = kb*64;

        #pragma unroll
        for (int t = 0; t < 2; t++) {
            const int idx = tid + t*256;
            const int r = idx >> 3, uu = idx & 7;
            const size_t g = (rowbase + k0g + r)*DM + hoff + uu*8;
            const uint32_t d = (uint32_t)(r*128 + ((uu ^ (r & 7)) << 4));
            *(uint4*)(sm + (sKh - sb) + d) = *(const uint4*)(Kh + g);
            *(uint4*)(sm + (sVh - sb) + d) = *(const uint4*)(Vh + g);
        }
        __syncthreads();

        float c[8][4];
        #pragma unroll
        for (int j = 0; j < 8; j++)
            #pragma unroll
            for (int e = 0; e < 4; e++) c[j][e] = 0.f;

        #pragma unroll
        for (int ks = 0; ks < 4; ks++) {
            uint32_t ah[4], al[4];
            const uint32_t ua = (uint32_t)((((2*ks + a_us) ^ (qrow & 7)) << 4) + qrow*128);
            ldmx4(ah, sQh + ua);
            ldmx4(al, sQl + ua);
            #pragma unroll
            for (int jp = 0; jp < 4; jp++) {
                uint32_t kh4[4];
                const int nr = jp*16 + b_nt*8 + l7;
                ldmx4(kh4, sKh + (uint32_t)((((2*ks + b_us) ^ (nr & 7)) << 4) + nr*128));
                mma_f16(c[2*jp],   ah, kh4);
                mma_f16(c[2*jp],   al, kh4);
                mma_f16(c[2*jp+1], ah, kh4 + 2);
                mma_f16(c[2*jp+1], al, kh4 + 2);
            }
        }

        if (allones) {
            #pragma unroll
            for (int j = 0; j < 8; j++)
                #pragma unroll
                for (int e = 0; e < 4; e++) c[j][e] *= 0.125f;
        } else {
            const int qg0 = q0 + wid*16 + (lane >> 2);
            #pragma unroll
            for (int j = 0; j < 8; j++) {
                const int colb = k0g + j*8 + 2*(lane & 3);
                #pragma unroll
                for (int e = 0; e < 4; e++) {
                    const int qq = (e < 2) ? qg0 : qg0 + 8;
                    const int mv = mask[(size_t)qq*S_LEN + colb + (e & 1)];
                    c[j][e] = mv ? c[j][e]*0.125f : -1e9f;
                }
            }
        }

        float rm0 = -3.0e38f, rm1 = -3.0e38f;
        #pragma unroll
        for (int j = 0; j < 8; j++) {
            rm0 = fmaxf(rm0, fmaxf(c[j][0], c[j][1]));
            rm1 = fmaxf(rm1, fmaxf(c[j][2], c[j][3]));
        }
        rm0 = fmaxf(rm0, __shfl_xor_sync(0xffffffffu, rm0, 1));
        rm0 = fmaxf(rm0, __shfl_xor_sync(0xffffffffu, rm0, 2));
        rm1 = fmaxf(rm1, __shfl_xor_sync(0xffffffffu, rm1, 1));
        rm1 = fmaxf(rm1, __shfl_xor_sync(0xffffffffu, rm1, 2));
        const float mn0 = fmaxf(m0, rm0), mn1 = fmaxf(m1, rm1);
        const float al0 = __expf(m0 - mn0), al1 = __expf(m1 - mn1);
        float rs0 = 0.f, rs1 = 0.f;
        #pragma unroll
        for (int j = 0; j < 8; j++) {
            c[j][0] = __expf(c[j][0] - mn0);
            c[j][1] = __expf(c[j][1] - mn0);
            c[j][2] = __expf(c[j][2] - mn1);
            c[j][3] = __expf(c[j][3] - mn1);
            rs0 += c[j][0] + c[j][1];
            rs1 += c[j][2] + c[j][3];
        }
        rs0 += __shfl_xor_sync(0xffffffffu, rs0, 1);
        rs0 += __shfl_xor_sync(0xffffffffu, rs0, 2);
        rs1 += __shfl_xor_sync(0xffffffffu, rs1, 1);
        rs1 += __shfl_xor_sync(0xffffffffu, rs1, 2);
        l0 = l0*al0 + rs0;
        l1 = l1*al1 + rs1;
        m0 = mn0; m1 = mn1;
        #pragma unroll
        for (int nt = 0; nt < 8; nt++) {
            o[nt][0] *= al0; o[nt][1] *= al0;
            o[nt][2] *= al1; o[nt][3] *= al1;
        }

        #pragma unroll
        for (int kt = 0; kt < 4; kt++) {
            uint32_t ph[4], pl[4];
            ph[0] = split2h(c[2*kt][0],   c[2*kt][1],   pl[0]);
            ph[1] = split2h(c[2*kt][2],   c[2*kt][3],   pl[1]);
            ph[2] = split2h(c[2*kt+1][0], c[2*kt+1][1], pl[2]);
            ph[3] = split2h(c[2*kt+1][2], c[2*kt+1][3], pl[3]);
            const int tv = kt*16 + vro;
            #pragma unroll
            for (int dp = 0; dp < 4; dp++) {
                uint32_t vh4[4];
                ldmx4t(vh4, sVh + (uint32_t)((((2*dp + vus) ^ (tv & 7)) << 4) + tv*128));
                mma_f16(o[2*dp],   ph, vh4);
                mma_f16(o[2*dp],   pl, vh4);
                mma_f16(o[2*dp+1], ph, vh4 + 2);
                mma_f16(o[2*dp+1], pl, vh4 + 2);
            }
        }
        __syncthreads();
    }

    const float inv0 = 1.f/l0, inv1 = 1.f/l1;
    const size_t gr0 = rowbase + q0 + wid*16 + (lane >> 2);
    #pragma unroll
    for (int nt = 0; nt < 8; nt++) {
        const int col = hoff + nt*8 + 2*(lane & 3);
        uint32_t lo0, lo1;
        const uint32_t h0 = split2h(o[nt][0]*inv0, o[nt][1]*inv0, lo0);
        const uint32_t h1 = split2h(o[nt][2]*inv1, o[nt][3]*inv1, lo1);
        *(uint32_t*)(Oh + gr0*DM + col)     = h0;
        *(uint32_t*)(Ol + gr0*DM + col)     = lo0;
        *(uint32_t*)(Oh + (gr0+8)*DM + col) = h1;
        *(uint32_t*)(Ol + (gr0+8)*DM + col) = lo1;
    }
}

// ---- host --------------------------------------------------------------
extern "C" void kernel_launch(void* const* d_in, const int* in_sizes, int n_in,
                              void* d_out, int out_size)
{
    const float* q    = (const float*)d_in[0];
    const float* k    = (const float*)d_in[1];
    const float* v    = (const float*)d_in[2];
    const int*   mask = (const int*)  d_in[3];
    const float* Wq   = (const float*)d_in[4];
    const float* bq   = (const float*)d_in[5];
    const float* Wk   = (const float*)d_in[6];
    const float* bk   = (const float*)d_in[7];
    const float* Wv   = (const float*)d_in[8];
    const float* bv   = (const float*)d_in[9];
    const float* Wo   = (const float*)d_in[10];
    const float* bo   = (const float*)d_in[11];
    float* out = (float*)d_out;

    __half *qh,*ql,*kh,*kl,*vh,*vl,*wqh,*wql,*wkh,*wkl,*wvh,*wvl,*woh,*wol;
    __half *Qh,*Ql,*Kh,*Kl,*Vh,*Vl,*Ah,*Al;
    cudaGetSymbolAddress((void**)&qh, g_qh);   cudaGetSymbolAddress((void**)&ql, g_ql);
    cudaGetSymbolAddress((void**)&kh, g_kh);   cudaGetSymbolAddress((void**)&kl, g_kl);
    cudaGetSymbolAddress((void**)&vh, g_vh);   cudaGetSymbolAddress((void**)&vl, g_vl);
    cudaGetSymbolAddress((void**)&wqh, g_wqh); cudaGetSymbolAddress((void**)&wql, g_wql);
    cudaGetSymbolAddress((void**)&wkh, g_wkh); cudaGetSymbolAddress((void**)&wkl, g_wkl);
    cudaGetSymbolAddress((void**)&wvh, g_wvh); cudaGetSymbolAddress((void**)&wvl, g_wvl);
    cudaGetSymbolAddress((void**)&woh, g_woh); cudaGetSymbolAddress((void**)&wol, g_wol);
    cudaGetSymbolAddress((void**)&Qh, g_Qh);   cudaGetSymbolAddress((void**)&Ql, g_Ql);
    cudaGetSymbolAddress((void**)&Kh, g_Kh);   cudaGetSymbolAddress((void**)&Kl, g_Kl);
    cudaGetSymbolAddress((void**)&Vh, g_Vh);   cudaGetSymbolAddress((void**)&Vl, g_Vl);
    cudaGetSymbolAddress((void**)&Ah, g_Ah);   cudaGetSymbolAddress((void**)&Al, g_Al);

    cudaFuncSetAttribute(flash_attn_mma, cudaFuncAttributeMaxDynamicSharedMemorySize, ATT_SMEM);

    const int n4_in = MROWS*DM/4, n4_w = DM*DM/4;

    reset_flag<<<1, 1>>>();
    check_mask<<<1024, 256>>>(mask, S_LEN*S_LEN);

    split_h<<<n4_in/256, 256>>>(q,  qh,  ql,  n4_in);
    split_h<<<n4_in/256, 256>>>(k,  kh,  kl,  n4_in);
    split_h<<<n4_in/256, 256>>>(v,  vh,  vl,  n4_in);
    split_h<<<n4_w/256,  256>>>(Wq, wqh, wql, n4_w);
    split_h<<<n4_w/256,  256>>>(Wk, wkh, wkl, n4_w);
    split_h<<<n4_w/256,  256>>>(Wv, wvh, wvl, n4_w);
    split_h<<<n4_w/256,  256>>>(Wo, woh, wol, n4_w);

    GemmP pq = { qh, ql, wqh, wql, bq, nullptr, Qh, Ql };
    GemmP pk = { kh, kl, wkh, wkl, bk, nullptr, Kh, Kl };
    GemmP pv = { vh, vl, wvh, wvl, bv, nullptr, Vh, Vl };
    dim3 gg3(DM/128, MROWS/128, 3);
    gemm_hmma<<<gg3, 256>>>(pq, pk, pv);

    dim3 ga(S_LEN/128, B_SZ*NH);
    flash_attn_mma<<<ga, 256, ATT_SMEM>>>(Qh, Ql, Kh, Vh, mask, Ah, Al);

    GemmP po = { Ah, Al, woh, wol, bo, out, nullptr, nullptr };
    dim3 gg1(DM/128, MROWS/128, 1);
    gemm_hmma<<<gg1, 256>>>(po, po, po);
}

// round 10
// speedup vs baseline: 1.7110x; 1.2229x over previous
#include <cuda_runtime.h>
#include <cuda_fp16.h>
#include <cstdint>
#include <math.h>

#define S_LEN 2048
#define B_SZ  2
#define DM    1024
#define NH    16
#define DK    64
#define MROWS (B_SZ * S_LEN)

// ---- scratch -----------------------------------------------------------
__device__ __half g_qh[MROWS*DM], g_ql[MROWS*DM];
__device__ __half g_kh[MROWS*DM], g_kl[MROWS*DM];
__device__ __half g_vh[MROWS*DM], g_vl[MROWS*DM];
__device__ __half g_wqh[DM*DM], g_wkh[DM*DM], g_wvh[DM*DM], g_woh[DM*DM];
__device__ __half g_Qh[MROWS*DM], g_Kh[MROWS*DM], g_Vh[MROWS*DM];
__device__ __half g_Ah[MROWS*DM], g_Al[MROWS*DM];
__device__ int g_mask_ones;

// ---- helpers -----------------------------------------------------------
__device__ __forceinline__ uint32_t smem_u32(const void* p) {
    uint32_t a;
    asm("{ .reg .u64 t; cvta.to.shared.u64 t, %1; cvt.u32.u64 %0, t; }" : "=r"(a) : "l"(p));
    return a;
}
__device__ __forceinline__ void ldmx4(uint32_t* r, uint32_t addr) {
    asm volatile("ldmatrix.sync.aligned.m8n8.x4.shared.b16 {%0,%1,%2,%3}, [%4];"
                 : "=r"(r[0]), "=r"(r[1]), "=r"(r[2]), "=r"(r[3]) : "r"(addr));
}
__device__ __forceinline__ void ldmx4t(uint32_t* r, uint32_t addr) {
    asm volatile("ldmatrix.sync.aligned.m8n8.x4.trans.shared.b16 {%0,%1,%2,%3}, [%4];"
                 : "=r"(r[0]), "=r"(r[1]), "=r"(r[2]), "=r"(r[3]) : "r"(addr));
}
__device__ __forceinline__ void mma_f16(float* c, const uint32_t* a, const uint32_t* b) {
    asm volatile("mma.sync.aligned.m16n8k16.row.col.f32.f16.f16.f32 "
                 "{%0,%1,%2,%3}, {%4,%5,%6,%7}, {%8,%9}, {%0,%1,%2,%3};"
                 : "+f"(c[0]), "+f"(c[1]), "+f"(c[2]), "+f"(c[3])
                 : "r"(a[0]), "r"(a[1]), "r"(a[2]), "r"(a[3]), "r"(b[0]), "r"(b[1]));
}
__device__ __forceinline__ uint32_t split2h(float x, float y, uint32_t& lo) {
    __half hx = __float2half_rn(x), hy = __float2half_rn(y);
    __half2 h(hx, hy), l(__float2half_rn(x - __half2float(hx)),
                         __float2half_rn(y - __half2float(hy)));
    lo = *reinterpret_cast<uint32_t*>(&l);
    return *reinterpret_cast<uint32_t*>(&h);
}

__global__ void reset_flag() { g_mask_ones = 1; }
__global__ __launch_bounds__(256) void check_mask(const int* __restrict__ m, int n) {
    int i = blockIdx.x * blockDim.x + threadIdx.x;
    int ok = 1;
    for (; i < n; i += gridDim.x * blockDim.x) ok &= (m[i] != 0);
    ok = __all_sync(0xffffffffu, ok);
    if ((threadIdx.x & 31) == 0 && !ok) atomicExch(&g_mask_ones, 0);
}

// ---- fp32 -> (fp16 hi, fp16 lo) ----------------------------------------
__global__ __launch_bounds__(256) void split_h(
    const float* __restrict__ x, __half* __restrict__ hi,
    __half* __restrict__ lo, int n4)
{
    int i = blockIdx.x * blockDim.x + threadIdx.x;
    if (i >= n4) return;
    float4 v = ((const float4*)x)[i];
    uint32_t l0, l1;
    uint32_t h0 = split2h(v.x, v.y, l0);
    uint32_t h1 = split2h(v.z, v.w, l1);
    ((uint32_t*)hi)[2*i] = h0; ((uint32_t*)hi)[2*i+1] = h1;
    ((uint32_t*)lo)[2*i] = l0; ((uint32_t*)lo)[2*i+1] = l1;
}

// ---- fp32 -> fp16 (weights: hi only) -----------------------------------
__global__ __launch_bounds__(256) void conv_h(
    const float* __restrict__ x, __half* __restrict__ hi, int n4)
{
    int i = blockIdx.x * blockDim.x + threadIdx.x;
    if (i >= n4) return;
    float4 v = ((const float4*)x)[i];
    __half2 a(__float2half_rn(v.x), __float2half_rn(v.y));
    __half2 b(__float2half_rn(v.z), __float2half_rn(v.w));
    ((uint32_t*)hi)[2*i]   = *reinterpret_cast<uint32_t*>(&a);
    ((uint32_t*)hi)[2*i+1] = *reinterpret_cast<uint32_t*>(&b);
}

// ---- GEMM: C = (Ah+Al)@Wh^T + bias ; fp16 2-term (A corrected) ---------
struct GemmP {
    const __half *ah, *al, *wh;
    const float* bias;
    float* outf;     // fp32 out (final projection)
    __half* outh;    // fp16-hi out (QKV projections)
};

#define GT_BYTES 8192   // 128 x 32 fp16

__global__ __launch_bounds__(256, 1) void gemm_hmma(GemmP p0, GemmP p1, GemmP p2)
{
    __shared__ char smem[3 * GT_BYTES];   // Ah | Al | Wh
    GemmP p = (blockIdx.z == 0) ? p0 : (blockIdx.z == 1 ? p1 : p2);

    const int tid = threadIdx.x, lane = tid & 31, wid = tid >> 5;
    const int wm = wid & 1, wn = wid >> 1;
    const int bm = blockIdx.y * 128, bn = blockIdx.x * 128;

    const uint32_t sb = smem_u32(smem);
    const uint32_t sAh = sb, sAl = sb + GT_BYTES, sWh = sb + 2*GT_BYTES;

    const int u = tid & 3, r0 = tid >> 2, r1 = r0 + 64;
    const uint32_t d0 = (uint32_t)(r0*64 + ((u ^ ((r0 >> 1) & 3)) << 4));
    const uint32_t d1 = (uint32_t)(r1*64 + ((u ^ ((r1 >> 1) & 3)) << 4));
    const size_t offA0 = (size_t)(bm + r0)*DM + u*8, offA1 = (size_t)(bm + r1)*DM + u*8;
    const size_t offW0 = (size_t)(bn + r0)*DM + u*8, offW1 = (size_t)(bn + r1)*DM + u*8;

    const int sub = lane >> 3;
    const int a_r16 = ((sub & 1) << 3) + (lane & 7), a_usel = sub >> 1;
    const int b_nt = sub >> 1, b_usel = sub & 1, b_r8 = lane & 7;

    int arow[4], asw[4];
    #pragma unroll
    for (int mt = 0; mt < 4; mt++) {
        const int gr = wm*64 + mt*16 + a_r16;
        arow[mt] = gr*64; asw[mt] = (gr >> 1) & 3;
    }
    int brow[2], bsw[2];
    #pragma unroll
    for (int j = 0; j < 2; j++) {
        const int nr = wn*32 + (2*j + b_nt)*8 + b_r8;
        brow[j] = nr*64; bsw[j] = (nr >> 1) & 3;
    }

    float acc[4][4][4];
    #pragma unroll
    for (int mt = 0; mt < 4; mt++)
        #pragma unroll
        for (int nt = 0; nt < 4; nt++)
            #pragma unroll
            for (int r = 0; r < 4; r++) acc[mt][nt][r] = 0.f;

    uint4 fAh0 = *(const uint4*)(p.ah + offA0), fAh1 = *(const uint4*)(p.ah + offA1);
    uint4 fAl0 = *(const uint4*)(p.al + offA0), fAl1 = *(const uint4*)(p.al + offA1);
    uint4 fW0  = *(const uint4*)(p.wh + offW0), fW1  = *(const uint4*)(p.wh + offW1);

    for (int ch = 0; ch < DM/32; ch++) {
        __syncthreads();
        *(uint4*)(smem + (sAh - sb) + d0) = fAh0;
        *(uint4*)(smem + (sAh - sb) + d1) = fAh1;
        *(uint4*)(smem + (sAl - sb) + d0) = fAl0;
        *(uint4*)(smem + (sAl - sb) + d1) = fAl1;
        *(uint4*)(smem + (sWh - sb) + d0) = fW0;
        *(uint4*)(smem + (sWh - sb) + d1) = fW1;
        __syncthreads();

        if (ch + 1 < DM/32) {
            const int kb = (ch + 1)*32;
            fAh0 = *(const uint4*)(p.ah + offA0 + kb);
            fAh1 = *(const uint4*)(p.ah + offA1 + kb);
            fAl0 = *(const uint4*)(p.al + offA0 + kb);
            fAl1 = *(const uint4*)(p.al + offA1 + kb);
            fW0  = *(const uint4*)(p.wh + offW0 + kb);
            fW1  = *(const uint4*)(p.wh + offW1 + kb);
        }

        #pragma unroll
        for (int ks = 0; ks < 2; ks++) {
            uint32_t bh[4][2];
            #pragma unroll
            for (int j = 0; j < 2; j++) {
                const uint32_t uoff = (uint32_t)(((2*ks + b_usel) ^ bsw[j]) << 4) + brow[j];
                ldmx4(&bh[2*j][0], sWh + uoff);
            }
            #pragma unroll
            for (int mt = 0; mt < 4; mt++) {
                uint32_t ah[4], al[4];
                const uint32_t uoff = (uint32_t)(((2*ks + a_usel) ^ asw[mt]) << 4) + arow[mt];
                ldmx4(ah, sAh + uoff);
                ldmx4(al, sAl + uoff);
                #pragma unroll
                for (int nt = 0; nt < 4; nt++) {
                    mma_f16(acc[mt][nt], ah, bh[nt]);
                    mma_f16(acc[mt][nt], al, bh[nt]);
                }
            }
        }
    }

    #pragma unroll
    for (int mt = 0; mt < 4; mt++) {
        const int row0 = bm + wm*64 + mt*16 + (lane >> 2);
        #pragma unroll
        for (int nt = 0; nt < 4; nt++) {
            const int col = bn + wn*32 + nt*8 + (lane & 3)*2;
            const float2 bv = *(const float2*)(p.bias + col);
            float x0 = acc[mt][nt][0] + bv.x, y0 = acc[mt][nt][1] + bv.y;
            float x1 = acc[mt][nt][2] + bv.x, y1 = acc[mt][nt][3] + bv.y;
            if (p.outf) {
                *(float2*)(p.outf + (size_t)row0*DM + col)     = make_float2(x0, y0);
                *(float2*)(p.outf + (size_t)(row0+8)*DM + col) = make_float2(x1, y1);
            } else {
                __half2 h0(__float2half_rn(x0), __float2half_rn(y0));
                __half2 h1(__float2half_rn(x1), __float2half_rn(y1));
                *(uint32_t*)(p.outh + (size_t)row0*DM + col)     = *reinterpret_cast<uint32_t*>(&h0);
                *(uint32_t*)(p.outh + (size_t)(row0+8)*DM + col) = *reinterpret_cast<uint32_t*>(&h1);
            }
        }
    }
}

// ---- flash attention: QK pure fp16; PV 2-term (P corrected) ------------
// CTA = 128 queries x (b,h); 8 warps m16; KV block 64.
// smem: Qh 16K | Kh 8K | Vh 8K = 32K
#define ATT_SMEM 32768

__global__ __launch_bounds__(256, 2) void flash_attn_mma(
    const __half* __restrict__ Qh,
    const __half* __restrict__ Kh, const __half* __restrict__ Vh,
    const int* __restrict__ mask,
    __half* __restrict__ Oh, __half* __restrict__ Ol)
{
    extern __shared__ char sm[];
    const uint32_t sb = smem_u32(sm);
    const uint32_t sQh = sb, sKh = sb + 16384, sVh = sb + 24576;

    const int tid = threadIdx.x, lane = tid & 31, wid = tid >> 5;
    const int qb = blockIdx.x, bh = blockIdx.y;
    const int b = bh >> 4, h = bh & 15;
    const int q0 = qb*128;
    const size_t rowbase = (size_t)b*S_LEN;
    const int hoff = h*DK;
    const int allones = g_mask_ones;

    #pragma unroll
    for (int t = 0; t < 4; t++) {
        const int idx = tid + t*256;
        const int r = idx >> 3, uu = idx & 7;
        const size_t g = (rowbase + q0 + r)*DM + hoff + uu*8;
        const uint32_t d = (uint32_t)(r*128 + ((uu ^ (r & 7)) << 4));
        *(uint4*)(sm + (sQh - sb) + d) = *(const uint4*)(Qh + g);
    }

    const int sub = lane >> 3, l7 = lane & 7;
    const int a_r = ((sub & 1) << 3) + l7, a_us = sub >> 1;
    const int b_nt = sub >> 1, b_us = sub & 1;
    const int qrow = wid*16 + a_r;
    const int vro = ((sub & 1) << 3) + l7, vus = sub >> 1;

    float o[8][4];
    #pragma unroll
    for (int nt = 0; nt < 8; nt++)
        #pragma unroll
        for (int e = 0; e < 4; e++) o[nt][e] = 0.f;
    float m0 = -3.0e38f, m1 = -3.0e38f, l0 = 0.f, l1 = 0.f;

    for (int kb = 0; kb < S_LEN/64; kb++) {
        const int k0g = kb*64;

        #pragma unroll
        for (int t = 0; t < 2; t++) {
            const int idx = tid + t*256;
            const int r = idx >> 3, uu = idx & 7;
            const size_t g = (rowbase + k0g + r)*DM + hoff + uu*8;
            const uint32_t d = (uint32_t)(r*128 + ((uu ^ (r & 7)) << 4));
            *(uint4*)(sm + (sKh - sb) + d) = *(const uint4*)(Kh + g);
            *(uint4*)(sm + (sVh - sb) + d) = *(const uint4*)(Vh + g);
        }
        __syncthreads();

        float c[8][4];
        #pragma unroll
        for (int j = 0; j < 8; j++)
            #pragma unroll
            for (int e = 0; e < 4; e++) c[j][e] = 0.f;

        #pragma unroll
        for (int ks = 0; ks < 4; ks++) {
            uint32_t ah[4];
            const uint32_t ua = (uint32_t)((((2*ks + a_us) ^ (qrow & 7)) << 4) + qrow*128);
            ldmx4(ah, sQh + ua);
            #pragma unroll
            for (int jp = 0; jp < 4; jp++) {
                uint32_t kh4[4];
                const int nr = jp*16 + b_nt*8 + l7;
                ldmx4(kh4, sKh + (uint32_t)((((2*ks + b_us) ^ (nr & 7)) << 4) + nr*128));
                mma_f16(c[2*jp],   ah, kh4);
                mma_f16(c[2*jp+1], ah, kh4 + 2);
            }
        }

        if (allones) {
            #pragma unroll
            for (int j = 0; j < 8; j++)
                #pragma unroll
                for (int e = 0; e < 4; e++) c[j][e] *= 0.125f;
        } else {
            const int qg0 = q0 + wid*16 + (lane >> 2);
            #pragma unroll
            for (int j = 0; j < 8; j++) {
                const int colb = k0g + j*8 + 2*(lane & 3);
                #pragma unroll
                for (int e = 0; e < 4; e++) {
                    const int qq = (e < 2) ? qg0 : qg0 + 8;
                    const int mv = mask[(size_t)qq*S_LEN + colb + (e & 1)];
                    c[j][e] = mv ? c[j][e]*0.125f : -1e9f;
                }
            }
        }

        float rm0 = -3.0e38f, rm1 = -3.0e38f;
        #pragma unroll
        for (int j = 0; j < 8; j++) {
            rm0 = fmaxf(rm0, fmaxf(c[j][0], c[j][1]));
            rm1 = fmaxf(rm1, fmaxf(c[j][2], c[j][3]));
        }
        rm0 = fmaxf(rm0, __shfl_xor_sync(0xffffffffu, rm0, 1));
        rm0 = fmaxf(rm0, __shfl_xor_sync(0xffffffffu, rm0, 2));
        rm1 = fmaxf(rm1, __shfl_xor_sync(0xffffffffu, rm1, 1));
        rm1 = fmaxf(rm1, __shfl_xor_sync(0xffffffffu, rm1, 2));
        const float mn0 = fmaxf(m0, rm0), mn1 = fmaxf(m1, rm1);
        const float al0 = __expf(m0 - mn0), al1 = __expf(m1 - mn1);
        float rs0 = 0.f, rs1 = 0.f;
        #pragma unroll
        for (int j = 0; j < 8; j++) {
            c[j][0] = __expf(c[j][0] - mn0);
            c[j][1] = __expf(c[j][1] - mn0);
            c[j][2] = __expf(c[j][2] - mn1);
            c[j][3] = __expf(c[j][3] - mn1);
            rs0 += c[j][0] + c[j][1];
            rs1 += c[j][2] + c[j][3];
        }
        rs0 += __shfl_xor_sync(0xffffffffu, rs0, 1);
        rs0 += __shfl_xor_sync(0xffffffffu, rs0, 2);
        rs1 += __shfl_xor_sync(0xffffffffu, rs1, 1);
        rs1 += __shfl_xor_sync(0xffffffffu, rs1, 2);
        l0 = l0*al0 + rs0;
        l1 = l1*al1 + rs1;
        m0 = mn0; m1 = mn1;
        #pragma unroll
        for (int nt = 0; nt < 8; nt++) {
            o[nt][0] *= al0; o[nt][1] *= al0;
            o[nt][2] *= al1; o[nt][3] *= al1;
        }

        #pragma unroll
        for (int kt = 0; kt < 4; kt++) {
            uint32_t ph[4], pl[4];
            ph[0] = split2h(c[2*kt][0],   c[2*kt][1],   pl[0]);
            ph[1] = split2h(c[2*kt][2],   c[2*kt][3],   pl[1]);
            ph[2] = split2h(c[2*kt+1][0], c[2*kt+1][1], pl[2]);
            ph[3] = split2h(c[2*kt+1][2], c[2*kt+1][3], pl[3]);
            const int tv = kt*16 + vro;
            #pragma unroll
            for (int dp = 0; dp < 4; dp++) {
                uint32_t vh4[4];
                ldmx4t(vh4, sVh + (uint32_t)((((2*dp + vus) ^ (tv & 7)) << 4) + tv*128));
                mma_f16(o[2*dp],   ph, vh4);
                mma_f16(o[2*dp],   pl, vh4);
                mma_f16(o[2*dp+1], ph, vh4 + 2);
                mma_f16(o[2*dp+1], pl, vh4 + 2);
            }
        }
        __syncthreads();
    }

    const float inv0 = 1.f/l0, inv1 = 1.f/l1;
    const size_t gr0 = rowbase + q0 + wid*16 + (lane >> 2);
    #pragma unroll
    for (int nt = 0; nt < 8; nt++) {
        const int col = hoff + nt*8 + 2*(lane & 3);
        uint32_t lo0, lo1;
        const uint32_t h0 = split2h(o[nt][0]*inv0, o[nt][1]*inv0, lo0);
        const uint32_t h1 = split2h(o[nt][2]*inv1, o[nt][3]*inv1, lo1);
        *(uint32_t*)(Oh + gr0*DM + col)     = h0;
        *(uint32_t*)(Ol + gr0*DM + col)     = lo0;
        *(uint32_t*)(Oh + (gr0+8)*DM + col) = h1;
        *(uint32_t*)(Ol + (gr0+8)*DM + col) = lo1;
    }
}

// ---- host --------------------------------------------------------------
extern "C" void kernel_launch(void* const* d_in, const int* in_sizes, int n_in,
                              void* d_out, int out_size)
{
    const float* q    = (const float*)d_in[0];
    const float* k    = (const float*)d_in[1];
    const float* v    = (const float*)d_in[2];
    const int*   mask = (const int*)  d_in[3];
    const float* Wq   = (const float*)d_in[4];
    const float* bq   = (const float*)d_in[5];
    const float* Wk   = (const float*)d_in[6];
    const float* bk   = (const float*)d_in[7];
    const float* Wv   = (const float*)d_in[8];
    const float* bv   = (const float*)d_in[9];
    const float* Wo   = (const float*)d_in[10];
    const float* bo   = (const float*)d_in[11];
    float* out = (float*)d_out;

    __half *qh,*ql,*kh,*kl,*vh,*vl,*wqh,*wkh,*wvh,*woh;
    __half *Qh,*Kh,*Vh,*Ah,*Al;
    cudaGetSymbolAddress((void**)&qh, g_qh);   cudaGetSymbolAddress((void**)&ql, g_ql);
    cudaGetSymbolAddress((void**)&kh, g_kh);   cudaGetSymbolAddress((void**)&kl, g_kl);
    cudaGetSymbolAddress((void**)&vh, g_vh);   cudaGetSymbolAddress((void**)&vl, g_vl);
    cudaGetSymbolAddress((void**)&wqh, g_wqh); cudaGetSymbolAddress((void**)&wkh, g_wkh);
    cudaGetSymbolAddress((void**)&wvh, g_wvh); cudaGetSymbolAddress((void**)&woh, g_woh);
    cudaGetSymbolAddress((void**)&Qh, g_Qh);   cudaGetSymbolAddress((void**)&Kh, g_Kh);
    cudaGetSymbolAddress((void**)&Vh, g_Vh);
    cudaGetSymbolAddress((void**)&Ah, g_Ah);   cudaGetSymbolAddress((void**)&Al, g_Al);

    cudaFuncSetAttribute(flash_attn_mma, cudaFuncAttributeMaxDynamicSharedMemorySize, ATT_SMEM);

    const int n4_in = MROWS*DM/4, n4_w = DM*DM/4;

    reset_flag<<<1, 1>>>();
    check_mask<<<1024, 256>>>(mask, S_LEN*S_LEN);

    split_h<<<n4_in/256, 256>>>(q, qh, ql, n4_in);
    split_h<<<n4_in/256, 256>>>(k, kh, kl, n4_in);
    split_h<<<n4_in/256, 256>>>(v, vh, vl, n4_in);
    conv_h<<<n4_w/256, 256>>>(Wq, wqh, n4_w);
    conv_h<<<n4_w/256, 256>>>(Wk, wkh, n4_w);
    conv_h<<<n4_w/256, 256>>>(Wv, wvh, n4_w);
    conv_h<<<n4_w/256, 256>>>(Wo, woh, n4_w);

    GemmP pq = { qh, ql, wqh, bq, nullptr, Qh };
    GemmP pk = { kh, kl, wkh, bk, nullptr, Kh };
    GemmP pv = { vh, vl, wvh, bv, nullptr, Vh };
    dim3 gg3(DM/128, MROWS/128, 3);
    gemm_hmma<<<gg3, 256>>>(pq, pk, pv);

    dim3 ga(S_LEN/128, B_SZ*NH);
    flash_attn_mma<<<ga, 256, ATT_SMEM>>>(Qh, Kh, Vh, mask, Ah, Al);

    GemmP po = { Ah, Al, woh, bo, out, nullptr };
    dim3 gg1(DM/128, MROWS/128, 1);
    gemm_hmma<<<gg1, 256>>>(po, po, po);
}

// round 12
// speedup vs baseline: 1.7254x; 1.0085x over previous
#include <cuda_runtime.h>
#include <cuda_fp16.h>
#include <cstdint>
#include <math.h>

#define S_LEN 2048
#define B_SZ  2
#define DM    1024
#define NH    16
#define DK    64
#define MROWS (B_SZ * S_LEN)

// ---- scratch -----------------------------------------------------------
__device__ __half g_qh[MROWS*DM], g_ql[MROWS*DM];
__device__ __half g_kh[MROWS*DM], g_kl[MROWS*DM];
__device__ __half g_vh[MROWS*DM], g_vl[MROWS*DM];
__device__ __half g_wqh[DM*DM], g_wkh[DM*DM], g_wvh[DM*DM], g_woh[DM*DM];
__device__ __half g_Qh[MROWS*DM], g_Kh[MROWS*DM], g_Vh[MROWS*DM];
__device__ __half g_Ah[MROWS*DM], g_Al[MROWS*DM];
__device__ int g_mask_ones;

// ---- helpers -----------------------------------------------------------
__device__ __forceinline__ uint32_t smem_u32(const void* p) {
    uint32_t a;
    asm("{ .reg .u64 t; cvta.to.shared.u64 t, %1; cvt.u32.u64 %0, t; }" : "=r"(a) : "l"(p));
    return a;
}
__device__ __forceinline__ void ldmx4(uint32_t* r, uint32_t addr) {
    asm volatile("ldmatrix.sync.aligned.m8n8.x4.shared.b16 {%0,%1,%2,%3}, [%4];"
                 : "=r"(r[0]), "=r"(r[1]), "=r"(r[2]), "=r"(r[3]) : "r"(addr));
}
__device__ __forceinline__ void ldmx4t(uint32_t* r, uint32_t addr) {
    asm volatile("ldmatrix.sync.aligned.m8n8.x4.trans.shared.b16 {%0,%1,%2,%3}, [%4];"
                 : "=r"(r[0]), "=r"(r[1]), "=r"(r[2]), "=r"(r[3]) : "r"(addr));
}
__device__ __forceinline__ void mma_f16(float* c, const uint32_t* a, const uint32_t* b) {
    asm volatile("mma.sync.aligned.m16n8k16.row.col.f32.f16.f16.f32 "
                 "{%0,%1,%2,%3}, {%4,%5,%6,%7}, {%8,%9}, {%0,%1,%2,%3};"
                 : "+f"(c[0]), "+f"(c[1]), "+f"(c[2]), "+f"(c[3])
                 : "r"(a[0]), "r"(a[1]), "r"(a[2]), "r"(a[3]), "r"(b[0]), "r"(b[1]));
}
__device__ __forceinline__ uint32_t split2h(float x, float y, uint32_t& lo) {
    __half hx = __float2half_rn(x), hy = __float2half_rn(y);
    __half2 h(hx, hy), l(__float2half_rn(x - __half2float(hx)),
                         __float2half_rn(y - __half2float(hy)));
    lo = *reinterpret_cast<uint32_t*>(&l);
    return *reinterpret_cast<uint32_t*>(&h);
}

__global__ void reset_flag() { g_mask_ones = 1; }
__global__ __launch_bounds__(256) void check_mask(const int* __restrict__ m, int n) {
    int i = blockIdx.x * blockDim.x + threadIdx.x;
    int ok = 1;
    for (; i < n; i += gridDim.x * blockDim.x) ok &= (m[i] != 0);
    ok = __all_sync(0xffffffffu, ok);
    if ((threadIdx.x & 31) == 0 && !ok) atomicExch(&g_mask_ones, 0);
}

// ---- fused splits: 3 tensors, 2 float4 per thread ----------------------
__global__ __launch_bounds__(256) void split_h3(
    const float* __restrict__ x0, __half* __restrict__ h0, __half* __restrict__ l0,
    const float* __restrict__ x1, __half* __restrict__ h1, __half* __restrict__ l1,
    const float* __restrict__ x2, __half* __restrict__ h2, __half* __restrict__ l2,
    int n4)
{
    const float* x = (blockIdx.y == 0) ? x0 : (blockIdx.y == 1 ? x1 : x2);
    __half* hh = (blockIdx.y == 0) ? h0 : (blockIdx.y == 1 ? h1 : h2);
    __half* ll = (blockIdx.y == 0) ? l0 : (blockIdx.y == 1 ? l1 : l2);
    const int base = blockIdx.x * 512 + threadIdx.x;
    #pragma unroll
    for (int t = 0; t < 2; t++) {
        const int i = base + t * 256;
        if (i >= n4) return;
        float4 v = ((const float4*)x)[i];
        uint32_t lw0, lw1;
        uint32_t hw0 = split2h(v.x, v.y, lw0);
        uint32_t hw1 = split2h(v.z, v.w, lw1);
        ((uint32_t*)hh)[2*i] = hw0; ((uint32_t*)hh)[2*i+1] = hw1;
        ((uint32_t*)ll)[2*i] = lw0; ((uint32_t*)ll)[2*i+1] = lw1;
    }
}

// ---- fused weight converts: 4 tensors, 2 float4 per thread -------------
__global__ __launch_bounds__(256) void conv_h4(
    const float* __restrict__ x0, __half* __restrict__ h0,
    const float* __restrict__ x1, __half* __restrict__ h1,
    const float* __restrict__ x2, __half* __restrict__ h2,
    const float* __restrict__ x3, __half* __restrict__ h3,
    int n4)
{
    const float* x = (blockIdx.y < 2) ? (blockIdx.y == 0 ? x0 : x1)
                                      : (blockIdx.y == 2 ? x2 : x3);
    __half* hh = (blockIdx.y < 2) ? (blockIdx.y == 0 ? h0 : h1)
                                  : (blockIdx.y == 2 ? h2 : h3);
    const int base = blockIdx.x * 512 + threadIdx.x;
    #pragma unroll
    for (int t = 0; t < 2; t++) {
        const int i = base + t * 256;
        if (i >= n4) return;
        float4 v = ((const float4*)x)[i];
        __half2 a(__float2half_rn(v.x), __float2half_rn(v.y));
        __half2 b(__float2half_rn(v.z), __float2half_rn(v.w));
        ((uint32_t*)hh)[2*i]   = *reinterpret_cast<uint32_t*>(&a);
        ((uint32_t*)hh)[2*i+1] = *reinterpret_cast<uint32_t*>(&b);
    }
}

// ---- GEMM: C = (Ah+Al)@Wh^T + bias ; fp16 2-term, double-buffered ------
struct GemmP {
    const __half *ah, *al, *wh;
    const float* bias;
    float* outf;
    __half* outh;
};

#define GT_BYTES 8192           // 128 x 32 fp16
#define GSTAGE   (3 * GT_BYTES) // Ah | Al | Wh per stage

__global__ __launch_bounds__(256, 1) void gemm_hmma(GemmP p0, GemmP p1, GemmP p2)
{
    __shared__ char smem[2 * GSTAGE];   // 49152 B, 2 stages
    GemmP p = (blockIdx.z == 0) ? p0 : (blockIdx.z == 1 ? p1 : p2);

    const int tid = threadIdx.x, lane = tid & 31, wid = tid >> 5;
    const int wm = wid & 1, wn = wid >> 1;
    const int bm = blockIdx.y * 128, bn = blockIdx.x * 128;

    const uint32_t sb = smem_u32(smem);

    const int u = tid & 3, r0 = tid >> 2, r1 = r0 + 64;
    const uint32_t d0 = (uint32_t)(r0*64 + ((u ^ ((r0 >> 1) & 3)) << 4));
    const uint32_t d1 = (uint32_t)(r1*64 + ((u ^ ((r1 >> 1) & 3)) << 4));
    const size_t offA0 = (size_t)(bm + r0)*DM + u*8, offA1 = (size_t)(bm + r1)*DM + u*8;
    const size_t offW0 = (size_t)(bn + r0)*DM + u*8, offW1 = (size_t)(bn + r1)*DM + u*8;

    const int sub = lane >> 3;
    const int a_r16 = ((sub & 1) << 3) + (lane & 7), a_usel = sub >> 1;
    const int b_nt = sub >> 1, b_usel = sub & 1, b_r8 = lane & 7;

    int arow[4], asw[4];
    #pragma unroll
    for (int mt = 0; mt < 4; mt++) {
        const int gr = wm*64 + mt*16 + a_r16;
        arow[mt] = gr*64; asw[mt] = (gr >> 1) & 3;
    }
    int brow[2], bsw[2];
    #pragma unroll
    for (int j = 0; j < 2; j++) {
        const int nr = wn*32 + (2*j + b_nt)*8 + b_r8;
        brow[j] = nr*64; bsw[j] = (nr >> 1) & 3;
    }

    float acc[4][4][4];
    #pragma unroll
    for (int mt = 0; mt < 4; mt++)
        #pragma unroll
        for (int nt = 0; nt < 4; nt++)
            #pragma unroll
            for (int r = 0; r < 4; r++) acc[mt][nt][r] = 0.f;

    // prologue: chunk 0 -> stage 0
    {
        uint4 a0 = *(const uint4*)(p.ah + offA0), a1 = *(const uint4*)(p.ah + offA1);
        uint4 b0 = *(const uint4*)(p.al + offA0), b1 = *(const uint4*)(p.al + offA1);
        uint4 w0 = *(const uint4*)(p.wh + offW0), w1 = *(const uint4*)(p.wh + offW1);
        *(uint4*)(smem + 0*GT_BYTES + d0) = a0; *(uint4*)(smem + 0*GT_BYTES + d1) = a1;
        *(uint4*)(smem + 1*GT_BYTES + d0) = b0; *(uint4*)(smem + 1*GT_BYTES + d1) = b1;
        *(uint4*)(smem + 2*GT_BYTES + d0) = w0; *(uint4*)(smem + 2*GT_BYTES + d1) = w1;
    }
    __syncthreads();

    for (int ch = 0; ch < DM/32; ch++) {
        const int s = ch & 1;
        const uint32_t sAh = sb + s*GSTAGE, sAl = sAh + GT_BYTES, sWh = sAh + 2*GT_BYTES;
        char* nstage = smem + (s ^ 1)*GSTAGE;

        uint4 fa0, fa1, fb0, fb1, fw0, fw1;
        const bool more = (ch + 1 < DM/32);
        if (more) {
            const int kb = (ch + 1)*32;
            fa0 = *(const uint4*)(p.ah + offA0 + kb);
            fa1 = *(const uint4*)(p.ah + offA1 + kb);
            fb0 = *(const uint4*)(p.al + offA0 + kb);
            fb1 = *(const uint4*)(p.al + offA1 + kb);
            fw0 = *(const uint4*)(p.wh + offW0 + kb);
            fw1 = *(const uint4*)(p.wh + offW1 + kb);
        }

        #pragma unroll
        for (int ks = 0; ks < 2; ks++) {
            uint32_t bh[4][2];
            #pragma unroll
            for (int j = 0; j < 2; j++) {
                const uint32_t uoff = (uint32_t)(((2*ks + b_usel) ^ bsw[j]) << 4) + brow[j];
                ldmx4(&bh[2*j][0], sWh + uoff);
            }
            #pragma unroll
            for (int mt = 0; mt < 4; mt++) {
                uint32_t ah[4], al[4];
                const uint32_t uoff = (uint32_t)(((2*ks + a_usel) ^ asw[mt]) << 4) + arow[mt];
                ldmx4(ah, sAh + uoff);
                ldmx4(al, sAl + uoff);
                #pragma unroll
                for (int nt = 0; nt < 4; nt++) {
                    mma_f16(acc[mt][nt], ah, bh[nt]);
                    mma_f16(acc[mt][nt], al, bh[nt]);
                }
            }
        }

        if (more) {
            *(uint4*)(nstage + 0*GT_BYTES + d0) = fa0;
            *(uint4*)(nstage + 0*GT_BYTES + d1) = fa1;
            *(uint4*)(nstage + 1*GT_BYTES + d0) = fb0;
            *(uint4*)(nstage + 1*GT_BYTES + d1) = fb1;
            *(uint4*)(nstage + 2*GT_BYTES + d0) = fw0;
            *(uint4*)(nstage + 2*GT_BYTES + d1) = fw1;
        }
        __syncthreads();
    }

    #pragma unroll
    for (int mt = 0; mt < 4; mt++) {
        const int row0 = bm + wm*64 + mt*16 + (lane >> 2);
        #pragma unroll
        for (int nt = 0; nt < 4; nt++) {
            const int col = bn + wn*32 + nt*8 + (lane & 3)*2;
            const float2 bv = *(const float2*)(p.bias + col);
            float x0 = acc[mt][nt][0] + bv.x, y0 = acc[mt][nt][1] + bv.y;
            float x1 = acc[mt][nt][2] + bv.x, y1 = acc[mt][nt][3] + bv.y;
            if (p.outf) {
                *(float2*)(p.outf + (size_t)row0*DM + col)     = make_float2(x0, y0);
                *(float2*)(p.outf + (size_t)(row0+8)*DM + col) = make_float2(x1, y1);
            } else {
                __half2 h0(__float2half_rn(x0), __float2half_rn(y0));
                __half2 h1(__float2half_rn(x1), __float2half_rn(y1));
                *(uint32_t*)(p.outh + (size_t)row0*DM + col)     = *reinterpret_cast<uint32_t*>(&h0);
                *(uint32_t*)(p.outh + (size_t)(row0+8)*DM + col) = *reinterpret_cast<uint32_t*>(&h1);
            }
        }
    }
}

// ---- flash attention: QK fp16; PV 2-term; K/V double-buffered ----------
// smem: Qh 16K | 2 x (Kh 8K | Vh 8K) = 48K; occ 2 -> 96K/SM
#define ATT_SMEM 49152

__global__ __launch_bounds__(256, 2) void flash_attn_mma(
    const __half* __restrict__ Qh,
    const __half* __restrict__ Kh, const __half* __restrict__ Vh,
    const int* __restrict__ mask,
    __half* __restrict__ Oh, __half* __restrict__ Ol)
{
    extern __shared__ char sm[];
    const uint32_t sb = smem_u32(sm);
    const uint32_t sQh = sb;

    const int tid = threadIdx.x, lane = tid & 31, wid = tid >> 5;
    const int qb = blockIdx.x, bh = blockIdx.y;
    const int b = bh >> 4, h = bh & 15;
    const int q0 = qb*128;
    const size_t rowbase = (size_t)b*S_LEN;
    const int hoff = h*DK;
    const int allones = g_mask_ones;

    // Q tile
    #pragma unroll
    for (int t = 0; t < 4; t++) {
        const int idx = tid + t*256;
        const int r = idx >> 3, uu = idx & 7;
        const size_t g = (rowbase + q0 + r)*DM + hoff + uu*8;
        const uint32_t d = (uint32_t)(r*128 + ((uu ^ (r & 7)) << 4));
        *(uint4*)(sm + d) = *(const uint4*)(Qh + g);
    }

    // KV staging geometry (per thread: 2 rows of K and V each)
    uint32_t kvd[2]; size_t kvg[2];
    #pragma unroll
    for (int t = 0; t < 2; t++) {
        const int idx = tid + t*256;
        const int r = idx >> 3, uu = idx & 7;
        kvd[t] = (uint32_t)(r*128 + ((uu ^ (r & 7)) << 4));
        kvg[t] = (size_t)r*DM + hoff + uu*8;
    }

    // prologue: KV block 0 -> stage 0
    #pragma unroll
    for (int t = 0; t < 2; t++) {
        *(uint4*)(sm + 16384 + kvd[t]) = *(const uint4*)(Kh + rowbase*DM + kvg[t]);
        *(uint4*)(sm + 24576 + kvd[t]) = *(const uint4*)(Vh + rowbase*DM + kvg[t]);
    }
    __syncthreads();

    const int sub = lane >> 3, l7 = lane & 7;
    const int a_r = ((sub & 1) << 3) + l7, a_us = sub >> 1;
    const int b_nt = sub >> 1, b_us = sub & 1;
    const int qrow = wid*16 + a_r;
    const int vro = ((sub & 1) << 3) + l7, vus = sub >> 1;

    float o[8][4];
    #pragma unroll
    for (int nt = 0; nt < 8; nt++)
        #pragma unroll
        for (int e = 0; e < 4; e++) o[nt][e] = 0.f;
    float m0 = -3.0e38f, m1 = -3.0e38f, l0 = 0.f, l1 = 0.f;

    for (int kb = 0; kb < S_LEN/64; kb++) {
        const int s = kb & 1;
        const uint32_t sKh = sb + 16384 + s*16384;
        const uint32_t sVh = sKh + 8192;
        const int k0g = kb*64;

        // prefetch next KV block into regs
        uint4 pk0, pk1, pv0, pv1;
        const bool more = (kb + 1 < S_LEN/64);
        if (more) {
            const size_t grow = (rowbase + (kb + 1)*64)*DM;
            pk0 = *(const uint4*)(Kh + grow + kvg[0]);
            pk1 = *(const uint4*)(Kh + grow + kvg[1]);
            pv0 = *(const uint4*)(Vh + grow + kvg[0]);
            pv1 = *(const uint4*)(Vh + grow + kvg[1]);
        }

        float c[8][4];
        #pragma unroll
        for (int j = 0; j < 8; j++)
            #pragma unroll
            for (int e = 0; e < 4; e++) c[j][e] = 0.f;

        #pragma unroll
        for (int ks = 0; ks < 4; ks++) {
            uint32_t ah[4];
            const uint32_t ua = (uint32_t)((((2*ks + a_us) ^ (qrow & 7)) << 4) + qrow*128);
            ldmx4(ah, sQh + ua);
            #pragma unroll
            for (int jp = 0; jp < 4; jp++) {
                uint32_t kh4[4];
                const int nr = jp*16 + b_nt*8 + l7;
                ldmx4(kh4, sKh + (uint32_t)((((2*ks + b_us) ^ (nr & 7)) << 4) + nr*128));
                mma_f16(c[2*jp],   ah, kh4);
                mma_f16(c[2*jp+1], ah, kh4 + 2);
            }
        }

        if (allones) {
            #pragma unroll
            for (int j = 0; j < 8; j++)
                #pragma unroll
                for (int e = 0; e < 4; e++) c[j][e] *= 0.125f;
        } else {
            const int qg0 = q0 + wid*16 + (lane >> 2);
            #pragma unroll
            for (int j = 0; j < 8; j++) {
                const int colb = k0g + j*8 + 2*(lane & 3);
                #pragma unroll
                for (int e = 0; e < 4; e++) {
                    const int qq = (e < 2) ? qg0 : qg0 + 8;
                    const int mv = mask[(size_t)qq*S_LEN + colb + (e & 1)];
                    c[j][e] = mv ? c[j][e]*0.125f : -1e9f;
                }
            }
        }

        float rm0 = -3.0e38f, rm1 = -3.0e38f;
        #pragma unroll
        for (int j = 0; j < 8; j++) {
            rm0 = fmaxf(rm0, fmaxf(c[j][0], c[j][1]));
            rm1 = fmaxf(rm1, fmaxf(c[j][2], c[j][3]));
        }
        rm0 = fmaxf(rm0, __shfl_xor_sync(0xffffffffu, rm0, 1));
        rm0 = fmaxf(rm0, __shfl_xor_sync(0xffffffffu, rm0, 2));
        rm1 = fmaxf(rm1, __shfl_xor_sync(0xffffffffu, rm1, 1));
        rm1 = fmaxf(rm1, __shfl_xor_sync(0xffffffffu, rm1, 2));
        const float mn0 = fmaxf(m0, rm0), mn1 = fmaxf(m1, rm1);
        const float al0 = __expf(m0 - mn0), al1 = __expf(m1 - mn1);
        float rs0 = 0.f, rs1 = 0.f;
        #pragma unroll
        for (int j = 0; j < 8; j++) {
            c[j][0] = __expf(c[j][0] - mn0);
            c[j][1] = __expf(c[j][1] - mn0);
            c[j][2] = __expf(c[j][2] - mn1);
            c[j][3] = __expf(c[j][3] - mn1);
            rs0 += c[j][0] + c[j][1];
            rs1 += c[j][2] + c[j][3];
        }
        rs0 += __shfl_xor_sync(0xffffffffu, rs0, 1);
        rs0 += __shfl_xor_sync(0xffffffffu, rs0, 2);
        rs1 += __shfl_xor_sync(0xffffffffu, rs1, 1);
        rs1 += __shfl_xor_sync(0xffffffffu, rs1, 2);
        l0 = l0*al0 + rs0;
        l1 = l1*al1 + rs1;
        m0 = mn0; m1 = mn1;
        #pragma unroll
        for (int nt = 0; nt < 8; nt++) {
            o[nt][0] *= al0; o[nt][1] *= al0;
            o[nt][2] *= al1; o[nt][3] *= al1;
        }

        #pragma unroll
        for (int kt = 0; kt < 4; kt++) {
            uint32_t ph[4], pl[4];
            ph[0] = split2h(c[2*kt][0],   c[2*kt][1],   pl[0]);
            ph[1] = split2h(c[2*kt][2],   c[2*kt][3],   pl[1]);
            ph[2] = split2h(c[2*kt+1][0], c[2*kt+1][1], pl[2]);
            ph[3] = split2h(c[2*kt+1][2], c[2*kt+1][3], pl[3]);
            const int tv = kt*16 + vro;
            #pragma unroll
            for (int dp = 0; dp < 4; dp++) {
                uint32_t vh4[4];
                ldmx4t(vh4, sVh + (uint32_t)((((2*dp + vus) ^ (tv & 7)) << 4) + tv*128));
                mma_f16(o[2*dp],   ph, vh4);
                mma_f16(o[2*dp],   pl, vh4);
                mma_f16(o[2*dp+1], ph, vh4 + 2);
                mma_f16(o[2*dp+1], pl, vh4 + 2);
            }
        }

        // land prefetched KV into next stage, then sync
        if (more) {
            char* nb = sm + 16384 + (s ^ 1)*16384;
            *(uint4*)(nb + kvd[0])        = pk0;
            *(uint4*)(nb + kvd[1])        = pk1;
            *(uint4*)(nb + 8192 + kvd[0]) = pv0;
            *(uint4*)(nb + 8192 + kvd[1]) = pv1;
        }
        __syncthreads();
    }

    const float inv0 = 1.f/l0, inv1 = 1.f/l1;
    const size_t gr0 = rowbase + q0 + wid*16 + (lane >> 2);
    #pragma unroll
    for (int nt = 0; nt < 8; nt++) {
        const int col = hoff + nt*8 + 2*(lane & 3);
        uint32_t lo0, lo1;
        const uint32_t h0 = split2h(o[nt][0]*inv0, o[nt][1]*inv0, lo0);
        const uint32_t h1 = split2h(o[nt][2]*inv1, o[nt][3]*inv1, lo1);
        *(uint32_t*)(Oh + gr0*DM + col)     = h0;
        *(uint32_t*)(Ol + gr0*DM + col)     = lo0;
        *(uint32_t*)(Oh + (gr0+8)*DM + col) = h1;
        *(uint32_t*)(Ol + (gr0+8)*DM + col) = lo1;
    }
}

// ---- host --------------------------------------------------------------
extern "C" void kernel_launch(void* const* d_in, const int* in_sizes, int n_in,
                              void* d_out, int out_size)
{
    const float* q    = (const float*)d_in[0];
    const float* k    = (const float*)d_in[1];
    const float* v    = (const float*)d_in[2];
    const int*   mask = (const int*)  d_in[3];
    const float* Wq   = (const float*)d_in[4];
    const float* bq   = (const float*)d_in[5];
    const float* Wk   = (const float*)d_in[6];
    const float* bk   = (const float*)d_in[7];
    const float* Wv   = (const float*)d_in[8];
    const float* bv   = (const float*)d_in[9];
    const float* Wo   = (const float*)d_in[10];
    const float* bo   = (const float*)d_in[11];
    float* out = (float*)d_out;

    __half *qh,*ql,*kh,*kl,*vh,*vl,*wqh,*wkh,*wvh,*woh;
    __half *Qh,*Kh,*Vh,*Ah,*Al;
    cudaGetSymbolAddress((void**)&qh, g_qh);   cudaGetSymbolAddress((void**)&ql, g_ql);
    cudaGetSymbolAddress((void**)&kh, g_kh);   cudaGetSymbolAddress((void**)&kl, g_kl);
    cudaGetSymbolAddress((void**)&vh, g_vh);   cudaGetSymbolAddress((void**)&vl, g_vl);
    cudaGetSymbolAddress((void**)&wqh, g_wqh); cudaGetSymbolAddress((void**)&wkh, g_wkh);
    cudaGetSymbolAddress((void**)&wvh, g_wvh); cudaGetSymbolAddress((void**)&woh, g_woh);
    cudaGetSymbolAddress((void**)&Qh, g_Qh);   cudaGetSymbolAddress((void**)&Kh, g_Kh);
    cudaGetSymbolAddress((void**)&Vh, g_Vh);
    cudaGetSymbolAddress((void**)&Ah, g_Ah);   cudaGetSymbolAddress((void**)&Al, g_Al);

    cudaFuncSetAttribute(flash_attn_mma, cudaFuncAttributeMaxDynamicSharedMemorySize, ATT_SMEM);

    const int n4_in = MROWS*DM/4, n4_w = DM*DM/4;

    reset_flag<<<1, 1>>>();
    check_mask<<<1024, 256>>>(mask, S_LEN*S_LEN);

    dim3 gs(n4_in/512, 3);
    split_h3<<<gs, 256>>>(q, qh, ql, k, kh, kl, v, vh, vl, n4_in);
    dim3 gc(n4_w/512, 4);
    conv_h4<<<gc, 256>>>(Wq, wqh, Wk, wkh, Wv, wvh, Wo, woh, n4_w);

    GemmP pq = { qh, ql, wqh, bq, nullptr, Qh };
    GemmP pk = { kh, kl, wkh, bk, nullptr, Kh };
    GemmP pv = { vh, vl, wvh, bv, nullptr, Vh };
    dim3 gg3(DM/128, MROWS/128, 3);
    gemm_hmma<<<gg3, 256>>>(pq, pk, pv);

    dim3 ga(S_LEN/128, B_SZ*NH);
    flash_attn_mma<<<ga, 256, ATT_SMEM>>>(Qh, Kh, Vh, mask, Ah, Al);

    GemmP po = { Ah, Al, woh, bo, out, nullptr };
    dim3 gg1(DM/128, MROWS/128, 1);
    gemm_hmma<<<gg1, 256>>>(po, po, po);
}

// round 13
// speedup vs baseline: 2.0756x; 1.2029x over previous
#include <cuda_runtime.h>
#include <cuda_fp16.h>
#include <cstdint>
#include <math.h>

#define S_LEN 2048
#define B_SZ  2
#define DM    1024
#define NH    16
#define DK    64
#define MROWS (B_SZ * S_LEN)

// ---- scratch -----------------------------------------------------------
__device__ __half g_qh[MROWS*DM], g_ql[MROWS*DM];
__device__ __half g_kh[MROWS*DM], g_kl[MROWS*DM];
__device__ __half g_vh[MROWS*DM], g_vl[MROWS*DM];
__device__ __half g_wqh[DM*DM], g_wkh[DM*DM], g_wvh[DM*DM], g_woh[DM*DM];
__device__ __half g_Qh[MROWS*DM], g_Kh[MROWS*DM], g_Vh[MROWS*DM];
__device__ __half g_Ah[MROWS*DM], g_Al[MROWS*DM];
__device__ int g_mask_ones;

// ---- helpers -----------------------------------------------------------
__device__ __forceinline__ uint32_t smem_u32(const void* p) {
    uint32_t a;
    asm("{ .reg .u64 t; cvta.to.shared.u64 t, %1; cvt.u32.u64 %0, t; }" : "=r"(a) : "l"(p));
    return a;
}
__device__ __forceinline__ void ldmx4(uint32_t* r, uint32_t addr) {
    asm volatile("ldmatrix.sync.aligned.m8n8.x4.shared.b16 {%0,%1,%2,%3}, [%4];"
                 : "=r"(r[0]), "=r"(r[1]), "=r"(r[2]), "=r"(r[3]) : "r"(addr));
}
__device__ __forceinline__ void ldmx4t(uint32_t* r, uint32_t addr) {
    asm volatile("ldmatrix.sync.aligned.m8n8.x4.trans.shared.b16 {%0,%1,%2,%3}, [%4];"
                 : "=r"(r[0]), "=r"(r[1]), "=r"(r[2]), "=r"(r[3]) : "r"(addr));
}
__device__ __forceinline__ void mma_f16(float* c, const uint32_t* a, const uint32_t* b) {
    asm volatile("mma.sync.aligned.m16n8k16.row.col.f32.f16.f16.f32 "
                 "{%0,%1,%2,%3}, {%4,%5,%6,%7}, {%8,%9}, {%0,%1,%2,%3};"
                 : "+f"(c[0]), "+f"(c[1]), "+f"(c[2]), "+f"(c[3])
                 : "r"(a[0]), "r"(a[1]), "r"(a[2]), "r"(a[3]), "r"(b[0]), "r"(b[1]));
}
__device__ __forceinline__ uint32_t split2h(float x, float y, uint32_t& lo) {
    __half hx = __float2half_rn(x), hy = __float2half_rn(y);
    __half2 h(hx, hy), l(__float2half_rn(x - __half2float(hx)),
                         __float2half_rn(y - __half2float(hy)));
    lo = *reinterpret_cast<uint32_t*>(&l);
    return *reinterpret_cast<uint32_t*>(&h);
}
__device__ __forceinline__ uint32_t pack2h(float x, float y) {
    __half2 h(__float2half_rn(x), __float2half_rn(y));
    return *reinterpret_cast<uint32_t*>(&h);
}

__global__ void reset_flag() { g_mask_ones = 1; }
__global__ __launch_bounds__(256) void check_mask(const int* __restrict__ m, int n) {
    int i = blockIdx.x * blockDim.x + threadIdx.x;
    int ok = 1;
    for (; i < n; i += gridDim.x * blockDim.x) ok &= (m[i] != 0);
    ok = __all_sync(0xffffffffu, ok);
    if ((threadIdx.x & 31) == 0 && !ok) atomicExch(&g_mask_ones, 0);
}

// ---- fused splits: 3 tensors, 2 float4 per thread ----------------------
__global__ __launch_bounds__(256) void split_h3(
    const float* __restrict__ x0, __half* __restrict__ h0, __half* __restrict__ l0,
    const float* __restrict__ x1, __half* __restrict__ h1, __half* __restrict__ l1,
    const float* __restrict__ x2, __half* __restrict__ h2, __half* __restrict__ l2,
    int n4)
{
    const float* x = (blockIdx.y == 0) ? x0 : (blockIdx.y == 1 ? x1 : x2);
    __half* hh = (blockIdx.y == 0) ? h0 : (blockIdx.y == 1 ? h1 : h2);
    __half* ll = (blockIdx.y == 0) ? l0 : (blockIdx.y == 1 ? l1 : l2);
    const int base = blockIdx.x * 512 + threadIdx.x;
    #pragma unroll
    for (int t = 0; t < 2; t++) {
        const int i = base + t * 256;
        if (i >= n4) return;
        float4 v = ((const float4*)x)[i];
        uint32_t lw0, lw1;
        uint32_t hw0 = split2h(v.x, v.y, lw0);
        uint32_t hw1 = split2h(v.z, v.w, lw1);
        ((uint32_t*)hh)[2*i] = hw0; ((uint32_t*)hh)[2*i+1] = hw1;
        ((uint32_t*)ll)[2*i] = lw0; ((uint32_t*)ll)[2*i+1] = lw1;
    }
}

// ---- fused weight converts: 4 tensors, 2 float4 per thread -------------
__global__ __launch_bounds__(256) void conv_h4(
    const float* __restrict__ x0, __half* __restrict__ h0,
    const float* __restrict__ x1, __half* __restrict__ h1,
    const float* __restrict__ x2, __half* __restrict__ h2,
    const float* __restrict__ x3, __half* __restrict__ h3,
    int n4)
{
    const float* x = (blockIdx.y < 2) ? (blockIdx.y == 0 ? x0 : x1)
                                      : (blockIdx.y == 2 ? x2 : x3);
    __half* hh = (blockIdx.y < 2) ? (blockIdx.y == 0 ? h0 : h1)
                                  : (blockIdx.y == 2 ? h2 : h3);
    const int base = blockIdx.x * 512 + threadIdx.x;
    #pragma unroll
    for (int t = 0; t < 2; t++) {
        const int i = base + t * 256;
        if (i >= n4) return;
        float4 v = ((const float4*)x)[i];
        ((uint32_t*)hh)[2*i]   = pack2h(v.x, v.y);
        ((uint32_t*)hh)[2*i+1] = pack2h(v.z, v.w);
    }
}

// ---- GEMM: C = (Ah+Al)@Wh^T + bias ; fp16 2-term, double-buffered ------
struct GemmP {
    const __half *ah, *al, *wh;
    const float* bias;
    float* outf;
    __half* outh;
};

#define GT_BYTES 8192           // 128 x 32 fp16
#define GSTAGE   (3 * GT_BYTES) // Ah | Al | Wh per stage

__global__ __launch_bounds__(256, 2) void gemm_hmma(GemmP p0, GemmP p1, GemmP p2)
{
    __shared__ char smem[2 * GSTAGE];   // 49152 B, 2 stages
    GemmP p = (blockIdx.z == 0) ? p0 : (blockIdx.z == 1 ? p1 : p2);

    const int tid = threadIdx.x, lane = tid & 31, wid = tid >> 5;
    const int wm = wid & 1, wn = wid >> 1;
    const int bm = blockIdx.y * 128, bn = blockIdx.x * 128;

    const uint32_t sb = smem_u32(smem);

    const int u = tid & 3, r0 = tid >> 2, r1 = r0 + 64;
    const uint32_t d0 = (uint32_t)(r0*64 + ((u ^ ((r0 >> 1) & 3)) << 4));
    const uint32_t d1 = (uint32_t)(r1*64 + ((u ^ ((r1 >> 1) & 3)) << 4));
    const size_t offA0 = (size_t)(bm + r0)*DM + u*8, offA1 = (size_t)(bm + r1)*DM + u*8;
    const size_t offW0 = (size_t)(bn + r0)*DM + u*8, offW1 = (size_t)(bn + r1)*DM + u*8;

    const int sub = lane >> 3;
    const int a_r16 = ((sub & 1) << 3) + (lane & 7), a_usel = sub >> 1;
    const int b_nt = sub >> 1, b_usel = sub & 1, b_r8 = lane & 7;

    int arow[4], asw[4];
    #pragma unroll
    for (int mt = 0; mt < 4; mt++) {
        const int gr = wm*64 + mt*16 + a_r16;
        arow[mt] = gr*64; asw[mt] = (gr >> 1) & 3;
    }
    int brow[2], bsw[2];
    #pragma unroll
    for (int j = 0; j < 2; j++) {
        const int nr = wn*32 + (2*j + b_nt)*8 + b_r8;
        brow[j] = nr*64; bsw[j] = (nr >> 1) & 3;
    }

    float acc[4][4][4];
    #pragma unroll
    for (int mt = 0; mt < 4; mt++)
        #pragma unroll
        for (int nt = 0; nt < 4; nt++)
            #pragma unroll
            for (int r = 0; r < 4; r++) acc[mt][nt][r] = 0.f;

    // prologue: chunk 0 -> stage 0
    {
        uint4 a0 = *(const uint4*)(p.ah + offA0), a1 = *(const uint4*)(p.ah + offA1);
        uint4 b0 = *(const uint4*)(p.al + offA0), b1 = *(const uint4*)(p.al + offA1);
        uint4 w0 = *(const uint4*)(p.wh + offW0), w1 = *(const uint4*)(p.wh + offW1);
        *(uint4*)(smem + 0*GT_BYTES + d0) = a0; *(uint4*)(smem + 0*GT_BYTES + d1) = a1;
        *(uint4*)(smem + 1*GT_BYTES + d0) = b0; *(uint4*)(smem + 1*GT_BYTES + d1) = b1;
        *(uint4*)(smem + 2*GT_BYTES + d0) = w0; *(uint4*)(smem + 2*GT_BYTES + d1) = w1;
    }
    __syncthreads();

    for (int ch = 0; ch < DM/32; ch++) {
        const int s = ch & 1;
        const uint32_t sAh = sb + s*GSTAGE, sAl = sAh + GT_BYTES, sWh = sAh + 2*GT_BYTES;
        char* nstage = smem + (s ^ 1)*GSTAGE;

        uint4 fa0, fa1, fb0, fb1, fw0, fw1;
        const bool more = (ch + 1 < DM/32);
        if (more) {
            const int kb = (ch + 1)*32;
            fa0 = *(const uint4*)(p.ah + offA0 + kb);
            fa1 = *(const uint4*)(p.ah + offA1 + kb);
            fb0 = *(const uint4*)(p.al + offA0 + kb);
            fb1 = *(const uint4*)(p.al + offA1 + kb);
            fw0 = *(const uint4*)(p.wh + offW0 + kb);
            fw1 = *(const uint4*)(p.wh + offW1 + kb);
        }

        #pragma unroll
        for (int ks = 0; ks < 2; ks++) {
            uint32_t bh[4][2];
            #pragma unroll
            for (int j = 0; j < 2; j++) {
                const uint32_t uoff = (uint32_t)(((2*ks + b_usel) ^ bsw[j]) << 4) + brow[j];
                ldmx4(&bh[2*j][0], sWh + uoff);
            }
            #pragma unroll
            for (int mt = 0; mt < 4; mt++) {
                uint32_t ah[4], al[4];
                const uint32_t uoff = (uint32_t)(((2*ks + a_usel) ^ asw[mt]) << 4) + arow[mt];
                ldmx4(ah, sAh + uoff);
                ldmx4(al, sAl + uoff);
                #pragma unroll
                for (int nt = 0; nt < 4; nt++) {
                    mma_f16(acc[mt][nt], ah, bh[nt]);
                    mma_f16(acc[mt][nt], al, bh[nt]);
                }
            }
        }

        if (more) {
            *(uint4*)(nstage + 0*GT_BYTES + d0) = fa0;
            *(uint4*)(nstage + 0*GT_BYTES + d1) = fa1;
            *(uint4*)(nstage + 1*GT_BYTES + d0) = fb0;
            *(uint4*)(nstage + 1*GT_BYTES + d1) = fb1;
            *(uint4*)(nstage + 2*GT_BYTES + d0) = fw0;
            *(uint4*)(nstage + 2*GT_BYTES + d1) = fw1;
        }
        __syncthreads();
    }

    #pragma unroll
    for (int mt = 0; mt < 4; mt++) {
        const int row0 = bm + wm*64 + mt*16 + (lane >> 2);
        #pragma unroll
        for (int nt = 0; nt < 4; nt++) {
            const int col = bn + wn*32 + nt*8 + (lane & 3)*2;
            const float2 bv = *(const float2*)(p.bias + col);
            float x0 = acc[mt][nt][0] + bv.x, y0 = acc[mt][nt][1] + bv.y;
            float x1 = acc[mt][nt][2] + bv.x, y1 = acc[mt][nt][3] + bv.y;
            if (p.outf) {
                *(float2*)(p.outf + (size_t)row0*DM + col)     = make_float2(x0, y0);
                *(float2*)(p.outf + (size_t)(row0+8)*DM + col) = make_float2(x1, y1);
            } else {
                *(uint32_t*)(p.outh + (size_t)row0*DM + col)     = pack2h(x0, y0);
                *(uint32_t*)(p.outh + (size_t)(row0+8)*DM + col) = pack2h(x1, y1);
            }
        }
    }
}

// ---- flash attention: QK fp16 1-term; PV fp16 1-term; KV dbuf ----------
// smem: Qh 16K | 2 x (Kh 8K | Vh 8K) = 48K; occ 2
#define ATT_SMEM 49152

__global__ __launch_bounds__(256, 2) void flash_attn_mma(
    const __half* __restrict__ Qh,
    const __half* __restrict__ Kh, const __half* __restrict__ Vh,
    const int* __restrict__ mask,
    __half* __restrict__ Oh, __half* __restrict__ Ol)
{
    extern __shared__ char sm[];
    const uint32_t sb = smem_u32(sm);
    const uint32_t sQh = sb;

    const int tid = threadIdx.x, lane = tid & 31, wid = tid >> 5;
    const int qb = blockIdx.x, bh = blockIdx.y;
    const int b = bh >> 4, h = bh & 15;
    const int q0 = qb*128;
    const size_t rowbase = (size_t)b*S_LEN;
    const int hoff = h*DK;
    const int allones = g_mask_ones;

    // Q tile
    #pragma unroll
    for (int t = 0; t < 4; t++) {
        const int idx = tid + t*256;
        const int r = idx >> 3, uu = idx & 7;
        const size_t g = (rowbase + q0 + r)*DM + hoff + uu*8;
        const uint32_t d = (uint32_t)(r*128 + ((uu ^ (r & 7)) << 4));
        *(uint4*)(sm + d) = *(const uint4*)(Qh + g);
    }

    // KV staging geometry
    uint32_t kvd[2]; size_t kvg[2];
    #pragma unroll
    for (int t = 0; t < 2; t++) {
        const int idx = tid + t*256;
        const int r = idx >> 3, uu = idx & 7;
        kvd[t] = (uint32_t)(r*128 + ((uu ^ (r & 7)) << 4));
        kvg[t] = (size_t)r*DM + hoff + uu*8;
    }

    // prologue: KV block 0 -> stage 0
    #pragma unroll
    for (int t = 0; t < 2; t++) {
        *(uint4*)(sm + 16384 + kvd[t]) = *(const uint4*)(Kh + rowbase*DM + kvg[t]);
        *(uint4*)(sm + 24576 + kvd[t]) = *(const uint4*)(Vh + rowbase*DM + kvg[t]);
    }
    __syncthreads();

    const int sub = lane >> 3, l7 = lane & 7;
    const int a_r = ((sub & 1) << 3) + l7, a_us = sub >> 1;
    const int b_nt = sub >> 1, b_us = sub & 1;
    const int qrow = wid*16 + a_r;
    const int vro = ((sub & 1) << 3) + l7, vus = sub >> 1;

    float o[8][4];
    #pragma unroll
    for (int nt = 0; nt < 8; nt++)
        #pragma unroll
        for (int e = 0; e < 4; e++) o[nt][e] = 0.f;
    float m0 = -3.0e38f, m1 = -3.0e38f, l0 = 0.f, l1 = 0.f;

    for (int kb = 0; kb < S_LEN/64; kb++) {
        const int s = kb & 1;
        const uint32_t sKh = sb + 16384 + s*16384;
        const uint32_t sVh = sKh + 8192;
        const int k0g = kb*64;

        uint4 pk0, pk1, pv0, pv1;
        const bool more = (kb + 1 < S_LEN/64);
        if (more) {
            const size_t grow = (rowbase + (kb + 1)*64)*DM;
            pk0 = *(const uint4*)(Kh + grow + kvg[0]);
            pk1 = *(const uint4*)(Kh + grow + kvg[1]);
            pv0 = *(const uint4*)(Vh + grow + kvg[0]);
            pv1 = *(const uint4*)(Vh + grow + kvg[1]);
        }

        float c[8][4];
        #pragma unroll
        for (int j = 0; j < 8; j++)
            #pragma unroll
            for (int e = 0; e < 4; e++) c[j][e] = 0.f;

        #pragma unroll
        for (int ks = 0; ks < 4; ks++) {
            uint32_t ah[4];
            const uint32_t ua = (uint32_t)((((2*ks + a_us) ^ (qrow & 7)) << 4) + qrow*128);
            ldmx4(ah, sQh + ua);
            #pragma unroll
            for (int jp = 0; jp < 4; jp++) {
                uint32_t kh4[4];
                const int nr = jp*16 + b_nt*8 + l7;
                ldmx4(kh4, sKh + (uint32_t)((((2*ks + b_us) ^ (nr & 7)) << 4) + nr*128));
                mma_f16(c[2*jp],   ah, kh4);
                mma_f16(c[2*jp+1], ah, kh4 + 2);
            }
        }

        if (allones) {
            #pragma unroll
            for (int j = 0; j < 8; j++)
                #pragma unroll
                for (int e = 0; e < 4; e++) c[j][e] *= 0.125f;
        } else {
            const int qg0 = q0 + wid*16 + (lane >> 2);
            #pragma unroll
            for (int j = 0; j < 8; j++) {
                const int colb = k0g + j*8 + 2*(lane & 3);
                #pragma unroll
                for (int e = 0; e < 4; e++) {
                    const int qq = (e < 2) ? qg0 : qg0 + 8;
                    const int mv = mask[(size_t)qq*S_LEN + colb + (e & 1)];
                    c[j][e] = mv ? c[j][e]*0.125f : -1e9f;
                }
            }
        }

        float rm0 = -3.0e38f, rm1 = -3.0e38f;
        #pragma unroll
        for (int j = 0; j < 8; j++) {
            rm0 = fmaxf(rm0, fmaxf(c[j][0], c[j][1]));
            rm1 = fmaxf(rm1, fmaxf(c[j][2], c[j][3]));
        }
        rm0 = fmaxf(rm0, __shfl_xor_sync(0xffffffffu, rm0, 1));
        rm0 = fmaxf(rm0, __shfl_xor_sync(0xffffffffu, rm0, 2));
        rm1 = fmaxf(rm1, __shfl_xor_sync(0xffffffffu, rm1, 1));
        rm1 = fmaxf(rm1, __shfl_xor_sync(0xffffffffu, rm1, 2));
        const float mn0 = fmaxf(m0, rm0), mn1 = fmaxf(m1, rm1);
        const float al0 = __expf(m0 - mn0), al1 = __expf(m1 - mn1);
        float rs0 = 0.f, rs1 = 0.f;
        #pragma unroll
        for (int j = 0; j < 8; j++) {
            c[j][0] = __expf(c[j][0] - mn0);
            c[j][1] = __expf(c[j][1] - mn0);
            c[j][2] = __expf(c[j][2] - mn1);
            c[j][3] = __expf(c[j][3] - mn1);
            rs0 += c[j][0] + c[j][1];
            rs1 += c[j][2] + c[j][3];
        }
        rs0 += __shfl_xor_sync(0xffffffffu, rs0, 1);
        rs0 += __shfl_xor_sync(0xffffffffu, rs0, 2);
        rs1 += __shfl_xor_sync(0xffffffffu, rs1, 1);
        rs1 += __shfl_xor_sync(0xffffffffu, rs1, 2);
        l0 = l0*al0 + rs0;
        l1 = l1*al1 + rs1;
        m0 = mn0; m1 = mn1;
        #pragma unroll
        for (int nt = 0; nt < 8; nt++) {
            o[nt][0] *= al0; o[nt][1] *= al0;
            o[nt][2] *= al1; o[nt][3] *= al1;
        }

        // O += P V : P straight fp16 (1-term)
        #pragma unroll
        for (int kt = 0; kt < 4; kt++) {
            uint32_t ph[4];
            ph[0] = pack2h(c[2*kt][0],   c[2*kt][1]);
            ph[1] = pack2h(c[2*kt][2],   c[2*kt][3]);
            ph[2] = pack2h(c[2*kt+1][0], c[2*kt+1][1]);
            ph[3] = pack2h(c[2*kt+1][2], c[2*kt+1][3]);
            const int tv = kt*16 + vro;
            #pragma unroll
            for (int dp = 0; dp < 4; dp++) {
                uint32_t vh4[4];
                ldmx4t(vh4, sVh + (uint32_t)((((2*dp + vus) ^ (tv & 7)) << 4) + tv*128));
                mma_f16(o[2*dp],   ph, vh4);
                mma_f16(o[2*dp+1], ph, vh4 + 2);
            }
        }

        if (more) {
            char* nb = sm + 16384 + (s ^ 1)*16384;
            *(uint4*)(nb + kvd[0])        = pk0;
            *(uint4*)(nb + kvd[1])        = pk1;
            *(uint4*)(nb + 8192 + kvd[0]) = pv0;
            *(uint4*)(nb + 8192 + kvd[1]) = pv1;
        }
        __syncthreads();
    }

    const float inv0 = 1.f/l0, inv1 = 1.f/l1;
    const size_t gr0 = rowbase + q0 + wid*16 + (lane >> 2);
    #pragma unroll
    for (int nt = 0; nt < 8; nt++) {
        const int col = hoff + nt*8 + 2*(lane & 3);
        uint32_t lo0, lo1;
        const uint32_t h0 = split2h(o[nt][0]*inv0, o[nt][1]*inv0, lo0);
        const uint32_t h1 = split2h(o[nt][2]*inv1, o[nt][3]*inv1, lo1);
        *(uint32_t*)(Oh + gr0*DM + col)     = h0;
        *(uint32_t*)(Ol + gr0*DM + col)     = lo0;
        *(uint32_t*)(Oh + (gr0+8)*DM + col) = h1;
        *(uint32_t*)(Ol + (gr0+8)*DM + col) = lo1;
    }
}

// ---- host --------------------------------------------------------------
extern "C" void kernel_launch(void* const* d_in, const int* in_sizes, int n_in,
                              void* d_out, int out_size)
{
    const float* q    = (const float*)d_in[0];
    const float* k    = (const float*)d_in[1];
    const float* v    = (const float*)d_in[2];
    const int*   mask = (const int*)  d_in[3];
    const float* Wq   = (const float*)d_in[4];
    const float* bq   = (const float*)d_in[5];
    const float* Wk   = (const float*)d_in[6];
    const float* bk   = (const float*)d_in[7];
    const float* Wv   = (const float*)d_in[8];
    const float* bv   = (const float*)d_in[9];
    const float* Wo   = (const float*)d_in[10];
    const float* bo   = (const float*)d_in[11];
    float* out = (float*)d_out;

    __half *qh,*ql,*kh,*kl,*vh,*vl,*wqh,*wkh,*wvh,*woh;
    __half *Qh,*Kh,*Vh,*Ah,*Al;
    cudaGetSymbolAddress((void**)&qh, g_qh);   cudaGetSymbolAddress((void**)&ql, g_ql);
    cudaGetSymbolAddress((void**)&kh, g_kh);   cudaGetSymbolAddress((void**)&kl, g_kl);
    cudaGetSymbolAddress((void**)&vh, g_vh);   cudaGetSymbolAddress((void**)&vl, g_vl);
    cudaGetSymbolAddress((void**)&wqh, g_wqh); cudaGetSymbolAddress((void**)&wkh, g_wkh);
    cudaGetSymbolAddress((void**)&wvh, g_wvh); cudaGetSymbolAddress((void**)&woh, g_woh);
    cudaGetSymbolAddress((void**)&Qh, g_Qh);   cudaGetSymbolAddress((void**)&Kh, g_Kh);
    cudaGetSymbolAddress((void**)&Vh, g_Vh);
    cudaGetSymbolAddress((void**)&Ah, g_Ah);   cudaGetSymbolAddress((void**)&Al, g_Al);

    cudaFuncSetAttribute(flash_attn_mma, cudaFuncAttributeMaxDynamicSharedMemorySize, ATT_SMEM);

    const int n4_in = MROWS*DM/4, n4_w = DM*DM/4;

    reset_flag<<<1, 1>>>();
    check_mask<<<1024, 256>>>(mask, S_LEN*S_LEN);

    dim3 gs(n4_in/512, 3);
    split_h3<<<gs, 256>>>(q, qh, ql, k, kh, kl, v, vh, vl, n4_in);
    dim3 gc(n4_w/512, 4);
    conv_h4<<<gc, 256>>>(Wq, wqh, Wk, wkh, Wv, wvh, Wo, woh, n4_w);

    GemmP pq = { qh, ql, wqh, bq, nullptr, Qh };
    GemmP pk = { kh, kl, wkh, bk, nullptr, Kh };
    GemmP pv = { vh, vl, wvh, bv, nullptr, Vh };
    dim3 gg3(DM/128, MROWS/128, 3);
    gemm_hmma<<<gg3, 256>>>(pq, pk, pv);

    dim3 ga(S_LEN/128, B_SZ*NH);
    flash_attn_mma<<<ga, 256, ATT_SMEM>>>(Qh, Kh, Vh, mask, Ah, Al);

    GemmP po = { Ah, Al, woh, bo, out, nullptr };
    dim3 gg1(DM/128, MROWS/128, 1);
    gemm_hmma<<<gg1, 256>>>(po, po, po);
}

// round 15
// speedup vs baseline: 2.4924x; 1.2008x over previous
#include <cuda_runtime.h>
#include <cuda_fp16.h>
#include <cstdint>
#include <math.h>

#define S_LEN 2048
#define B_SZ  2
#define DM    1024
#define NH    16
#define DK    64
#define MROWS (B_SZ * S_LEN)

// ---- scratch -----------------------------------------------------------
__device__ __half g_qh[MROWS*DM], g_kh[MROWS*DM], g_vh[MROWS*DM];
__device__ __half g_wqh[DM*DM], g_wkh[DM*DM], g_wvh[DM*DM], g_woh[DM*DM];
__device__ __half g_Qh[MROWS*DM], g_Kh[MROWS*DM], g_Vh[MROWS*DM];
__device__ __half g_Ah[MROWS*DM], g_Al[MROWS*DM];
__device__ int g_mask_ones;

// ---- helpers -----------------------------------------------------------
__device__ __forceinline__ uint32_t smem_u32(const void* p) {
    uint32_t a;
    asm("{ .reg .u64 t; cvta.to.shared.u64 t, %1; cvt.u32.u64 %0, t; }" : "=r"(a) : "l"(p));
    return a;
}
__device__ __forceinline__ void ldmx4(uint32_t* r, uint32_t addr) {
    asm volatile("ldmatrix.sync.aligned.m8n8.x4.shared.b16 {%0,%1,%2,%3}, [%4];"
                 : "=r"(r[0]), "=r"(r[1]), "=r"(r[2]), "=r"(r[3]) : "r"(addr));
}
__device__ __forceinline__ void ldmx4t(uint32_t* r, uint32_t addr) {
    asm volatile("ldmatrix.sync.aligned.m8n8.x4.trans.shared.b16 {%0,%1,%2,%3}, [%4];"
                 : "=r"(r[0]), "=r"(r[1]), "=r"(r[2]), "=r"(r[3]) : "r"(addr));
}
__device__ __forceinline__ void mma_f16(float* c, const uint32_t* a, const uint32_t* b) {
    asm volatile("mma.sync.aligned.m16n8k16.row.col.f32.f16.f16.f32 "
                 "{%0,%1,%2,%3}, {%4,%5,%6,%7}, {%8,%9}, {%0,%1,%2,%3};"
                 : "+f"(c[0]), "+f"(c[1]), "+f"(c[2]), "+f"(c[3])
                 : "r"(a[0]), "r"(a[1]), "r"(a[2]), "r"(a[3]), "r"(b[0]), "r"(b[1]));
}
__device__ __forceinline__ uint32_t split2h(float x, float y, uint32_t& lo) {
    __half hx = __float2half_rn(x), hy = __float2half_rn(y);
    __half2 h(hx, hy), l(__float2half_rn(x - __half2float(hx)),
                         __float2half_rn(y - __half2float(hy)));
    lo = *reinterpret_cast<uint32_t*>(&l);
    return *reinterpret_cast<uint32_t*>(&h);
}
__device__ __forceinline__ uint32_t pack2h(float x, float y) {
    __half2 h(__float2half_rn(x), __float2half_rn(y));
    return *reinterpret_cast<uint32_t*>(&h);
}

__global__ void reset_flag() { g_mask_ones = 1; }
__global__ __launch_bounds__(256) void check_mask(const int* __restrict__ m, int n) {
    int i = blockIdx.x * blockDim.x + threadIdx.x;
    int ok = 1;
    for (; i < n; i += gridDim.x * blockDim.x) ok &= (m[i] != 0);
    ok = __all_sync(0xffffffffu, ok);
    if ((threadIdx.x & 31) == 0 && !ok) atomicExch(&g_mask_ones, 0);
}

// ---- fused converts: 3 input tensors -----------------------------------
__global__ __launch_bounds__(256) void conv_h3(
    const float* __restrict__ x0, __half* __restrict__ h0,
    const float* __restrict__ x1, __half* __restrict__ h1,
    const float* __restrict__ x2, __half* __restrict__ h2,
    int n4)
{
    const float* x = (blockIdx.y == 0) ? x0 : (blockIdx.y == 1 ? x1 : x2);
    __half* hh = (blockIdx.y == 0) ? h0 : (blockIdx.y == 1 ? h1 : h2);
    const int base = blockIdx.x * 512 + threadIdx.x;
    #pragma unroll
    for (int t = 0; t < 2; t++) {
        const int i = base + t * 256;
        if (i >= n4) return;
        float4 v = ((const float4*)x)[i];
        ((uint32_t*)hh)[2*i]   = pack2h(v.x, v.y);
        ((uint32_t*)hh)[2*i+1] = pack2h(v.z, v.w);
    }
}

// ---- fused converts: 4 weight tensors ----------------------------------
__global__ __launch_bounds__(256) void conv_h4(
    const float* __restrict__ x0, __half* __restrict__ h0,
    const float* __restrict__ x1, __half* __restrict__ h1,
    const float* __restrict__ x2, __half* __restrict__ h2,
    const float* __restrict__ x3, __half* __restrict__ h3,
    int n4)
{
    const float* x = (blockIdx.y < 2) ? (blockIdx.y == 0 ? x0 : x1)
                                      : (blockIdx.y == 2 ? x2 : x3);
    __half* hh = (blockIdx.y < 2) ? (blockIdx.y == 0 ? h0 : h1)
                                  : (blockIdx.y == 2 ? h2 : h3);
    const int base = blockIdx.x * 512 + threadIdx.x;
    #pragma unroll
    for (int t = 0; t < 2; t++) {
        const int i = base + t * 256;
        if (i >= n4) return;
        float4 v = ((const float4*)x)[i];
        ((uint32_t*)hh)[2*i]   = pack2h(v.x, v.y);
        ((uint32_t*)hh)[2*i+1] = pack2h(v.z, v.w);
    }
}

// ---- GEMM: C = A@Wh^T + bias; CORR: A = Ah+Al (2-term), else pure fp16 -
struct GemmP {
    const __half *ah, *al, *wh;
    const float* bias;
    float* outf;
    __half* outh;
};

#define GT_BYTES 8192   // 128 x 32 fp16

template<bool CORR>
__global__ __launch_bounds__(256, 2) void gemm_hmma(GemmP p0, GemmP p1, GemmP p2)
{
    constexpr int STAGE = CORR ? 3 * GT_BYTES : 2 * GT_BYTES;  // Ah|Wh[|Al]
    __shared__ char smem[2 * STAGE];
    GemmP p = (blockIdx.z == 0) ? p0 : (blockIdx.z == 1 ? p1 : p2);

    const int tid = threadIdx.x, lane = tid & 31, wid = tid >> 5;
    const int wm = wid & 1, wn = wid >> 1;
    const int bm = blockIdx.y * 128, bn = blockIdx.x * 128;

    const uint32_t sb = smem_u32(smem);

    const int u = tid & 3, r0 = tid >> 2, r1 = r0 + 64;
    const uint32_t d0 = (uint32_t)(r0*64 + ((u ^ ((r0 >> 1) & 3)) << 4));
    const uint32_t d1 = (uint32_t)(r1*64 + ((u ^ ((r1 >> 1) & 3)) << 4));
    const size_t offA0 = (size_t)(bm + r0)*DM + u*8, offA1 = (size_t)(bm + r1)*DM + u*8;
    const size_t offW0 = (size_t)(bn + r0)*DM + u*8, offW1 = (size_t)(bn + r1)*DM + u*8;

    const int sub = lane >> 3;
    const int a_r16 = ((sub & 1) << 3) + (lane & 7), a_usel = sub >> 1;
    const int b_nt = sub >> 1, b_usel = sub & 1, b_r8 = lane & 7;

    int arow[4], asw[4];
    #pragma unroll
    for (int mt = 0; mt < 4; mt++) {
        const int gr = wm*64 + mt*16 + a_r16;
        arow[mt] = gr*64; asw[mt] = (gr >> 1) & 3;
    }
    int brow[2], bsw[2];
    #pragma unroll
    for (int j = 0; j < 2; j++) {
        const int nr = wn*32 + (2*j + b_nt)*8 + b_r8;
        brow[j] = nr*64; bsw[j] = (nr >> 1) & 3;
    }

    float acc[4][4][4];
    #pragma unroll
    for (int mt = 0; mt < 4; mt++)
        #pragma unroll
        for (int nt = 0; nt < 4; nt++)
            #pragma unroll
            for (int r = 0; r < 4; r++) acc[mt][nt][r] = 0.f;

    // prologue: chunk 0 -> stage 0
    {
        uint4 a0 = *(const uint4*)(p.ah + offA0), a1 = *(const uint4*)(p.ah + offA1);
        uint4 w0 = *(const uint4*)(p.wh + offW0), w1 = *(const uint4*)(p.wh + offW1);
        *(uint4*)(smem + 0*GT_BYTES + d0) = a0; *(uint4*)(smem + 0*GT_BYTES + d1) = a1;
        *(uint4*)(smem + 1*GT_BYTES + d0) = w0; *(uint4*)(smem + 1*GT_BYTES + d1) = w1;
        if (CORR) {
            uint4 b0 = *(const uint4*)(p.al + offA0), b1 = *(const uint4*)(p.al + offA1);
            *(uint4*)(smem + 2*GT_BYTES + d0) = b0; *(uint4*)(smem + 2*GT_BYTES + d1) = b1;
        }
    }
    __syncthreads();

    for (int ch = 0; ch < DM/32; ch++) {
        const int s = ch & 1;
        const uint32_t sAh = sb + s*STAGE, sWh = sAh + GT_BYTES, sAl = sAh + 2*GT_BYTES;
        char* nstage = smem + (s ^ 1)*STAGE;

        uint4 fa0, fa1, fb0, fb1, fw0, fw1;
        const bool more = (ch + 1 < DM/32);
        if (more) {
            const int kb = (ch + 1)*32;
            fa0 = *(const uint4*)(p.ah + offA0 + kb);
            fa1 = *(const uint4*)(p.ah + offA1 + kb);
            fw0 = *(const uint4*)(p.wh + offW0 + kb);
            fw1 = *(const uint4*)(p.wh + offW1 + kb);
            if (CORR) {
                fb0 = *(const uint4*)(p.al + offA0 + kb);
                fb1 = *(const uint4*)(p.al + offA1 + kb);
            }
        }

        #pragma unroll
        for (int ks = 0; ks < 2; ks++) {
            uint32_t bh[4][2];
            #pragma unroll
            for (int j = 0; j < 2; j++) {
                const uint32_t uoff = (uint32_t)(((2*ks + b_usel) ^ bsw[j]) << 4) + brow[j];
                ldmx4(&bh[2*j][0], sWh + uoff);
            }
            #pragma unroll
            for (int mt = 0; mt < 4; mt++) {
                uint32_t ah[4], al[4];
                const uint32_t uoff = (uint32_t)(((2*ks + a_usel) ^ asw[mt]) << 4) + arow[mt];
                ldmx4(ah, sAh + uoff);
                if (CORR) ldmx4(al, sAl + uoff);
                #pragma unroll
                for (int nt = 0; nt < 4; nt++) {
                    mma_f16(acc[mt][nt], ah, bh[nt]);
                    if (CORR) mma_f16(acc[mt][nt], al, bh[nt]);
                }
            }
        }

        if (more) {
            *(uint4*)(nstage + 0*GT_BYTES + d0) = fa0;
            *(uint4*)(nstage + 0*GT_BYTES + d1) = fa1;
            *(uint4*)(nstage + 1*GT_BYTES + d0) = fw0;
            *(uint4*)(nstage + 1*GT_BYTES + d1) = fw1;
            if (CORR) {
                *(uint4*)(nstage + 2*GT_BYTES + d0) = fb0;
                *(uint4*)(nstage + 2*GT_BYTES + d1) = fb1;
            }
        }
        __syncthreads();
    }

    #pragma unroll
    for (int mt = 0; mt < 4; mt++) {
        const int row0 = bm + wm*64 + mt*16 + (lane >> 2);
        #pragma unroll
        for (int nt = 0; nt < 4; nt++) {
            const int col = bn + wn*32 + nt*8 + (lane & 3)*2;
            const float2 bv = *(const float2*)(p.bias + col);
            float x0 = acc[mt][nt][0] + bv.x, y0 = acc[mt][nt][1] + bv.y;
            float x1 = acc[mt][nt][2] + bv.x, y1 = acc[mt][nt][3] + bv.y;
            if (p.outf) {
                *(float2*)(p.outf + (size_t)row0*DM + col)     = make_float2(x0, y0);
                *(float2*)(p.outf + (size_t)(row0+8)*DM + col) = make_float2(x1, y1);
            } else {
                *(uint32_t*)(p.outh + (size_t)row0*DM + col)     = pack2h(x0, y0);
                *(uint32_t*)(p.outh + (size_t)(row0+8)*DM + col) = pack2h(x1, y1);
            }
        }
    }
}

// ---- flash attention: QK fp16 1-term; PV fp16 1-term; KV dbuf ----------
// smem: Qh 16K | 2 x (Kh 8K | Vh 8K) = 48K; occ 2
#define ATT_SMEM 49152

__global__ __launch_bounds__(256, 2) void flash_attn_mma(
    const __half* __restrict__ Qh,
    const __half* __restrict__ Kh, const __half* __restrict__ Vh,
    const int* __restrict__ mask,
    __half* __restrict__ Oh, __half* __restrict__ Ol)
{
    extern __shared__ char sm[];
    const uint32_t sb = smem_u32(sm);
    const uint32_t sQh = sb;

    const int tid = threadIdx.x, lane = tid & 31, wid = tid >> 5;
    const int qb = blockIdx.x, bh = blockIdx.y;
    const int b = bh >> 4, h = bh & 15;
    const int q0 = qb*128;
    const size_t rowbase = (size_t)b*S_LEN;
    const int hoff = h*DK;
    const int allones = g_mask_ones;

    // Q tile
    #pragma unroll
    for (int t = 0; t < 4; t++) {
        const int idx = tid + t*256;
        const int r = idx >> 3, uu = idx & 7;
        const size_t g = (rowbase + q0 + r)*DM + hoff + uu*8;
        const uint32_t d = (uint32_t)(r*128 + ((uu ^ (r & 7)) << 4));
        *(uint4*)(sm + d) = *(const uint4*)(Qh + g);
    }

    // KV staging geometry
    uint32_t kvd[2]; size_t kvg[2];
    #pragma unroll
    for (int t = 0; t < 2; t++) {
        const int idx = tid + t*256;
        const int r = idx >> 3, uu = idx & 7;
        kvd[t] = (uint32_t)(r*128 + ((uu ^ (r & 7)) << 4));
        kvg[t] = (size_t)r*DM + hoff + uu*8;
    }

    // prologue: KV block 0 -> stage 0
    #pragma unroll
    for (int t = 0; t < 2; t++) {
        *(uint4*)(sm + 16384 + kvd[t]) = *(const uint4*)(Kh + rowbase*DM + kvg[t]);
        *(uint4*)(sm + 24576 + kvd[t]) = *(const uint4*)(Vh + rowbase*DM + kvg[t]);
    }
    __syncthreads();

    const int sub = lane >> 3, l7 = lane & 7;
    const int a_r = ((sub & 1) << 3) + l7, a_us = sub >> 1;
    const int b_nt = sub >> 1, b_us = sub & 1;
    const int qrow = wid*16 + a_r;
    const int vro = ((sub & 1) << 3) + l7, vus = sub >> 1;

    float o[8][4];
    #pragma unroll
    for (int nt = 0; nt < 8; nt++)
        #pragma unroll
        for (int e = 0; e < 4; e++) o[nt][e] = 0.f;
    float m0 = -3.0e38f, m1 = -3.0e38f, l0 = 0.f, l1 = 0.f;

    for (int kb = 0; kb < S_LEN/64; kb++) {
        const int s = kb & 1;
        const uint32_t sKh = sb + 16384 + s*16384;
        const uint32_t sVh = sKh + 8192;
        const int k0g = kb*64;

        uint4 pk0, pk1, pv0, pv1;
        const bool more = (kb + 1 < S_LEN/64);
        if (more) {
            const size_t grow = (rowbase + (kb + 1)*64)*DM;
            pk0 = *(const uint4*)(Kh + grow + kvg[0]);
            pk1 = *(const uint4*)(Kh + grow + kvg[1]);
            pv0 = *(const uint4*)(Vh + grow + kvg[0]);
            pv1 = *(const uint4*)(Vh + grow + kvg[1]);
        }

        float c[8][4];
        #pragma unroll
        for (int j = 0; j < 8; j++)
            #pragma unroll
            for (int e = 0; e < 4; e++) c[j][e] = 0.f;

        #pragma unroll
        for (int ks = 0; ks < 4; ks++) {
            uint32_t ah[4];
            const uint32_t ua = (uint32_t)((((2*ks + a_us) ^ (qrow & 7)) << 4) + qrow*128);
            ldmx4(ah, sQh + ua);
            #pragma unroll
            for (int jp = 0; jp < 4; jp++) {
                uint32_t kh4[4];
                const int nr = jp*16 + b_nt*8 + l7;
                ldmx4(kh4, sKh + (uint32_t)((((2*ks + b_us) ^ (nr & 7)) << 4) + nr*128));
                mma_f16(c[2*jp],   ah, kh4);
                mma_f16(c[2*jp+1], ah, kh4 + 2);
            }
        }

        if (allones) {
            #pragma unroll
            for (int j = 0; j < 8; j++)
                #pragma unroll
                for (int e = 0; e < 4; e++) c[j][e] *= 0.125f;
        } else {
            const int qg0 = q0 + wid*16 + (lane >> 2);
            #pragma unroll
            for (int j = 0; j < 8; j++) {
                const int colb = k0g + j*8 + 2*(lane & 3);
                #pragma unroll
                for (int e = 0; e < 4; e++) {
                    const int qq = (e < 2) ? qg0 : qg0 + 8;
                    const int mv = mask[(size_t)qq*S_LEN + colb + (e & 1)];
                    c[j][e] = mv ? c[j][e]*0.125f : -1e9f;
                }
            }
        }

        float rm0 = -3.0e38f, rm1 = -3.0e38f;
        #pragma unroll
        for (int j = 0; j < 8; j++) {
            rm0 = fmaxf(rm0, fmaxf(c[j][0], c[j][1]));
            rm1 = fmaxf(rm1, fmaxf(c[j][2], c[j][3]));
        }
        rm0 = fmaxf(rm0, __shfl_xor_sync(0xffffffffu, rm0, 1));
        rm0 = fmaxf(rm0, __shfl_xor_sync(0xffffffffu, rm0, 2));
        rm1 = fmaxf(rm1, __shfl_xor_sync(0xffffffffu, rm1, 1));
        rm1 = fmaxf(rm1, __shfl_xor_sync(0xffffffffu, rm1, 2));
        const float mn0 = fmaxf(m0, rm0), mn1 = fmaxf(m1, rm1);
        const float al0 = __expf(m0 - mn0), al1 = __expf(m1 - mn1);
        float rs0 = 0.f, rs1 = 0.f;
        #pragma unroll
        for (int j = 0; j < 8; j++) {
            c[j][0] = __expf(c[j][0] - mn0);
            c[j][1] = __expf(c[j][1] - mn0);
            c[j][2] = __expf(c[j][2] - mn1);
            c[j][3] = __expf(c[j][3] - mn1);
            rs0 += c[j][0] + c[j][1];
            rs1 += c[j][2] + c[j][3];
        }
        rs0 += __shfl_xor_sync(0xffffffffu, rs0, 1);
        rs0 += __shfl_xor_sync(0xffffffffu, rs0, 2);
        rs1 += __shfl_xor_sync(0xffffffffu, rs1, 1);
        rs1 += __shfl_xor_sync(0xffffffffu, rs1, 2);
        l0 = l0*al0 + rs0;
        l1 = l1*al1 + rs1;
        m0 = mn0; m1 = mn1;
        #pragma unroll
        for (int nt = 0; nt < 8; nt++) {
            o[nt][0] *= al0; o[nt][1] *= al0;
            o[nt][2] *= al1; o[nt][3] *= al1;
        }

        // O += P V : P straight fp16
        #pragma unroll
        for (int kt = 0; kt < 4; kt++) {
            uint32_t ph[4];
            ph[0] = pack2h(c[2*kt][0],   c[2*kt][1]);
            ph[1] = pack2h(c[2*kt][2],   c[2*kt][3]);
            ph[2] = pack2h(c[2*kt+1][0], c[2*kt+1][1]);
            ph[3] = pack2h(c[2*kt+1][2], c[2*kt+1][3]);
            const int tv = kt*16 + vro;
            #pragma unroll
            for (int dp = 0; dp < 4; dp++) {
                uint32_t vh4[4];
                ldmx4t(vh4, sVh + (uint32_t)((((2*dp + vus) ^ (tv & 7)) << 4) + tv*128));
                mma_f16(o[2*dp],   ph, vh4);
                mma_f16(o[2*dp+1], ph, vh4 + 2);
            }
        }

        if (more) {
            char* nb = sm + 16384 + (s ^ 1)*16384;
            *(uint4*)(nb + kvd[0])        = pk0;
            *(uint4*)(nb + kvd[1])        = pk1;
            *(uint4*)(nb + 8192 + kvd[0]) = pv0;
            *(uint4*)(nb + 8192 + kvd[1]) = pv1;
        }
        __syncthreads();
    }

    const float inv0 = 1.f/l0, inv1 = 1.f/l1;
    const size_t gr0 = rowbase + q0 + wid*16 + (lane >> 2);
    #pragma unroll
    for (int nt = 0; nt < 8; nt++) {
        const int col = hoff + nt*8 + 2*(lane & 3);
        uint32_t lo0, lo1;
        const uint32_t h0 = split2h(o[nt][0]*inv0, o[nt][1]*inv0, lo0);
        const uint32_t h1 = split2h(o[nt][2]*inv1, o[nt][3]*inv1, lo1);
        *(uint32_t*)(Oh + gr0*DM + col)     = h0;
        *(uint32_t*)(Ol + gr0*DM + col)     = lo0;
        *(uint32_t*)(Oh + (gr0+8)*DM + col) = h1;
        *(uint32_t*)(Ol + (gr0+8)*DM + col) = lo1;
    }
}

// ---- host --------------------------------------------------------------
extern "C" void kernel_launch(void* const* d_in, const int* in_sizes, int n_in,
                              void* d_out, int out_size)
{
    const float* q    = (const float*)d_in[0];
    const float* k    = (const float*)d_in[1];
    const float* v    = (const float*)d_in[2];
    const int*   mask = (const int*)  d_in[3];
    const float* Wq   = (const float*)d_in[4];
    const float* bq   = (const float*)d_in[5];
    const float* Wk   = (const float*)d_in[6];
    const float* bk   = (const float*)d_in[7];
    const float* Wv   = (const float*)d_in[8];
    const float* bv   = (const float*)d_in[9];
    const float* Wo   = (const float*)d_in[10];
    const float* bo   = (const float*)d_in[11];
    float* out = (float*)d_out;

    __half *qh,*kh,*vh,*wqh,*wkh,*wvh,*woh;
    __half *Qh,*Kh,*Vh,*Ah,*Al;
    cudaGetSymbolAddress((void**)&qh, g_qh);
    cudaGetSymbolAddress((void**)&kh, g_kh);
    cudaGetSymbolAddress((void**)&vh, g_vh);
    cudaGetSymbolAddress((void**)&wqh, g_wqh); cudaGetSymbolAddress((void**)&wkh, g_wkh);
    cudaGetSymbolAddress((void**)&wvh, g_wvh); cudaGetSymbolAddress((void**)&woh, g_woh);
    cudaGetSymbolAddress((void**)&Qh, g_Qh);   cudaGetSymbolAddress((void**)&Kh, g_Kh);
    cudaGetSymbolAddress((void**)&Vh, g_Vh);
    cudaGetSymbolAddress((void**)&Ah, g_Ah);   cudaGetSymbolAddress((void**)&Al, g_Al);

    cudaFuncSetAttribute(flash_attn_mma, cudaFuncAttributeMaxDynamicSharedMemorySize, ATT_SMEM);

    const int n4_in = MROWS*DM/4, n4_w = DM*DM/4;

    reset_flag<<<1, 1>>>();
    check_mask<<<1024, 256>>>(mask, S_LEN*S_LEN);

    dim3 gs(n4_in/512, 3);
    conv_h3<<<gs, 256>>>(q, qh, k, kh, v, vh, n4_in);
    dim3 gc(n4_w/512, 4);
    conv_h4<<<gc, 256>>>(Wq, wqh, Wk, wkh, Wv, wvh, Wo, woh, n4_w);

    // QKV projections: pure fp16 (1-term)
    GemmP pq = { qh, nullptr, wqh, bq, nullptr, Qh };
    GemmP pk = { kh, nullptr, wkh, bk, nullptr, Kh };
    GemmP pv = { vh, nullptr, wvh, bv, nullptr, Vh };
    dim3 gg3(DM/128, MROWS/128, 3);
    gemm_hmma<false><<<gg3, 256>>>(pq, pk, pv);

    dim3 ga(S_LEN/128, B_SZ*NH);
    flash_attn_mma<<<ga, 256, ATT_SMEM>>>(Qh, Kh, Vh, mask, Ah, Al);

    // final projection: 2-term (A corrected)
    GemmP po = { Ah, Al, woh, bo, out, nullptr };
    dim3 gg1(DM/128, MROWS/128, 1);
    gemm_hmma<true><<<gg1, 256>>>(po, po, po);
}

// round 16
// speedup vs baseline: 2.6995x; 1.0831x over previous
#include <cuda_runtime.h>
#include <cuda_fp16.h>
#include <cstdint>
#include <math.h>

#define S_LEN 2048
#define B_SZ  2
#define DM    1024
#define NH    16
#define DK    64
#define MROWS (B_SZ * S_LEN)

// ---- scratch -----------------------------------------------------------
__device__ __half g_qh[MROWS*DM], g_kh[MROWS*DM], g_vh[MROWS*DM];
__device__ __half g_wqh[DM*DM], g_wkh[DM*DM], g_wvh[DM*DM], g_woh[DM*DM];
__device__ __half g_Qh[MROWS*DM], g_Kh[MROWS*DM], g_Vh[MROWS*DM];
__device__ __half g_Ah[MROWS*DM];
__device__ int g_mask_ones;

// ---- helpers -----------------------------------------------------------
__device__ __forceinline__ uint32_t smem_u32(const void* p) {
    uint32_t a;
    asm("{ .reg .u64 t; cvta.to.shared.u64 t, %1; cvt.u32.u64 %0, t; }" : "=r"(a) : "l"(p));
    return a;
}
__device__ __forceinline__ void ldmx4(uint32_t* r, uint32_t addr) {
    asm volatile("ldmatrix.sync.aligned.m8n8.x4.shared.b16 {%0,%1,%2,%3}, [%4];"
                 : "=r"(r[0]), "=r"(r[1]), "=r"(r[2]), "=r"(r[3]) : "r"(addr));
}
__device__ __forceinline__ void ldmx4t(uint32_t* r, uint32_t addr) {
    asm volatile("ldmatrix.sync.aligned.m8n8.x4.trans.shared.b16 {%0,%1,%2,%3}, [%4];"
                 : "=r"(r[0]), "=r"(r[1]), "=r"(r[2]), "=r"(r[3]) : "r"(addr));
}
__device__ __forceinline__ void mma_f16(float* c, const uint32_t* a, const uint32_t* b) {
    asm volatile("mma.sync.aligned.m16n8k16.row.col.f32.f16.f16.f32 "
                 "{%0,%1,%2,%3}, {%4,%5,%6,%7}, {%8,%9}, {%0,%1,%2,%3};"
                 : "+f"(c[0]), "+f"(c[1]), "+f"(c[2]), "+f"(c[3])
                 : "r"(a[0]), "r"(a[1]), "r"(a[2]), "r"(a[3]), "r"(b[0]), "r"(b[1]));
}
__device__ __forceinline__ uint32_t pack2h(float x, float y) {
    __half2 h(__float2half_rn(x), __float2half_rn(y));
    return *reinterpret_cast<uint32_t*>(&h);
}

__global__ void reset_flag() { g_mask_ones = 1; }
__global__ __launch_bounds__(256) void check_mask(const int* __restrict__ m, int n) {
    int i = blockIdx.x * blockDim.x + threadIdx.x;
    int ok = 1;
    for (; i < n; i += gridDim.x * blockDim.x) ok &= (m[i] != 0);
    ok = __all_sync(0xffffffffu, ok);
    if ((threadIdx.x & 31) == 0 && !ok) atomicExch(&g_mask_ones, 0);
}

// ---- fused converts: 3 input tensors -----------------------------------
__global__ __launch_bounds__(256) void conv_h3(
    const float* __restrict__ x0, __half* __restrict__ h0,
    const float* __restrict__ x1, __half* __restrict__ h1,
    const float* __restrict__ x2, __half* __restrict__ h2,
    int n4)
{
    const float* x = (blockIdx.y == 0) ? x0 : (blockIdx.y == 1 ? x1 : x2);
    __half* hh = (blockIdx.y == 0) ? h0 : (blockIdx.y == 1 ? h1 : h2);
    const int base = blockIdx.x * 512 + threadIdx.x;
    #pragma unroll
    for (int t = 0; t < 2; t++) {
        const int i = base + t * 256;
        if (i >= n4) return;
        float4 v = ((const float4*)x)[i];
        ((uint32_t*)hh)[2*i]   = pack2h(v.x, v.y);
        ((uint32_t*)hh)[2*i+1] = pack2h(v.z, v.w);
    }
}

// ---- fused converts: 4 weight tensors ----------------------------------
__global__ __launch_bounds__(256) void conv_h4(
    const float* __restrict__ x0, __half* __restrict__ h0,
    const float* __restrict__ x1, __half* __restrict__ h1,
    const float* __restrict__ x2, __half* __restrict__ h2,
    const float* __restrict__ x3, __half* __restrict__ h3,
    int n4)
{
    const float* x = (blockIdx.y < 2) ? (blockIdx.y == 0 ? x0 : x1)
                                      : (blockIdx.y == 2 ? x2 : x3);
    __half* hh = (blockIdx.y < 2) ? (blockIdx.y == 0 ? h0 : h1)
                                  : (blockIdx.y == 2 ? h2 : h3);
    const int base = blockIdx.x * 512 + threadIdx.x;
    #pragma unroll
    for (int t = 0; t < 2; t++) {
        const int i = base + t * 256;
        if (i >= n4) return;
        float4 v = ((const float4*)x)[i];
        ((uint32_t*)hh)[2*i]   = pack2h(v.x, v.y);
        ((uint32_t*)hh)[2*i+1] = pack2h(v.z, v.w);
    }
}

// ---- GEMM: C = A@Wh^T + bias; pure fp16, double-buffered ---------------
struct GemmP {
    const __half *ah, *wh;
    const float* bias;
    float* outf;
    __half* outh;
};

#define GT_BYTES 8192           // 128 x 32 fp16
#define GSTAGE   (2 * GT_BYTES) // Ah | Wh per stage

__global__ __launch_bounds__(256, 2) void gemm_hmma(GemmP p0, GemmP p1, GemmP p2)
{
    __shared__ char smem[2 * GSTAGE];
    GemmP p = (blockIdx.z == 0) ? p0 : (blockIdx.z == 1 ? p1 : p2);

    const int tid = threadIdx.x, lane = tid & 31, wid = tid >> 5;
    const int wm = wid & 1, wn = wid >> 1;
    const int bm = blockIdx.y * 128, bn = blockIdx.x * 128;

    const uint32_t sb = smem_u32(smem);

    const int u = tid & 3, r0 = tid >> 2, r1 = r0 + 64;
    const uint32_t d0 = (uint32_t)(r0*64 + ((u ^ ((r0 >> 1) & 3)) << 4));
    const uint32_t d1 = (uint32_t)(r1*64 + ((u ^ ((r1 >> 1) & 3)) << 4));
    const size_t offA0 = (size_t)(bm + r0)*DM + u*8, offA1 = (size_t)(bm + r1)*DM + u*8;
    const size_t offW0 = (size_t)(bn + r0)*DM + u*8, offW1 = (size_t)(bn + r1)*DM + u*8;

    const int sub = lane >> 3;
    const int a_r16 = ((sub & 1) << 3) + (lane & 7), a_usel = sub >> 1;
    const int b_nt = sub >> 1, b_usel = sub & 1, b_r8 = lane & 7;

    int arow[4], asw[4];
    #pragma unroll
    for (int mt = 0; mt < 4; mt++) {
        const int gr = wm*64 + mt*16 + a_r16;
        arow[mt] = gr*64; asw[mt] = (gr >> 1) & 3;
    }
    int brow[2], bsw[2];
    #pragma unroll
    for (int j = 0; j < 2; j++) {
        const int nr = wn*32 + (2*j + b_nt)*8 + b_r8;
        brow[j] = nr*64; bsw[j] = (nr >> 1) & 3;
    }

    float acc[4][4][4];
    #pragma unroll
    for (int mt = 0; mt < 4; mt++)
        #pragma unroll
        for (int nt = 0; nt < 4; nt++)
            #pragma unroll
            for (int r = 0; r < 4; r++) acc[mt][nt][r] = 0.f;

    // prologue: chunk 0 -> stage 0
    {
        uint4 a0 = *(const uint4*)(p.ah + offA0), a1 = *(const uint4*)(p.ah + offA1);
        uint4 w0 = *(const uint4*)(p.wh + offW0), w1 = *(const uint4*)(p.wh + offW1);
        *(uint4*)(smem + 0*GT_BYTES + d0) = a0; *(uint4*)(smem + 0*GT_BYTES + d1) = a1;
        *(uint4*)(smem + 1*GT_BYTES + d0) = w0; *(uint4*)(smem + 1*GT_BYTES + d1) = w1;
    }
    __syncthreads();

    for (int ch = 0; ch < DM/32; ch++) {
        const int s = ch & 1;
        const uint32_t sAh = sb + s*GSTAGE, sWh = sAh + GT_BYTES;
        char* nstage = smem + (s ^ 1)*GSTAGE;

        uint4 fa0, fa1, fw0, fw1;
        const bool more = (ch + 1 < DM/32);
        if (more) {
            const int kb = (ch + 1)*32;
            fa0 = *(const uint4*)(p.ah + offA0 + kb);
            fa1 = *(const uint4*)(p.ah + offA1 + kb);
            fw0 = *(const uint4*)(p.wh + offW0 + kb);
            fw1 = *(const uint4*)(p.wh + offW1 + kb);
        }

        #pragma unroll
        for (int ks = 0; ks < 2; ks++) {
            uint32_t bh[4][2];
            #pragma unroll
            for (int j = 0; j < 2; j++) {
                const uint32_t uoff = (uint32_t)(((2*ks + b_usel) ^ bsw[j]) << 4) + brow[j];
                ldmx4(&bh[2*j][0], sWh + uoff);
            }
            #pragma unroll
            for (int mt = 0; mt < 4; mt++) {
                uint32_t ah[4];
                const uint32_t uoff = (uint32_t)(((2*ks + a_usel) ^ asw[mt]) << 4) + arow[mt];
                ldmx4(ah, sAh + uoff);
                #pragma unroll
                for (int nt = 0; nt < 4; nt++)
                    mma_f16(acc[mt][nt], ah, bh[nt]);
            }
        }

        if (more) {
            *(uint4*)(nstage + 0*GT_BYTES + d0) = fa0;
            *(uint4*)(nstage + 0*GT_BYTES + d1) = fa1;
            *(uint4*)(nstage + 1*GT_BYTES + d0) = fw0;
            *(uint4*)(nstage + 1*GT_BYTES + d1) = fw1;
        }
        __syncthreads();
    }

    #pragma unroll
    for (int mt = 0; mt < 4; mt++) {
        const int row0 = bm + wm*64 + mt*16 + (lane >> 2);
        #pragma unroll
        for (int nt = 0; nt < 4; nt++) {
            const int col = bn + wn*32 + nt*8 + (lane & 3)*2;
            const float2 bv = *(const float2*)(p.bias + col);
            float x0 = acc[mt][nt][0] + bv.x, y0 = acc[mt][nt][1] + bv.y;
            float x1 = acc[mt][nt][2] + bv.x, y1 = acc[mt][nt][3] + bv.y;
            if (p.outf) {
                *(float2*)(p.outf + (size_t)row0*DM + col)     = make_float2(x0, y0);
                *(float2*)(p.outf + (size_t)(row0+8)*DM + col) = make_float2(x1, y1);
            } else {
                *(uint32_t*)(p.outh + (size_t)row0*DM + col)     = pack2h(x0, y0);
                *(uint32_t*)(p.outh + (size_t)(row0+8)*DM + col) = pack2h(x1, y1);
            }
        }
    }
}

// ---- flash attention: QK fp16; PV fp16; KV dbuf ------------------------
// smem: Qh 16K | 2 x (Kh 8K | Vh 8K) = 48K; occ 2
#define ATT_SMEM 49152

__global__ __launch_bounds__(256, 2) void flash_attn_mma(
    const __half* __restrict__ Qh,
    const __half* __restrict__ Kh, const __half* __restrict__ Vh,
    const int* __restrict__ mask,
    __half* __restrict__ Oh)
{
    extern __shared__ char sm[];
    const uint32_t sb = smem_u32(sm);
    const uint32_t sQh = sb;

    const int tid = threadIdx.x, lane = tid & 31, wid = tid >> 5;
    const int qb = blockIdx.x, bh = blockIdx.y;
    const int b = bh >> 4, h = bh & 15;
    const int q0 = qb*128;
    const size_t rowbase = (size_t)b*S_LEN;
    const int hoff = h*DK;
    const int allones = g_mask_ones;

    // Q tile
    #pragma unroll
    for (int t = 0; t < 4; t++) {
        const int idx = tid + t*256;
        const int r = idx >> 3, uu = idx & 7;
        const size_t g = (rowbase + q0 + r)*DM + hoff + uu*8;
        const uint32_t d = (uint32_t)(r*128 + ((uu ^ (r & 7)) << 4));
        *(uint4*)(sm + d) = *(const uint4*)(Qh + g);
    }

    // KV staging geometry
    uint32_t kvd[2]; size_t kvg[2];
    #pragma unroll
    for (int t = 0; t < 2; t++) {
        const int idx = tid + t*256;
        const int r = idx >> 3, uu = idx & 7;
        kvd[t] = (uint32_t)(r*128 + ((uu ^ (r & 7)) << 4));
        kvg[t] = (size_t)r*DM + hoff + uu*8;
    }

    // prologue: KV block 0 -> stage 0
    #pragma unroll
    for (int t = 0; t < 2; t++) {
        *(uint4*)(sm + 16384 + kvd[t]) = *(const uint4*)(Kh + rowbase*DM + kvg[t]);
        *(uint4*)(sm + 24576 + kvd[t]) = *(const uint4*)(Vh + rowbase*DM + kvg[t]);
    }
    __syncthreads();

    const int sub = lane >> 3, l7 = lane & 7;
    const int a_r = ((sub & 1) << 3) + l7, a_us = sub >> 1;
    const int b_nt = sub >> 1, b_us = sub & 1;
    const int qrow = wid*16 + a_r;
    const int vro = ((sub & 1) << 3) + l7, vus = sub >> 1;

    float o[8][4];
    #pragma unroll
    for (int nt = 0; nt < 8; nt++)
        #pragma unroll
        for (int e = 0; e < 4; e++) o[nt][e] = 0.f;
    float m0 = -3.0e38f, m1 = -3.0e38f, l0 = 0.f, l1 = 0.f;

    for (int kb = 0; kb < S_LEN/64; kb++) {
        const int s = kb & 1;
        const uint32_t sKh = sb + 16384 + s*16384;
        const uint32_t sVh = sKh + 8192;
        const int k0g = kb*64;

        uint4 pk0, pk1, pv0, pv1;
        const bool more = (kb + 1 < S_LEN/64);
        if (more) {
            const size_t grow = (rowbase + (kb + 1)*64)*DM;
            pk0 = *(const uint4*)(Kh + grow + kvg[0]);
            pk1 = *(const uint4*)(Kh + grow + kvg[1]);
            pv0 = *(const uint4*)(Vh + grow + kvg[0]);
            pv1 = *(const uint4*)(Vh + grow + kvg[1]);
        }

        float c[8][4];
        #pragma unroll
        for (int j = 0; j < 8; j++)
            #pragma unroll
            for (int e = 0; e < 4; e++) c[j][e] = 0.f;

        #pragma unroll
        for (int ks = 0; ks < 4; ks++) {
            uint32_t ah[4];
            const uint32_t ua = (uint32_t)((((2*ks + a_us) ^ (qrow & 7)) << 4) + qrow*128);
            ldmx4(ah, sQh + ua);
            #pragma unroll
            for (int jp = 0; jp < 4; jp++) {
                uint32_t kh4[4];
                const int nr = jp*16 + b_nt*8 + l7;
                ldmx4(kh4, sKh + (uint32_t)((((2*ks + b_us) ^ (nr & 7)) << 4) + nr*128));
                mma_f16(c[2*jp],   ah, kh4);
                mma_f16(c[2*jp+1], ah, kh4 + 2);
            }
        }

        if (allones) {
            #pragma unroll
            for (int j = 0; j < 8; j++)
                #pragma unroll
                for (int e = 0; e < 4; e++) c[j][e] *= 0.125f;
        } else {
            const int qg0 = q0 + wid*16 + (lane >> 2);
            #pragma unroll
            for (int j = 0; j < 8; j++) {
                const int colb = k0g + j*8 + 2*(lane & 3);
                #pragma unroll
                for (int e = 0; e < 4; e++) {
                    const int qq = (e < 2) ? qg0 : qg0 + 8;
                    const int mv = mask[(size_t)qq*S_LEN + colb + (e & 1)];
                    c[j][e] = mv ? c[j][e]*0.125f : -1e9f;
                }
            }
        }

        float rm0 = -3.0e38f, rm1 = -3.0e38f;
        #pragma unroll
        for (int j = 0; j < 8; j++) {
            rm0 = fmaxf(rm0, fmaxf(c[j][0], c[j][1]));
            rm1 = fmaxf(rm1, fmaxf(c[j][2], c[j][3]));
        }
        rm0 = fmaxf(rm0, __shfl_xor_sync(0xffffffffu, rm0, 1));
        rm0 = fmaxf(rm0, __shfl_xor_sync(0xffffffffu, rm0, 2));
        rm1 = fmaxf(rm1, __shfl_xor_sync(0xffffffffu, rm1, 1));
        rm1 = fmaxf(rm1, __shfl_xor_sync(0xffffffffu, rm1, 2));
        const float mn0 = fmaxf(m0, rm0), mn1 = fmaxf(m1, rm1);
        const float al0 = __expf(m0 - mn0), al1 = __expf(m1 - mn1);
        float rs0 = 0.f, rs1 = 0.f;
        #pragma unroll
        for (int j = 0; j < 8; j++) {
            c[j][0] = __expf(c[j][0] - mn0);
            c[j][1] = __expf(c[j][1] - mn0);
            c[j][2] = __expf(c[j][2] - mn1);
            c[j][3] = __expf(c[j][3] - mn1);
            rs0 += c[j][0] + c[j][1];
            rs1 += c[j][2] + c[j][3];
        }
        rs0 += __shfl_xor_sync(0xffffffffu, rs0, 1);
        rs0 += __shfl_xor_sync(0xffffffffu, rs0, 2);
        rs1 += __shfl_xor_sync(0xffffffffu, rs1, 1);
        rs1 += __shfl_xor_sync(0xffffffffu, rs1, 2);
        l0 = l0*al0 + rs0;
        l1 = l1*al1 + rs1;
        m0 = mn0; m1 = mn1;
        #pragma unroll
        for (int nt = 0; nt < 8; nt++) {
            o[nt][0] *= al0; o[nt][1] *= al0;
            o[nt][2] *= al1; o[nt][3] *= al1;
        }

        // O += P V : P straight fp16
        #pragma unroll
        for (int kt = 0; kt < 4; kt++) {
            uint32_t ph[4];
            ph[0] = pack2h(c[2*kt][0],   c[2*kt][1]);
            ph[1] = pack2h(c[2*kt][2],   c[2*kt][3]);
            ph[2] = pack2h(c[2*kt+1][0], c[2*kt+1][1]);
            ph[3] = pack2h(c[2*kt+1][2], c[2*kt+1][3]);
            const int tv = kt*16 + vro;
            #pragma unroll
            for (int dp = 0; dp < 4; dp++) {
                uint32_t vh4[4];
                ldmx4t(vh4, sVh + (uint32_t)((((2*dp + vus) ^ (tv & 7)) << 4) + tv*128));
                mma_f16(o[2*dp],   ph, vh4);
                mma_f16(o[2*dp+1], ph, vh4 + 2);
            }
        }

        if (more) {
            char* nb = sm + 16384 + (s ^ 1)*16384;
            *(uint4*)(nb + kvd[0])        = pk0;
            *(uint4*)(nb + kvd[1])        = pk1;
            *(uint4*)(nb + 8192 + kvd[0]) = pv0;
            *(uint4*)(nb + 8192 + kvd[1]) = pv1;
        }
        __syncthreads();
    }

    // epilogue: O / l -> fp16 only
    const float inv0 = 1.f/l0, inv1 = 1.f/l1;
    const size_t gr0 = rowbase + q0 + wid*16 + (lane >> 2);
    #pragma unroll
    for (int nt = 0; nt < 8; nt++) {
        const int col = hoff + nt*8 + 2*(lane & 3);
        *(uint32_t*)(Oh + gr0*DM + col)     = pack2h(o[nt][0]*inv0, o[nt][1]*inv0);
        *(uint32_t*)(Oh + (gr0+8)*DM + col) = pack2h(o[nt][2]*inv1, o[nt][3]*inv1);
    }
}

// ---- host --------------------------------------------------------------
extern "C" void kernel_launch(void* const* d_in, const int* in_sizes, int n_in,
                              void* d_out, int out_size)
{
    const float* q    = (const float*)d_in[0];
    const float* k    = (const float*)d_in[1];
    const float* v    = (const float*)d_in[2];
    const int*   mask = (const int*)  d_in[3];
    const float* Wq   = (const float*)d_in[4];
    const float* bq   = (const float*)d_in[5];
    const float* Wk   = (const float*)d_in[6];
    const float* bk   = (const float*)d_in[7];
    const float* Wv   = (const float*)d_in[8];
    const float* bv   = (const float*)d_in[9];
    const float* Wo   = (const float*)d_in[10];
    const float* bo   = (const float*)d_in[11];
    float* out = (float*)d_out;

    __half *qh,*kh,*vh,*wqh,*wkh,*wvh,*woh;
    __half *Qh,*Kh,*Vh,*Ah;
    cudaGetSymbolAddress((void**)&qh, g_qh);
    cudaGetSymbolAddress((void**)&kh, g_kh);
    cudaGetSymbolAddress((void**)&vh, g_vh);
    cudaGetSymbolAddress((void**)&wqh, g_wqh); cudaGetSymbolAddress((void**)&wkh, g_wkh);
    cudaGetSymbolAddress((void**)&wvh, g_wvh); cudaGetSymbolAddress((void**)&woh, g_woh);
    cudaGetSymbolAddress((void**)&Qh, g_Qh);   cudaGetSymbolAddress((void**)&Kh, g_Kh);
    cudaGetSymbolAddress((void**)&Vh, g_Vh);
    cudaGetSymbolAddress((void**)&Ah, g_Ah);

    cudaFuncSetAttribute(flash_attn_mma, cudaFuncAttributeMaxDynamicSharedMemorySize, ATT_SMEM);

    const int n4_in = MROWS*DM/4, n4_w = DM*DM/4;

    reset_flag<<<1, 1>>>();
    check_mask<<<1024, 256>>>(mask, S_LEN*S_LEN);

    dim3 gs(n4_in/512, 3);
    conv_h3<<<gs, 256>>>(q, qh, k, kh, v, vh, n4_in);
    dim3 gc(n4_w/512, 4);
    conv_h4<<<gc, 256>>>(Wq, wqh, Wk, wkh, Wv, wvh, Wo, woh, n4_w);

    // QKV projections: pure fp16
    GemmP pq = { qh, wqh, bq, nullptr, Qh };
    GemmP pk = { kh, wkh, bk, nullptr, Kh };
    GemmP pv = { vh, wvh, bv, nullptr, Vh };
    dim3 gg3(DM/128, MROWS/128, 3);
    gemm_hmma<<<gg3, 256>>>(pq, pk, pv);

    dim3 ga(S_LEN/128, B_SZ*NH);
    flash_attn_mma<<<ga, 256, ATT_SMEM>>>(Qh, Kh, Vh, mask, Ah);

    // final projection: pure fp16 -> fp32 out
    GemmP po = { Ah, woh, bo, out, nullptr };
    dim3 gg1(DM/128, MROWS/128, 1);
    gemm_hmma<<<gg1, 256>>>(po, po, po);
}

// round 17
// speedup vs baseline: 2.7029x; 1.0012x over previous
#include <cuda_runtime.h>
#include <cuda_fp16.h>
#include <cstdint>
#include <math.h>

#define S_LEN 2048
#define B_SZ  2
#define DM    1024
#define NH    16
#define DK    64
#define MROWS (B_SZ * S_LEN)
#define NWORKERS 296

// ---- scratch -----------------------------------------------------------
__device__ __half g_qh[MROWS*DM], g_kh[MROWS*DM], g_vh[MROWS*DM];
__device__ __half g_wqh[DM*DM], g_wkh[DM*DM], g_wvh[DM*DM], g_woh[DM*DM];
__device__ __half g_Qh[MROWS*DM], g_Kh[MROWS*DM], g_Vh[MROWS*DM];
__device__ __half g_Ah[MROWS*DM];
__device__ int g_mask_ones;
__device__ int g_cnt[4];

// ---- helpers -----------------------------------------------------------
__device__ __forceinline__ uint32_t smem_u32(const void* p) {
    uint32_t a;
    asm("{ .reg .u64 t; cvta.to.shared.u64 t, %1; cvt.u32.u64 %0, t; }" : "=r"(a) : "l"(p));
    return a;
}
__device__ __forceinline__ void ldmx4(uint32_t* r, uint32_t addr) {
    asm volatile("ldmatrix.sync.aligned.m8n8.x4.shared.b16 {%0,%1,%2,%3}, [%4];"
                 : "=r"(r[0]), "=r"(r[1]), "=r"(r[2]), "=r"(r[3]) : "r"(addr));
}
__device__ __forceinline__ void ldmx4t(uint32_t* r, uint32_t addr) {
    asm volatile("ldmatrix.sync.aligned.m8n8.x4.trans.shared.b16 {%0,%1,%2,%3}, [%4];"
                 : "=r"(r[0]), "=r"(r[1]), "=r"(r[2]), "=r"(r[3]) : "r"(addr));
}
__device__ __forceinline__ void mma_f16(float* c, const uint32_t* a, const uint32_t* b) {
    asm volatile("mma.sync.aligned.m16n8k16.row.col.f32.f16.f16.f32 "
                 "{%0,%1,%2,%3}, {%4,%5,%6,%7}, {%8,%9}, {%0,%1,%2,%3};"
                 : "+f"(c[0]), "+f"(c[1]), "+f"(c[2]), "+f"(c[3])
                 : "r"(a[0]), "r"(a[1]), "r"(a[2]), "r"(a[3]), "r"(b[0]), "r"(b[1]));
}
__device__ __forceinline__ uint32_t pack2h(float x, float y) {
    __half2 h(__float2half_rn(x), __float2half_rn(y));
    return *reinterpret_cast<uint32_t*>(&h);
}

__global__ void reset_state() {
    g_mask_ones = 1;
    g_cnt[0] = 0; g_cnt[1] = 0; g_cnt[2] = 0; g_cnt[3] = 0;
}
__global__ __launch_bounds__(256) void check_mask(const int* __restrict__ m, int n) {
    int i = blockIdx.x * blockDim.x + threadIdx.x;
    int ok = 1;
    for (; i < n; i += gridDim.x * blockDim.x) ok &= (m[i] != 0);
    ok = __all_sync(0xffffffffu, ok);
    if ((threadIdx.x & 31) == 0 && !ok) atomicExch(&g_mask_ones, 0);
}

// ---- fused converts: 3 input tensors -----------------------------------
__global__ __launch_bounds__(256) void conv_h3(
    const float* __restrict__ x0, __half* __restrict__ h0,
    const float* __restrict__ x1, __half* __restrict__ h1,
    const float* __restrict__ x2, __half* __restrict__ h2,
    int n4)
{
    const float* x = (blockIdx.y == 0) ? x0 : (blockIdx.y == 1 ? x1 : x2);
    __half* hh = (blockIdx.y == 0) ? h0 : (blockIdx.y == 1 ? h1 : h2);
    const int base = blockIdx.x * 512 + threadIdx.x;
    #pragma unroll
    for (int t = 0; t < 2; t++) {
        const int i = base + t * 256;
        if (i >= n4) return;
        float4 v = ((const float4*)x)[i];
        ((uint32_t*)hh)[2*i]   = pack2h(v.x, v.y);
        ((uint32_t*)hh)[2*i+1] = pack2h(v.z, v.w);
    }
}

// ---- fused converts: 4 weight tensors ----------------------------------
__global__ __launch_bounds__(256) void conv_h4(
    const float* __restrict__ x0, __half* __restrict__ h0,
    const float* __restrict__ x1, __half* __restrict__ h1,
    const float* __restrict__ x2, __half* __restrict__ h2,
    const float* __restrict__ x3, __half* __restrict__ h3,
    int n4)
{
    const float* x = (blockIdx.y < 2) ? (blockIdx.y == 0 ? x0 : x1)
                                      : (blockIdx.y == 2 ? x2 : x3);
    __half* hh = (blockIdx.y < 2) ? (blockIdx.y == 0 ? h0 : h1)
                                  : (blockIdx.y == 2 ? h2 : h3);
    const int base = blockIdx.x * 512 + threadIdx.x;
    #pragma unroll
    for (int t = 0; t < 2; t++) {
        const int i = base + t * 256;
        if (i >= n4) return;
        float4 v = ((const float4*)x)[i];
        ((uint32_t*)hh)[2*i]   = pack2h(v.x, v.y);
        ((uint32_t*)hh)[2*i+1] = pack2h(v.z, v.w);
    }
}

// ---- GEMM: persistent tile pool; C = A@Wh^T + bias, pure fp16 ----------
struct GemmP {
    const __half *ah, *wh;
    const float* bias;
    float* outf;
    __half* outh;
};

#define GT_BYTES 8192           // 128 x 32 fp16
#define GSTAGE   (2 * GT_BYTES) // Ah | Wh per stage

__global__ __launch_bounds__(256, 2) void gemm_hmma(GemmP p0, GemmP p1, GemmP p2,
                                                    int ntiles, int cidx)
{
    __shared__ char smem[2 * GSTAGE];
    __shared__ int s_tile;

    const int tid = threadIdx.x, lane = tid & 31, wid = tid >> 5;
    const int wm = wid & 1, wn = wid >> 1;

    const uint32_t sb = smem_u32(smem);

    // tile-independent geometry
    const int u = tid & 3, r0 = tid >> 2, r1 = r0 + 64;
    const uint32_t d0 = (uint32_t)(r0*64 + ((u ^ ((r0 >> 1) & 3)) << 4));
    const uint32_t d1 = (uint32_t)(r1*64 + ((u ^ ((r1 >> 1) & 3)) << 4));

    const int sub = lane >> 3;
    const int a_r16 = ((sub & 1) << 3) + (lane & 7), a_usel = sub >> 1;
    const int b_nt = sub >> 1, b_usel = sub & 1, b_r8 = lane & 7;

    int arow[4], asw[4];
    #pragma unroll
    for (int mt = 0; mt < 4; mt++) {
        const int gr = wm*64 + mt*16 + a_r16;
        arow[mt] = gr*64; asw[mt] = (gr >> 1) & 3;
    }
    int brow[2], bsw[2];
    #pragma unroll
    for (int j = 0; j < 2; j++) {
        const int nr = wn*32 + (2*j + b_nt)*8 + b_r8;
        brow[j] = nr*64; bsw[j] = (nr >> 1) & 3;
    }

    for (;;) {
        if (tid == 0) s_tile = atomicAdd(&g_cnt[cidx], 1);
        __syncthreads();
        const int tile = s_tile;
        if (tile >= ntiles) break;

        const int z = tile >> 8;            // problem id (256 tiles each)
        const int w = tile & 255;
        const int bn = (w & 7) * 128;
        const int bm = (w >> 3) * 128;
        GemmP p = (z == 0) ? p0 : (z == 1 ? p1 : p2);

        const size_t offA0 = (size_t)(bm + r0)*DM + u*8, offA1 = (size_t)(bm + r1)*DM + u*8;
        const size_t offW0 = (size_t)(bn + r0)*DM + u*8, offW1 = (size_t)(bn + r1)*DM + u*8;

        float acc[4][4][4];
        #pragma unroll
        for (int mt = 0; mt < 4; mt++)
            #pragma unroll
            for (int nt = 0; nt < 4; nt++)
                #pragma unroll
                for (int r = 0; r < 4; r++) acc[mt][nt][r] = 0.f;

        // prologue: chunk 0 -> stage 0
        {
            uint4 a0 = *(const uint4*)(p.ah + offA0), a1 = *(const uint4*)(p.ah + offA1);
            uint4 w0 = *(const uint4*)(p.wh + offW0), w1 = *(const uint4*)(p.wh + offW1);
            *(uint4*)(smem + 0*GT_BYTES + d0) = a0; *(uint4*)(smem + 0*GT_BYTES + d1) = a1;
            *(uint4*)(smem + 1*GT_BYTES + d0) = w0; *(uint4*)(smem + 1*GT_BYTES + d1) = w1;
        }
        __syncthreads();

        for (int ch = 0; ch < DM/32; ch++) {
            const int s = ch & 1;
            const uint32_t sAh = sb + s*GSTAGE, sWh = sAh + GT_BYTES;
            char* nstage = smem + (s ^ 1)*GSTAGE;

            uint4 fa0, fa1, fw0, fw1;
            const bool more = (ch + 1 < DM/32);
            if (more) {
                const int kb = (ch + 1)*32;
                fa0 = *(const uint4*)(p.ah + offA0 + kb);
                fa1 = *(const uint4*)(p.ah + offA1 + kb);
                fw0 = *(const uint4*)(p.wh + offW0 + kb);
                fw1 = *(const uint4*)(p.wh + offW1 + kb);
            }

            #pragma unroll
            for (int ks = 0; ks < 2; ks++) {
                uint32_t bh[4][2];
                #pragma unroll
                for (int j = 0; j < 2; j++) {
                    const uint32_t uoff = (uint32_t)(((2*ks + b_usel) ^ bsw[j]) << 4) + brow[j];
                    ldmx4(&bh[2*j][0], sWh + uoff);
                }
                #pragma unroll
                for (int mt = 0; mt < 4; mt++) {
                    uint32_t ah[4];
                    const uint32_t uoff = (uint32_t)(((2*ks + a_usel) ^ asw[mt]) << 4) + arow[mt];
                    ldmx4(ah, sAh + uoff);
                    #pragma unroll
                    for (int nt = 0; nt < 4; nt++)
                        mma_f16(acc[mt][nt], ah, bh[nt]);
                }
            }

            if (more) {
                *(uint4*)(nstage + 0*GT_BYTES + d0) = fa0;
                *(uint4*)(nstage + 0*GT_BYTES + d1) = fa1;
                *(uint4*)(nstage + 1*GT_BYTES + d0) = fw0;
                *(uint4*)(nstage + 1*GT_BYTES + d1) = fw1;
            }
            __syncthreads();
        }

        #pragma unroll
        for (int mt = 0; mt < 4; mt++) {
            const int row0 = bm + wm*64 + mt*16 + (lane >> 2);
            #pragma unroll
            for (int nt = 0; nt < 4; nt++) {
                const int col = bn + wn*32 + nt*8 + (lane & 3)*2;
                const float2 bv = *(const float2*)(p.bias + col);
                float x0 = acc[mt][nt][0] + bv.x, y0 = acc[mt][nt][1] + bv.y;
                float x1 = acc[mt][nt][2] + bv.x, y1 = acc[mt][nt][3] + bv.y;
                if (p.outf) {
                    *(float2*)(p.outf + (size_t)row0*DM + col)     = make_float2(x0, y0);
                    *(float2*)(p.outf + (size_t)(row0+8)*DM + col) = make_float2(x1, y1);
                } else {
                    *(uint32_t*)(p.outh + (size_t)row0*DM + col)     = pack2h(x0, y0);
                    *(uint32_t*)(p.outh + (size_t)(row0+8)*DM + col) = pack2h(x1, y1);
                }
            }
        }
    }
}

// ---- flash attention: persistent work pool; QK/PV pure fp16; KV dbuf ---
// smem: Qh 16K | 2 x (Kh 8K | Vh 8K) = 48K; occ 2
#define ATT_SMEM 49280   // 48K tiles + 128B control

__global__ __launch_bounds__(256, 2) void flash_attn_mma(
    const __half* __restrict__ Qh,
    const __half* __restrict__ Kh, const __half* __restrict__ Vh,
    const int* __restrict__ mask,
    __half* __restrict__ Oh, int nworks)
{
    extern __shared__ char sm[];
    const uint32_t sb = smem_u32(sm);
    const uint32_t sQh = sb;
    int* s_work = (int*)(sm + 49152);

    const int tid = threadIdx.x, lane = tid & 31, wid = tid >> 5;
    const int allones = g_mask_ones;

    // work-independent lane geometry
    const int sub = lane >> 3, l7 = lane & 7;
    const int a_r = ((sub & 1) << 3) + l7, a_us = sub >> 1;
    const int b_nt = sub >> 1, b_us = sub & 1;
    const int qrow = wid*16 + a_r;
    const int vro = ((sub & 1) << 3) + l7, vus = sub >> 1;

    uint32_t kvd[2]; int kvr[2], kvu[2];
    #pragma unroll
    for (int t = 0; t < 2; t++) {
        const int idx = tid + t*256;
        const int r = idx >> 3, uu = idx & 7;
        kvd[t] = (uint32_t)(r*128 + ((uu ^ (r & 7)) << 4));
        kvr[t] = r; kvu[t] = uu;
    }

    for (;;) {
        if (tid == 0) *s_work = atomicAdd(&g_cnt[1], 1);
        __syncthreads();
        const int wk = *s_work;
        if (wk >= nworks) break;

        const int qb = wk & 15, bh = wk >> 4;
        const int b = bh >> 4, h = bh & 15;
        const int q0 = qb*128;
        const size_t rowbase = (size_t)b*S_LEN;
        const int hoff = h*DK;

        size_t kvg[2];
        #pragma unroll
        for (int t = 0; t < 2; t++) kvg[t] = (size_t)kvr[t]*DM + hoff + kvu[t]*8;

        // Q tile
        #pragma unroll
        for (int t = 0; t < 4; t++) {
            const int idx = tid + t*256;
            const int r = idx >> 3, uu = idx & 7;
            const size_t g = (rowbase + q0 + r)*DM + hoff + uu*8;
            const uint32_t d = (uint32_t)(r*128 + ((uu ^ (r & 7)) << 4));
            *(uint4*)(sm + d) = *(const uint4*)(Qh + g);
        }
        // KV block 0 -> stage 0
        #pragma unroll
        for (int t = 0; t < 2; t++) {
            *(uint4*)(sm + 16384 + kvd[t]) = *(const uint4*)(Kh + rowbase*DM + kvg[t]);
            *(uint4*)(sm + 24576 + kvd[t]) = *(const uint4*)(Vh + rowbase*DM + kvg[t]);
        }
        __syncthreads();

        float o[8][4];
        #pragma unroll
        for (int nt = 0; nt < 8; nt++)
            #pragma unroll
            for (int e = 0; e < 4; e++) o[nt][e] = 0.f;
        float m0 = -3.0e38f, m1 = -3.0e38f, l0 = 0.f, l1 = 0.f;

        for (int kb = 0; kb < S_LEN/64; kb++) {
            const int s = kb & 1;
            const uint32_t sKh = sb + 16384 + s*16384;
            const uint32_t sVh = sKh + 8192;
            const int k0g = kb*64;

            uint4 pk0, pk1, pv0, pv1;
            const bool more = (kb + 1 < S_LEN/64);
            if (more) {
                const size_t grow = (rowbase + (kb + 1)*64)*DM;
                pk0 = *(const uint4*)(Kh + grow + kvg[0]);
                pk1 = *(const uint4*)(Kh + grow + kvg[1]);
                pv0 = *(const uint4*)(Vh + grow + kvg[0]);
                pv1 = *(const uint4*)(Vh + grow + kvg[1]);
            }

            float c[8][4];
            #pragma unroll
            for (int j = 0; j < 8; j++)
                #pragma unroll
                for (int e = 0; e < 4; e++) c[j][e] = 0.f;

            #pragma unroll
            for (int ks = 0; ks < 4; ks++) {
                uint32_t ah[4];
                const uint32_t ua = (uint32_t)((((2*ks + a_us) ^ (qrow & 7)) << 4) + qrow*128);
                ldmx4(ah, sQh + ua);
                #pragma unroll
                for (int jp = 0; jp < 4; jp++) {
                    uint32_t kh4[4];
                    const int nr = jp*16 + b_nt*8 + l7;
                    ldmx4(kh4, sKh + (uint32_t)((((2*ks + b_us) ^ (nr & 7)) << 4) + nr*128));
                    mma_f16(c[2*jp],   ah, kh4);
                    mma_f16(c[2*jp+1], ah, kh4 + 2);
                }
            }

            if (allones) {
                #pragma unroll
                for (int j = 0; j < 8; j++)
                    #pragma unroll
                    for (int e = 0; e < 4; e++) c[j][e] *= 0.125f;
            } else {
                const int qg0 = q0 + wid*16 + (lane >> 2);
                #pragma unroll
                for (int j = 0; j < 8; j++) {
                    const int colb = k0g + j*8 + 2*(lane & 3);
                    #pragma unroll
                    for (int e = 0; e < 4; e++) {
                        const int qq = (e < 2) ? qg0 : qg0 + 8;
                        const int mv = mask[(size_t)qq*S_LEN + colb + (e & 1)];
                        c[j][e] = mv ? c[j][e]*0.125f : -1e9f;
                    }
                }
            }

            float rm0 = -3.0e38f, rm1 = -3.0e38f;
            #pragma unroll
            for (int j = 0; j < 8; j++) {
                rm0 = fmaxf(rm0, fmaxf(c[j][0], c[j][1]));
                rm1 = fmaxf(rm1, fmaxf(c[j][2], c[j][3]));
            }
            rm0 = fmaxf(rm0, __shfl_xor_sync(0xffffffffu, rm0, 1));
            rm0 = fmaxf(rm0, __shfl_xor_sync(0xffffffffu, rm0, 2));
            rm1 = fmaxf(rm1, __shfl_xor_sync(0xffffffffu, rm1, 1));
            rm1 = fmaxf(rm1, __shfl_xor_sync(0xffffffffu, rm1, 2));
            const float mn0 = fmaxf(m0, rm0), mn1 = fmaxf(m1, rm1);
            const float al0 = __expf(m0 - mn0), al1 = __expf(m1 - mn1);
            float rs0 = 0.f, rs1 = 0.f;
            #pragma unroll
            for (int j = 0; j < 8; j++) {
                c[j][0] = __expf(c[j][0] - mn0);
                c[j][1] = __expf(c[j][1] - mn0);
                c[j][2] = __expf(c[j][2] - mn1);
                c[j][3] = __expf(c[j][3] - mn1);
                rs0 += c[j][0] + c[j][1];
                rs1 += c[j][2] + c[j][3];
            }
            rs0 += __shfl_xor_sync(0xffffffffu, rs0, 1);
            rs0 += __shfl_xor_sync(0xffffffffu, rs0, 2);
            rs1 += __shfl_xor_sync(0xffffffffu, rs1, 1);
            rs1 += __shfl_xor_sync(0xffffffffu, rs1, 2);
            l0 = l0*al0 + rs0;
            l1 = l1*al1 + rs1;
            m0 = mn0; m1 = mn1;
            #pragma unroll
            for (int nt = 0; nt < 8; nt++) {
                o[nt][0] *= al0; o[nt][1] *= al0;
                o[nt][2] *= al1; o[nt][3] *= al1;
            }

            // O += P V : P straight fp16
            #pragma unroll
            for (int kt = 0; kt < 4; kt++) {
                uint32_t ph[4];
                ph[0] = pack2h(c[2*kt][0],   c[2*kt][1]);
                ph[1] = pack2h(c[2*kt][2],   c[2*kt][3]);
                ph[2] = pack2h(c[2*kt+1][0], c[2*kt+1][1]);
                ph[3] = pack2h(c[2*kt+1][2], c[2*kt+1][3]);
                const int tv = kt*16 + vro;
                #pragma unroll
                for (int dp = 0; dp < 4; dp++) {
                    uint32_t vh4[4];
                    ldmx4t(vh4, sVh + (uint32_t)((((2*dp + vus) ^ (tv & 7)) << 4) + tv*128));
                    mma_f16(o[2*dp],   ph, vh4);
                    mma_f16(o[2*dp+1], ph, vh4 + 2);
                }
            }

            if (more) {
                char* nb = sm + 16384 + (s ^ 1)*16384;
                *(uint4*)(nb + kvd[0])        = pk0;
                *(uint4*)(nb + kvd[1])        = pk1;
                *(uint4*)(nb + 8192 + kvd[0]) = pv0;
                *(uint4*)(nb + 8192 + kvd[1]) = pv1;
            }
            __syncthreads();
        }

        // epilogue: O / l -> fp16
        const float inv0 = 1.f/l0, inv1 = 1.f/l1;
        const size_t gr0 = rowbase + q0 + wid*16 + (lane >> 2);
        #pragma unroll
        for (int nt = 0; nt < 8; nt++) {
            const int col = hoff + nt*8 + 2*(lane & 3);
            *(uint32_t*)(Oh + gr0*DM + col)     = pack2h(o[nt][0]*inv0, o[nt][1]*inv0);
            *(uint32_t*)(Oh + (gr0+8)*DM + col) = pack2h(o[nt][2]*inv1, o[nt][3]*inv1);
        }
    }
}

// ---- host --------------------------------------------------------------
extern "C" void kernel_launch(void* const* d_in, const int* in_sizes, int n_in,
                              void* d_out, int out_size)
{
    const float* q    = (const float*)d_in[0];
    const float* k    = (const float*)d_in[1];
    const float* v    = (const float*)d_in[2];
    const int*   mask = (const int*)  d_in[3];
    const float* Wq   = (const float*)d_in[4];
    const float* bq   = (const float*)d_in[5];
    const float* Wk   = (const float*)d_in[6];
    const float* bk   = (const float*)d_in[7];
    const float* Wv   = (const float*)d_in[8];
    const float* bv   = (const float*)d_in[9];
    const float* Wo   = (const float*)d_in[10];
    const float* bo   = (const float*)d_in[11];
    float* out = (float*)d_out;

    __half *qh,*kh,*vh,*wqh,*wkh,*wvh,*woh;
    __half *Qh,*Kh,*Vh,*Ah;
    cudaGetSymbolAddress((void**)&qh, g_qh);
    cudaGetSymbolAddress((void**)&kh, g_kh);
    cudaGetSymbolAddress((void**)&vh, g_vh);
    cudaGetSymbolAddress((void**)&wqh, g_wqh); cudaGetSymbolAddress((void**)&wkh, g_wkh);
    cudaGetSymbolAddress((void**)&wvh, g_wvh); cudaGetSymbolAddress((void**)&woh, g_woh);
    cudaGetSymbolAddress((void**)&Qh, g_Qh);   cudaGetSymbolAddress((void**)&Kh, g_Kh);
    cudaGetSymbolAddress((void**)&Vh, g_Vh);
    cudaGetSymbolAddress((void**)&Ah, g_Ah);

    cudaFuncSetAttribute(flash_attn_mma, cudaFuncAttributeMaxDynamicSharedMemorySize, ATT_SMEM);

    const int n4_in = MROWS*DM/4, n4_w = DM*DM/4;

    reset_state<<<1, 1>>>();
    check_mask<<<1024, 256>>>(mask, S_LEN*S_LEN);

    dim3 gs(n4_in/512, 3);
    conv_h3<<<gs, 256>>>(q, qh, k, kh, v, vh, n4_in);
    dim3 gc(n4_w/512, 4);
    conv_h4<<<gc, 256>>>(Wq, wqh, Wk, wkh, Wv, wvh, Wo, woh, n4_w);

    // QKV projections: persistent pool over 3 x 256 tiles
    GemmP pq = { qh, wqh, bq, nullptr, Qh };
    GemmP pk = { kh, wkh, bk, nullptr, Kh };
    GemmP pv = { vh, wvh, bv, nullptr, Vh };
    gemm_hmma<<<NWORKERS, 256>>>(pq, pk, pv, 768, 0);

    // attention: persistent pool over 512 works
    flash_attn_mma<<<NWORKERS, 256, ATT_SMEM>>>(Qh, Kh, Vh, mask, Ah, 512);

    // final projection: persistent pool over 256 tiles
    GemmP po = { Ah, woh, bo, out, nullptr };
    gemm_hmma<<<NWORKERS, 256>>>(po, po, po, 256, 2);
}